// round 3
// baseline (speedup 1.0000x reference)
#include <cuda_runtime.h>
#include <math.h>

#define Bn 8
#define Cch 32
#define Nn 512
#define Lt 64
#define BUF (Bn*Cch*Nn*Lt)

// Scratch (device globals — no allocation allowed)
__device__ float g_A[BUF];
__device__ float g_B[BUF];
__device__ float g_C[BUF];
__device__ float g_D[BUF];
__device__ float g_E[BUF];
__device__ float g_SK[BUF];
__device__ float g_A2[Nn*Nn];

#define FMA4(acc, s, h) { (acc).x += (s)*(h).x; (acc).y += (s)*(h).y; (acc).z += (s)*(h).z; (acc).w += (s)*(h).w; }

// ---------------- start conv: x[8,2,512,64] -> h[8,32,512,64] ----------------
__global__ void k_start(const float* __restrict__ x, const float* __restrict__ W,
                        const float* __restrict__ bias, float* __restrict__ h) {
  int idx4 = blockIdx.x * 256 + threadIdx.x;            // BUF/4 float4 elems
  int l4 = (idx4 & 15) * 4;
  int n  = (idx4 >> 4) & 511;
  int c  = (idx4 >> 13) & 31;
  int b  = idx4 >> 18;
  int xb = ((b * 2) * Nn + n) * Lt + l4;
  float4 x0 = *(const float4*)&x[xb];
  float4 x1 = *(const float4*)&x[xb + Nn * Lt];
  float w0 = W[c * 2], w1 = W[c * 2 + 1], bs = bias[c];
  float4 o;
  o.x = x0.x * w0 + x1.x * w1 + bs;
  o.y = x0.y * w0 + x1.y * w1 + bs;
  o.z = x0.z * w0 + x1.z * w1 + bs;
  o.w = x0.w * w0 + x1.w * w1 + bs;
  *(float4*)&h[(((b * 32 + c) * Nn + n) * Lt) + l4] = o;
}

// ---------------- A2 = adj @ adj  (512x512x512) ----------------
__global__ void k_a2(const float* __restrict__ adj, float* __restrict__ A2) {
  __shared__ float As[32][33], Bs[32][33];
  int tx = threadIdx.x, ty = threadIdx.y;  // (32, 8)
  int p0 = blockIdx.y * 32, m0 = blockIdx.x * 32;
  float acc[4] = {0.f, 0.f, 0.f, 0.f};
  for (int k0 = 0; k0 < Nn; k0 += 32) {
    #pragma unroll
    for (int r = 0; r < 4; r++) {
      As[ty + 8 * r][tx] = adj[(p0 + ty + 8 * r) * Nn + k0 + tx];
      Bs[ty + 8 * r][tx] = adj[(k0 + ty + 8 * r) * Nn + m0 + tx];
    }
    __syncthreads();
    #pragma unroll
    for (int k = 0; k < 32; k++) {
      float bv = Bs[k][tx];
      #pragma unroll
      for (int r = 0; r < 4; r++) acc[r] += As[ty + 8 * r][k] * bv;
    }
    __syncthreads();
  }
  #pragma unroll
  for (int r = 0; r < 4; r++) A2[(p0 + ty + 8 * r) * Nn + m0 + tx] = acc[r];
}

// ---------------- gated TCN + skip (modes: 0 init skip, 1 add skip, 2 final out) ----------------
__global__ void k_tcn(const float* __restrict__ h_in, float* __restrict__ t_out,
                      float* __restrict__ skipbuf, float* __restrict__ outp,
                      const float* __restrict__ Wf, const float* __restrict__ bfv,
                      const float* __restrict__ Wg, const float* __restrict__ bgv,
                      const float* __restrict__ Wsk, const float* __restrict__ bskv,
                      const float* __restrict__ obng, const float* __restrict__ obnb,
                      int Lin, int mode) {
  __shared__ float hs[33][64];     // extra row: reads at [c][64] fall into next row, defined mem
  __shared__ float hns[32][73];
  __shared__ float wfs[2048], wgs[2048], wsks[1024];
  int t = threadIdx.x;
  int n = blockIdx.x, b = blockIdx.y;
  int base = ((b * 32) * Nn + n) * Lt;

  #pragma unroll
  for (int q = 0; q < 2; q++) {
    int fidx = t + q * 256;
    int c = fidx >> 4, l4 = (fidx & 15) * 4;
    *(float4*)&hs[c][l4] = *(const float4*)&h_in[base + c * (Nn * Lt) + l4];
    *(float4*)&wfs[fidx * 4] = *(const float4*)&Wf[fidx * 4];
    *(float4*)&wgs[fidx * 4] = *(const float4*)&Wg[fidx * 4];
  }
  ((float4*)wsks)[t] = ((const float4*)Wsk)[t];
  __syncthreads();

  int o = t >> 3, sub = t & 7;
  int Lout = Lin - 1;
  int l0 = sub * 8;
  float f[8], g[8];
  float bfo = bfv[o], bgo = bgv[o];
  #pragma unroll
  for (int j = 0; j < 8; j++) { f[j] = bfo; g[j] = bgo; }

  for (int c = 0; c < 32; c++) {
    float wf0 = wfs[(o * 32 + c) * 2], wf1 = wfs[(o * 32 + c) * 2 + 1];
    float wg0 = wgs[(o * 32 + c) * 2], wg1 = wgs[(o * 32 + c) * 2 + 1];
    float hp = hs[c][l0];
    #pragma unroll
    for (int j = 0; j < 8; j++) {
      float hc = hs[c][l0 + j + 1];
      f[j] += hp * wf0 + hc * wf1;
      g[j] += hp * wg0 + hc * wg1;
      hp = hc;
    }
  }

  int obase = base + o * (Nn * Lt);
  #pragma unroll
  for (int j = 0; j < 8; j++) {
    int l = l0 + j;
    float hv = tanhf(f[j]) * (1.0f / (1.0f + expf(-g[j])));
    hns[o][l] = hv;
    if (mode != 2 && l < Lout) t_out[obase + l] = hv;
  }
  __syncthreads();

  float s[8];
  float bs = bskv[o];
  #pragma unroll
  for (int j = 0; j < 8; j++) s[j] = bs;
  for (int c = 0; c < 32; c++) {
    float w = wsks[o * 32 + c];
    #pragma unroll
    for (int j = 0; j < 8; j++) s[j] += w * hns[c][l0 + j];
  }

  if (mode == 0) {
    #pragma unroll
    for (int j = 0; j < 8; j++) {
      int l = l0 + j;
      if (l >= 2 && l < Lout) skipbuf[obase + l - 2] = s[j];
    }
  } else if (mode == 1) {
    #pragma unroll
    for (int j = 0; j < 8; j++) {
      int l = l0 + j;
      if (l >= 1 && l < Lout) skipbuf[obase + l - 1] += s[j];
    }
  } else {
    float inv = obng[o] * rsqrtf(1.0f + 1e-5f);
    float bb = obnb[o];
    #pragma unroll
    for (int j = 0; j < 8; j++) {
      int l = l0 + j;
      if (l < 61)
        outp[((b * 61 + l) * Nn + n) * 32 + o] = (skipbuf[obase + l] + s[j]) * inv + bb;
    }
  }
}

// ---------------- fused diffusion: X1 = adj^T . H, X2 = A2^T . H (per bc batch) ----------------
// 64(m) x 64(l) tile, 4x4 per thread, float4 LDS/STG. 3 LDS.128 : 32 FFMA per k-step.
__global__ void __launch_bounds__(256, 3) k_diff(
    const float* __restrict__ H, const float* __restrict__ adj,
    const float* __restrict__ A2,
    float* __restrict__ X1, float* __restrict__ X2) {
  __shared__ float Hs[32][64], A1s[32][64], A2s[32][64];
  int t = threadIdx.x;
  int tx = t & 15, ty = t >> 4;        // tx: l-quad, ty: m-quad
  int m0 = blockIdx.x * 64;
  int bc = blockIdx.y;
  int hbase = bc * (Nn * Lt);

  float4 acc1[4], acc2[4];
  #pragma unroll
  for (int r = 0; r < 4; r++) {
    acc1[r] = make_float4(0.f, 0.f, 0.f, 0.f);
    acc2[r] = make_float4(0.f, 0.f, 0.f, 0.f);
  }

  int lrow = t >> 4;            // 0..15
  int lcol = (t & 15) * 4;      // 0..60
  for (int k0 = 0; k0 < Nn; k0 += 32) {
    #pragma unroll
    for (int q = 0; q < 2; q++) {
      int r = lrow + q * 16;
      *(float4*)&Hs[r][lcol]  = *(const float4*)&H[hbase + (k0 + r) * Lt + lcol];
      *(float4*)&A1s[r][lcol] = *(const float4*)&adj[(k0 + r) * Nn + m0 + lcol];
      *(float4*)&A2s[r][lcol] = *(const float4*)&A2[(k0 + r) * Nn + m0 + lcol];
    }
    __syncthreads();
    #pragma unroll
    for (int k = 0; k < 32; k++) {
      float4 h  = *(float4*)&Hs[k][tx * 4];
      float4 a1 = *(float4*)&A1s[k][ty * 4];
      float4 a2 = *(float4*)&A2s[k][ty * 4];
      FMA4(acc1[0], a1.x, h); FMA4(acc1[1], a1.y, h);
      FMA4(acc1[2], a1.z, h); FMA4(acc1[3], a1.w, h);
      FMA4(acc2[0], a2.x, h); FMA4(acc2[1], a2.y, h);
      FMA4(acc2[2], a2.z, h); FMA4(acc2[3], a2.w, h);
    }
    __syncthreads();
  }

  #pragma unroll
  for (int r = 0; r < 4; r++) {
    int off = hbase + (m0 + ty * 4 + r) * Lt + tx * 4;
    *(float4*)&X1[off] = acc1[r];
    *(float4*)&X2[off] = acc2[r];
  }
}

// ---------------- graph-conv 1x1 (96->32) + BN + residual + BN ----------------
__global__ void k_gcmix(const float* __restrict__ Ht, const float* __restrict__ X1,
                        const float* __restrict__ X2, const float* __restrict__ Res,
                        float* __restrict__ Out,
                        const float* __restrict__ Wgc, const float* __restrict__ bgc,
                        const float* __restrict__ gg, const float* __restrict__ gb,
                        const float* __restrict__ bng, const float* __restrict__ bnb,
                        int Lout) {
  __shared__ float hs[32][64], x1s[32][64], x2s[32][64];
  __shared__ float wgs[32 * 96];
  int t = threadIdx.x;
  int n = blockIdx.x, b = blockIdx.y;
  int base = ((b * 32) * Nn + n) * Lt;

  #pragma unroll
  for (int q = 0; q < 2; q++) {
    int fidx = t + q * 256;
    int c = fidx >> 4, l4 = (fidx & 15) * 4;
    int gptr = base + c * (Nn * Lt) + l4;
    *(float4*)&hs[c][l4]  = *(const float4*)&Ht[gptr];
    *(float4*)&x1s[c][l4] = *(const float4*)&X1[gptr];
    *(float4*)&x2s[c][l4] = *(const float4*)&X2[gptr];
  }
  #pragma unroll
  for (int q = 0; q < 3; q++) {
    int fidx = t + q * 256;
    *(float4*)&wgs[fidx * 4] = *(const float4*)&Wgc[fidx * 4];
  }
  __syncthreads();

  int og = t >> 5, lt = t & 31;
  float acc[4][2] = {};
  for (int c = 0; c < 32; c++) {
    float h0 = hs[c][lt],  h1 = hs[c][lt + 32];
    float p0 = x1s[c][lt], p1 = x1s[c][lt + 32];
    float q0 = x2s[c][lt], q1 = x2s[c][lt + 32];
    #pragma unroll
    for (int r = 0; r < 4; r++) {
      int o = og * 4 + r;
      float wh = wgs[o * 96 + c], w1 = wgs[o * 96 + 32 + c], w2 = wgs[o * 96 + 64 + c];
      acc[r][0] += wh * h0 + w1 * p0 + w2 * q0;
      acc[r][1] += wh * h1 + w1 * p1 + w2 * q1;
    }
  }

  const float inv0 = rsqrtf(1.0f + 1e-5f);
  #pragma unroll
  for (int r = 0; r < 4; r++) {
    int o = og * 4 + r;
    float gi = gg[o] * inv0, gbb = gb[o];
    float bi = bng[o] * inv0, bbb = bnb[o];
    int ob = base + o * (Nn * Lt);
    #pragma unroll
    for (int jj = 0; jj < 2; jj++) {
      int l = lt + 32 * jj;
      if (l < Lout) {
        float v = (acc[r][jj] + bgc[o]) * gi + gbb;
        v += Res[ob + l + 1];
        Out[ob + l] = v * bi + bbb;
      }
    }
  }
}

extern "C" void kernel_launch(void* const* d_in, const int* in_sizes, int n_in,
                              void* d_out, int out_size) {
  const float* x      = (const float*)d_in[0];
  const float* adj    = (const float*)d_in[1];
  const float* Wstart = (const float*)d_in[2];
  const float* bstart = (const float*)d_in[3];
  const float* Wf     = (const float*)d_in[4];
  const float* bf     = (const float*)d_in[5];
  const float* Wg     = (const float*)d_in[6];
  const float* bg     = (const float*)d_in[7];
  const float* Wsk    = (const float*)d_in[8];
  const float* bsk    = (const float*)d_in[9];
  const float* Wgc    = (const float*)d_in[10];
  const float* bgc    = (const float*)d_in[11];
  const float* gcg    = (const float*)d_in[12];
  const float* gcb    = (const float*)d_in[13];
  const float* bng    = (const float*)d_in[14];
  const float* bnb    = (const float*)d_in[15];
  const float* obng   = (const float*)d_in[16];
  const float* obnb   = (const float*)d_in[17];
  float* out = (float*)d_out;

  float *A, *Bu, *Cu, *Du, *Eu, *SK, *A2p;
  cudaGetSymbolAddress((void**)&A,   g_A);
  cudaGetSymbolAddress((void**)&Bu,  g_B);
  cudaGetSymbolAddress((void**)&Cu,  g_C);
  cudaGetSymbolAddress((void**)&Du,  g_D);
  cudaGetSymbolAddress((void**)&Eu,  g_E);
  cudaGetSymbolAddress((void**)&SK,  g_SK);
  cudaGetSymbolAddress((void**)&A2p, g_A2);

  dim3 bn_grid(Nn, Bn);          // (512, 8)
  dim3 diff_grid(8, Bn * Cch);   // (8 m-tiles, 256 batches)

  k_start<<<BUF / 4 / 256, 256>>>(x, Wstart, bstart, A);
  k_a2<<<dim3(16, 16), dim3(32, 8)>>>(adj, A2p);

  // ---- layer 0 (Lin=64 -> Lout=63) ----
  k_tcn<<<bn_grid, 256>>>(A, Bu, SK, nullptr,
                          Wf, bf, Wg, bg, Wsk, bsk, nullptr, nullptr, 64, 0);
  k_diff<<<diff_grid, 256>>>(Bu, adj, A2p, Cu, Du);
  k_gcmix<<<bn_grid, 256>>>(Bu, Cu, Du, A, Eu,
                            Wgc, bgc, gcg, gcb, bng, bnb, 63);

  // ---- layer 1 (Lin=63 -> Lout=62) ----
  k_tcn<<<bn_grid, 256>>>(Eu, Bu, SK, nullptr,
                          Wf + 2048, bf + 32, Wg + 2048, bg + 32,
                          Wsk + 1024, bsk + 32, nullptr, nullptr, 63, 1);
  k_diff<<<diff_grid, 256>>>(Bu, adj, A2p, Cu, Du);
  k_gcmix<<<bn_grid, 256>>>(Bu, Cu, Du, Eu, A,
                            Wgc + 3072, bgc + 32, gcg + 32, gcb + 32,
                            bng + 32, bnb + 32, 62);

  // ---- layer 2 (Lin=62 -> Lout=61, fused final BN + transpose) ----
  k_tcn<<<bn_grid, 256>>>(A, Bu, SK, out,
                          Wf + 4096, bf + 64, Wg + 4096, bg + 64,
                          Wsk + 2048, bsk + 64, obng, obnb, 62, 2);
}

// round 4
// speedup vs baseline: 1.8989x; 1.8989x over previous
#include <cuda_runtime.h>
#include <math.h>
#include <stdint.h>

#define Bn 8
#define Cch 32
#define Nn 512
#define Lt 64
#define BUF (Bn*Cch*Nn*Lt)

// Scratch (device globals — no allocation allowed)
__device__ float g_A[BUF];
__device__ float g_B[BUF];
__device__ float g_C[BUF];
__device__ float g_D[BUF];
__device__ float g_E[BUF];
__device__ float g_SK[BUF];
__device__ float g_A2[Nn*Nn];

__device__ __forceinline__ float tf32r(float x) {
  uint32_t u;
  asm("cvt.rna.tf32.f32 %0, %1;" : "=r"(u) : "f"(x));
  return __uint_as_float(u);
}

// ---------------- start conv: x[8,2,512,64] -> h[8,32,512,64] ----------------
__global__ void k_start(const float* __restrict__ x, const float* __restrict__ W,
                        const float* __restrict__ bias, float* __restrict__ h) {
  int idx = blockIdx.x * 256 + threadIdx.x;
  if (idx >= BUF) return;
  int l = idx & 63;
  int n = (idx >> 6) & 511;
  int c = (idx >> 15) & 31;
  int b = idx >> 20;
  int xb = ((b * 2) * Nn + n) * Lt + l;
  h[idx] = x[xb] * W[c * 2] + x[xb + Nn * Lt] * W[c * 2 + 1] + bias[c];
}

// ---------------- A2 = adj @ adj  (512x512x512) ----------------
__global__ void k_a2(const float* __restrict__ adj, float* __restrict__ A2) {
  __shared__ float As[32][33], Bs[32][33];
  int tx = threadIdx.x, ty = threadIdx.y;  // (32, 8)
  int p0 = blockIdx.y * 32, m0 = blockIdx.x * 32;
  float acc[4] = {0.f, 0.f, 0.f, 0.f};
  for (int k0 = 0; k0 < Nn; k0 += 32) {
    #pragma unroll
    for (int r = 0; r < 4; r++) {
      As[ty + 8 * r][tx] = adj[(p0 + ty + 8 * r) * Nn + k0 + tx];
      Bs[ty + 8 * r][tx] = adj[(k0 + ty + 8 * r) * Nn + m0 + tx];
    }
    __syncthreads();
    #pragma unroll
    for (int k = 0; k < 32; k++) {
      float bv = Bs[k][tx];
      #pragma unroll
      for (int r = 0; r < 4; r++) acc[r] += As[ty + 8 * r][k] * bv;
    }
    __syncthreads();
  }
  #pragma unroll
  for (int r = 0; r < 4; r++) A2[(p0 + ty + 8 * r) * Nn + m0 + tx] = acc[r];
}

// ---------------- gated TCN + skip (modes: 0 init skip, 1 add skip, 2 final out) ----------------
__global__ void k_tcn(const float* __restrict__ h_in, float* __restrict__ t_out,
                      float* __restrict__ skipbuf, float* __restrict__ outp,
                      const float* __restrict__ Wf, const float* __restrict__ bfv,
                      const float* __restrict__ Wg, const float* __restrict__ bgv,
                      const float* __restrict__ Wsk, const float* __restrict__ bskv,
                      const float* __restrict__ obng, const float* __restrict__ obnb,
                      int Lin, int mode) {
  __shared__ float hs[32][73];
  __shared__ float hns[32][73];
  __shared__ float wfs[2048], wgs[2048], wsks[1024];
  int t = threadIdx.x;
  int n = blockIdx.x, b = blockIdx.y;
  int base = ((b * 32) * Nn + n) * Lt;

  for (int idx = t; idx < 32 * 64; idx += 256) {
    int c = idx >> 6, l = idx & 63;
    hs[c][l] = h_in[base + c * (Nn * Lt) + l];
  }
  for (int idx = t; idx < 2048; idx += 256) { wfs[idx] = Wf[idx]; wgs[idx] = Wg[idx]; }
  for (int idx = t; idx < 1024; idx += 256) wsks[idx] = Wsk[idx];
  __syncthreads();

  int o = t >> 3, sub = t & 7;
  int Lout = Lin - 1;
  int l0 = sub * 8;
  float f[8], g[8];
  float bfo = bfv[o], bgo = bgv[o];
  #pragma unroll
  for (int j = 0; j < 8; j++) { f[j] = bfo; g[j] = bgo; }

  for (int c = 0; c < 32; c++) {
    float wf0 = wfs[(o * 32 + c) * 2], wf1 = wfs[(o * 32 + c) * 2 + 1];
    float wg0 = wgs[(o * 32 + c) * 2], wg1 = wgs[(o * 32 + c) * 2 + 1];
    float hp = hs[c][l0];
    #pragma unroll
    for (int j = 0; j < 8; j++) {
      float hc = hs[c][l0 + j + 1];
      f[j] += hp * wf0 + hc * wf1;
      g[j] += hp * wg0 + hc * wg1;
      hp = hc;
    }
  }

  int obase = base + o * (Nn * Lt);
  #pragma unroll
  for (int j = 0; j < 8; j++) {
    int l = l0 + j;
    float hv = tanhf(f[j]) * (1.0f / (1.0f + expf(-g[j])));
    hns[o][l] = hv;
    if (mode != 2 && l < Lout) t_out[obase + l] = hv;
  }
  __syncthreads();

  float s[8];
  float bs = bskv[o];
  #pragma unroll
  for (int j = 0; j < 8; j++) s[j] = bs;
  for (int c = 0; c < 32; c++) {
    float w = wsks[o * 32 + c];
    #pragma unroll
    for (int j = 0; j < 8; j++) s[j] += w * hns[c][l0 + j];
  }

  if (mode == 0) {
    #pragma unroll
    for (int j = 0; j < 8; j++) {
      int l = l0 + j;
      if (l >= 2 && l < Lout) skipbuf[obase + l - 2] = s[j];
    }
  } else if (mode == 1) {
    #pragma unroll
    for (int j = 0; j < 8; j++) {
      int l = l0 + j;
      if (l >= 1 && l < Lout) skipbuf[obase + l - 1] += s[j];
    }
  } else {
    float inv = obng[o] * rsqrtf(1.0f + 1e-5f);
    float bb = obnb[o];
    #pragma unroll
    for (int j = 0; j < 8; j++) {
      int l = l0 + j;
      if (l < 61)
        outp[((b * 61 + l) * Nn + n) * 32 + o] = (skipbuf[obase + l] + s[j]) * inv + bb;
    }
  }
}

// ---------------- fused diffusion via TF32 mma: X1 = adj^T H, X2 = A2^T H ----------------
// Block tile: 64(m) x 64(l), K=512 in chunks of 32. 8 warps: 4 (m) x 2 (l).
// Each warp: m16, l32 (4 n-tiles of 8), two GEMMs sharing B fragments.
#define PADW 68
__global__ void __launch_bounds__(256, 3) k_diff(
    const float* __restrict__ H, const float* __restrict__ adj,
    const float* __restrict__ A2,
    float* __restrict__ X1, float* __restrict__ X2) {
  __shared__ float Hs[32][PADW], A1s[32][PADW], A2s[32][PADW];
  int t = threadIdx.x;
  int m0 = blockIdx.x * 64;
  int bc = blockIdx.y;
  int hbase = bc * (Nn * Lt);

  int wid = t >> 5, lane = t & 31;
  int wm = (wid & 3) * 16;   // warp m-offset in tile
  int wl = (wid >> 2) * 32;  // warp l-offset in tile
  int grp = lane >> 2, qid = lane & 3;

  float acc1[4][4] = {}, acc2[4][4] = {};

  int lr = t >> 4;            // 0..15 (rows r, r+16)
  int lc = (t & 15) * 4;      // 0..60

  for (int k0 = 0; k0 < Nn; k0 += 32) {
    #pragma unroll
    for (int q = 0; q < 2; q++) {
      int r = lr + q * 16;
      float4 hv = *(const float4*)&H[hbase + (k0 + r) * Lt + lc];
      float4 a1 = *(const float4*)&adj[(k0 + r) * Nn + m0 + lc];
      float4 a2 = *(const float4*)&A2[(k0 + r) * Nn + m0 + lc];
      hv.x = tf32r(hv.x); hv.y = tf32r(hv.y); hv.z = tf32r(hv.z); hv.w = tf32r(hv.w);
      a1.x = tf32r(a1.x); a1.y = tf32r(a1.y); a1.z = tf32r(a1.z); a1.w = tf32r(a1.w);
      a2.x = tf32r(a2.x); a2.y = tf32r(a2.y); a2.z = tf32r(a2.z); a2.w = tf32r(a2.w);
      *(float4*)&Hs[r][lc]  = hv;
      *(float4*)&A1s[r][lc] = a1;
      *(float4*)&A2s[r][lc] = a2;
    }
    __syncthreads();

    #pragma unroll
    for (int kk = 0; kk < 32; kk += 8) {
      int kr0 = kk + qid, kr1 = kk + qid + 4;
      // A fragments (adjT[m][k] = A1s[k][m]); order a0,a1,a2,a3 per PTX mapping
      uint32_t a1f0 = __float_as_uint(A1s[kr0][wm + grp]);
      uint32_t a1f1 = __float_as_uint(A1s[kr0][wm + grp + 8]);
      uint32_t a1f2 = __float_as_uint(A1s[kr1][wm + grp]);
      uint32_t a1f3 = __float_as_uint(A1s[kr1][wm + grp + 8]);
      uint32_t a2f0 = __float_as_uint(A2s[kr0][wm + grp]);
      uint32_t a2f1 = __float_as_uint(A2s[kr0][wm + grp + 8]);
      uint32_t a2f2 = __float_as_uint(A2s[kr1][wm + grp]);
      uint32_t a2f3 = __float_as_uint(A2s[kr1][wm + grp + 8]);
      #pragma unroll
      for (int nt = 0; nt < 4; nt++) {
        uint32_t b0 = __float_as_uint(Hs[kr0][wl + nt * 8 + grp]);
        uint32_t b1 = __float_as_uint(Hs[kr1][wl + nt * 8 + grp]);
        asm volatile(
          "mma.sync.aligned.m16n8k8.row.col.f32.tf32.tf32.f32 "
          "{%0,%1,%2,%3}, {%4,%5,%6,%7}, {%8,%9}, {%0,%1,%2,%3};\n"
          : "+f"(acc1[nt][0]), "+f"(acc1[nt][1]), "+f"(acc1[nt][2]), "+f"(acc1[nt][3])
          : "r"(a1f0), "r"(a1f1), "r"(a1f2), "r"(a1f3), "r"(b0), "r"(b1));
        asm volatile(
          "mma.sync.aligned.m16n8k8.row.col.f32.tf32.tf32.f32 "
          "{%0,%1,%2,%3}, {%4,%5,%6,%7}, {%8,%9}, {%0,%1,%2,%3};\n"
          : "+f"(acc2[nt][0]), "+f"(acc2[nt][1]), "+f"(acc2[nt][2]), "+f"(acc2[nt][3])
          : "r"(a2f0), "r"(a2f1), "r"(a2f2), "r"(a2f3), "r"(b0), "r"(b1));
      }
    }
    __syncthreads();
  }

  // Store: c0,c1 at (row=grp, col=2*qid, 2*qid+1); c2,c3 at row grp+8.
  int row0 = m0 + wm + grp;
  #pragma unroll
  for (int nt = 0; nt < 4; nt++) {
    int col = wl + nt * 8 + 2 * qid;
    float2 v01 = make_float2(acc1[nt][0], acc1[nt][1]);
    float2 v23 = make_float2(acc1[nt][2], acc1[nt][3]);
    *(float2*)&X1[hbase + row0 * Lt + col] = v01;
    *(float2*)&X1[hbase + (row0 + 8) * Lt + col] = v23;
    float2 w01 = make_float2(acc2[nt][0], acc2[nt][1]);
    float2 w23 = make_float2(acc2[nt][2], acc2[nt][3]);
    *(float2*)&X2[hbase + row0 * Lt + col] = w01;
    *(float2*)&X2[hbase + (row0 + 8) * Lt + col] = w23;
  }
}

// ---------------- graph-conv 1x1 (96->32) + BN + residual + BN ----------------
__global__ void k_gcmix(const float* __restrict__ Ht, const float* __restrict__ X1,
                        const float* __restrict__ X2, const float* __restrict__ Res,
                        float* __restrict__ Out,
                        const float* __restrict__ Wgc, const float* __restrict__ bgc,
                        const float* __restrict__ gg, const float* __restrict__ gb,
                        const float* __restrict__ bng, const float* __restrict__ bnb,
                        int Lout) {
  __shared__ float hs[32][64], x1s[32][64], x2s[32][64];
  __shared__ float wgs[32 * 96];
  int t = threadIdx.x;
  int n = blockIdx.x, b = blockIdx.y;
  int base = ((b * 32) * Nn + n) * Lt;

  for (int idx = t; idx < 2048; idx += 256) {
    int c = idx >> 6, l = idx & 63;
    int gptr = base + c * (Nn * Lt) + l;
    hs[c][l] = Ht[gptr];
    x1s[c][l] = X1[gptr];
    x2s[c][l] = X2[gptr];
  }
  for (int idx = t; idx < 3072; idx += 256) wgs[idx] = Wgc[idx];
  __syncthreads();

  int og = t >> 5, lt = t & 31;
  float acc[4][2] = {};
  for (int c = 0; c < 32; c++) {
    float h0 = hs[c][lt],  h1 = hs[c][lt + 32];
    float p0 = x1s[c][lt], p1 = x1s[c][lt + 32];
    float q0 = x2s[c][lt], q1 = x2s[c][lt + 32];
    #pragma unroll
    for (int r = 0; r < 4; r++) {
      int o = og * 4 + r;
      float wh = wgs[o * 96 + c], w1 = wgs[o * 96 + 32 + c], w2 = wgs[o * 96 + 64 + c];
      acc[r][0] += wh * h0 + w1 * p0 + w2 * q0;
      acc[r][1] += wh * h1 + w1 * p1 + w2 * q1;
    }
  }

  const float inv0 = rsqrtf(1.0f + 1e-5f);
  #pragma unroll
  for (int r = 0; r < 4; r++) {
    int o = og * 4 + r;
    float gi = gg[o] * inv0, gbb = gb[o];
    float bi = bng[o] * inv0, bbb = bnb[o];
    int ob = base + o * (Nn * Lt);
    #pragma unroll
    for (int jj = 0; jj < 2; jj++) {
      int l = lt + 32 * jj;
      if (l < Lout) {
        float v = (acc[r][jj] + bgc[o]) * gi + gbb;
        v += Res[ob + l + 1];
        Out[ob + l] = v * bi + bbb;
      }
    }
  }
}

extern "C" void kernel_launch(void* const* d_in, const int* in_sizes, int n_in,
                              void* d_out, int out_size) {
  const float* x      = (const float*)d_in[0];
  const float* adj    = (const float*)d_in[1];
  const float* Wstart = (const float*)d_in[2];
  const float* bstart = (const float*)d_in[3];
  const float* Wf     = (const float*)d_in[4];
  const float* bf     = (const float*)d_in[5];
  const float* Wg     = (const float*)d_in[6];
  const float* bg     = (const float*)d_in[7];
  const float* Wsk    = (const float*)d_in[8];
  const float* bsk    = (const float*)d_in[9];
  const float* Wgc    = (const float*)d_in[10];
  const float* bgc    = (const float*)d_in[11];
  const float* gcg    = (const float*)d_in[12];
  const float* gcb    = (const float*)d_in[13];
  const float* bng    = (const float*)d_in[14];
  const float* bnb    = (const float*)d_in[15];
  const float* obng   = (const float*)d_in[16];
  const float* obnb   = (const float*)d_in[17];
  float* out = (float*)d_out;

  float *A, *Bu, *Cu, *Du, *Eu, *SK, *A2p;
  cudaGetSymbolAddress((void**)&A,   g_A);
  cudaGetSymbolAddress((void**)&Bu,  g_B);
  cudaGetSymbolAddress((void**)&Cu,  g_C);
  cudaGetSymbolAddress((void**)&Du,  g_D);
  cudaGetSymbolAddress((void**)&Eu,  g_E);
  cudaGetSymbolAddress((void**)&SK,  g_SK);
  cudaGetSymbolAddress((void**)&A2p, g_A2);

  dim3 bn_grid(Nn, Bn);          // (512, 8)
  dim3 diff_grid(8, Bn * Cch);   // (8 m-tiles, 256 batches)

  k_start<<<(BUF + 255) / 256, 256>>>(x, Wstart, bstart, A);
  k_a2<<<dim3(16, 16), dim3(32, 8)>>>(adj, A2p);

  // ---- layer 0 (Lin=64 -> Lout=63) ----
  k_tcn<<<bn_grid, 256>>>(A, Bu, SK, nullptr,
                          Wf, bf, Wg, bg, Wsk, bsk, nullptr, nullptr, 64, 0);
  k_diff<<<diff_grid, 256>>>(Bu, adj, A2p, Cu, Du);
  k_gcmix<<<bn_grid, 256>>>(Bu, Cu, Du, A, Eu,
                            Wgc, bgc, gcg, gcb, bng, bnb, 63);

  // ---- layer 1 (Lin=63 -> Lout=62) ----
  k_tcn<<<bn_grid, 256>>>(Eu, Bu, SK, nullptr,
                          Wf + 2048, bf + 32, Wg + 2048, bg + 32,
                          Wsk + 1024, bsk + 32, nullptr, nullptr, 63, 1);
  k_diff<<<diff_grid, 256>>>(Bu, adj, A2p, Cu, Du);
  k_gcmix<<<bn_grid, 256>>>(Bu, Cu, Du, Eu, A,
                            Wgc + 3072, bgc + 32, gcg + 32, gcb + 32,
                            bng + 32, bnb + 32, 62);

  // ---- layer 2 (Lin=62 -> Lout=61, fused final BN + transpose) ----
  k_tcn<<<bn_grid, 256>>>(A, Bu, SK, out,
                          Wf + 4096, bf + 64, Wg + 4096, bg + 64,
                          Wsk + 2048, bsk + 64, obng, obnb, 62, 2);
}

// round 5
// speedup vs baseline: 1.9049x; 1.0031x over previous
#include <cuda_runtime.h>
#include <math.h>
#include <stdint.h>

#define Bn 8
#define Cch 32
#define Nn 512
#define Lt 64
#define BUF (Bn*Cch*Nn*Lt)

__device__ float g_A[BUF];
__device__ float g_B[BUF];
__device__ float g_C[BUF];
__device__ float g_D[BUF];
__device__ float g_E[BUF];
__device__ float g_SK[BUF];
__device__ float g_A2[Nn*Nn];

__device__ __forceinline__ float tf32r(float x) {
  uint32_t u;
  asm("cvt.rna.tf32.f32 %0, %1;" : "=r"(u) : "f"(x));
  return __uint_as_float(u);
}
__device__ __forceinline__ float fsig(float x) {
  return __fdividef(1.0f, 1.0f + __expf(-x));
}
__device__ __forceinline__ float ftanh(float x) {
  float e = __expf(-2.0f * x);
  return __fdividef(1.0f - e, 1.0f + e);
}

// ---------------- start conv ----------------
__global__ void k_start(const float* __restrict__ x, const float* __restrict__ W,
                        const float* __restrict__ bias, float* __restrict__ h) {
  int idx = blockIdx.x * 256 + threadIdx.x;
  if (idx >= BUF) return;
  int l = idx & 63;
  int n = (idx >> 6) & 511;
  int c = (idx >> 15) & 31;
  int b = idx >> 20;
  int xb = ((b * 2) * Nn + n) * Lt + l;
  h[idx] = x[xb] * W[c * 2] + x[xb + Nn * Lt] * W[c * 2 + 1] + bias[c];
}

// ---------------- A2 = adj @ adj ----------------
__global__ void k_a2(const float* __restrict__ adj, float* __restrict__ A2) {
  __shared__ float As[32][33], Bs[32][33];
  int tx = threadIdx.x, ty = threadIdx.y;
  int p0 = blockIdx.y * 32, m0 = blockIdx.x * 32;
  float acc[4] = {0.f, 0.f, 0.f, 0.f};
  for (int k0 = 0; k0 < Nn; k0 += 32) {
    #pragma unroll
    for (int r = 0; r < 4; r++) {
      As[ty + 8 * r][tx] = adj[(p0 + ty + 8 * r) * Nn + k0 + tx];
      Bs[ty + 8 * r][tx] = adj[(k0 + ty + 8 * r) * Nn + m0 + tx];
    }
    __syncthreads();
    #pragma unroll
    for (int k = 0; k < 32; k++) {
      float bv = Bs[k][tx];
      #pragma unroll
      for (int r = 0; r < 4; r++) acc[r] += As[ty + 8 * r][k] * bv;
    }
    __syncthreads();
  }
  #pragma unroll
  for (int r = 0; r < 4; r++) A2[(p0 + ty + 8 * r) * Nn + m0 + tx] = acc[r];
}

// ---------------- standalone gated TCN (layer 0, mode 0) ----------------
__global__ void k_tcn(const float* __restrict__ h_in, float* __restrict__ t_out,
                      float* __restrict__ skipbuf,
                      const float* __restrict__ Wf, const float* __restrict__ bfv,
                      const float* __restrict__ Wg, const float* __restrict__ bgv,
                      const float* __restrict__ Wsk, const float* __restrict__ bskv,
                      int Lin) {
  __shared__ float hs[32][73];
  __shared__ float hns[32][73];
  __shared__ float wfs[2048], wgs[2048], wsks[1024];
  int t = threadIdx.x;
  int n = blockIdx.x, b = blockIdx.y;
  int base = ((b * 32) * Nn + n) * Lt;

  for (int idx = t; idx < 32 * 64; idx += 256) {
    int c = idx >> 6, l = idx & 63;
    hs[c][l] = h_in[base + c * (Nn * Lt) + l];
  }
  for (int idx = t; idx < 2048; idx += 256) { wfs[idx] = Wf[idx]; wgs[idx] = Wg[idx]; }
  for (int idx = t; idx < 1024; idx += 256) wsks[idx] = Wsk[idx];
  __syncthreads();

  int o = t >> 3, sub = t & 7;
  int Lout = Lin - 1;
  int l0 = sub * 8;
  float f[8], g[8];
  float bfo = bfv[o], bgo = bgv[o];
  #pragma unroll
  for (int j = 0; j < 8; j++) { f[j] = bfo; g[j] = bgo; }

  for (int c = 0; c < 32; c++) {
    float wf0 = wfs[(o * 32 + c) * 2], wf1 = wfs[(o * 32 + c) * 2 + 1];
    float wg0 = wgs[(o * 32 + c) * 2], wg1 = wgs[(o * 32 + c) * 2 + 1];
    float hp = hs[c][l0];
    #pragma unroll
    for (int j = 0; j < 8; j++) {
      float hc = hs[c][l0 + j + 1];
      f[j] += hp * wf0 + hc * wf1;
      g[j] += hp * wg0 + hc * wg1;
      hp = hc;
    }
  }

  int obase = base + o * (Nn * Lt);
  #pragma unroll
  for (int j = 0; j < 8; j++) {
    int l = l0 + j;
    float hv = ftanh(f[j]) * fsig(g[j]);
    hns[o][l] = hv;
    if (l < Lout) t_out[obase + l] = hv;
  }
  __syncthreads();

  float s[8];
  float bs = bskv[o];
  #pragma unroll
  for (int j = 0; j < 8; j++) s[j] = bs;
  for (int c = 0; c < 32; c++) {
    float w = wsks[o * 32 + c];
    #pragma unroll
    for (int j = 0; j < 8; j++) s[j] += w * hns[c][l0 + j];
  }
  #pragma unroll
  for (int j = 0; j < 8; j++) {
    int l = l0 + j;
    if (l >= 2 && l < Lout) skipbuf[obase + l - 2] = s[j];
  }
}

// ---------------- fused diffusion (TF32 mma, unchanged) ----------------
#define PADW 68
__global__ void __launch_bounds__(256, 3) k_diff(
    const float* __restrict__ H, const float* __restrict__ adj,
    const float* __restrict__ A2,
    float* __restrict__ X1, float* __restrict__ X2) {
  __shared__ float Hs[32][PADW], A1s[32][PADW], A2s[32][PADW];
  int t = threadIdx.x;
  int m0 = blockIdx.x * 64;
  int bc = blockIdx.y;
  int hbase = bc * (Nn * Lt);

  int wid = t >> 5, lane = t & 31;
  int wm = (wid & 3) * 16;
  int wl = (wid >> 2) * 32;
  int grp = lane >> 2, qid = lane & 3;

  float acc1[4][4] = {}, acc2[4][4] = {};

  int lr = t >> 4;
  int lc = (t & 15) * 4;

  for (int k0 = 0; k0 < Nn; k0 += 32) {
    #pragma unroll
    for (int q = 0; q < 2; q++) {
      int r = lr + q * 16;
      float4 hv = *(const float4*)&H[hbase + (k0 + r) * Lt + lc];
      float4 a1 = *(const float4*)&adj[(k0 + r) * Nn + m0 + lc];
      float4 a2 = *(const float4*)&A2[(k0 + r) * Nn + m0 + lc];
      hv.x = tf32r(hv.x); hv.y = tf32r(hv.y); hv.z = tf32r(hv.z); hv.w = tf32r(hv.w);
      a1.x = tf32r(a1.x); a1.y = tf32r(a1.y); a1.z = tf32r(a1.z); a1.w = tf32r(a1.w);
      a2.x = tf32r(a2.x); a2.y = tf32r(a2.y); a2.z = tf32r(a2.z); a2.w = tf32r(a2.w);
      *(float4*)&Hs[r][lc]  = hv;
      *(float4*)&A1s[r][lc] = a1;
      *(float4*)&A2s[r][lc] = a2;
    }
    __syncthreads();

    #pragma unroll
    for (int kk = 0; kk < 32; kk += 8) {
      int kr0 = kk + qid, kr1 = kk + qid + 4;
      uint32_t a1f0 = __float_as_uint(A1s[kr0][wm + grp]);
      uint32_t a1f1 = __float_as_uint(A1s[kr0][wm + grp + 8]);
      uint32_t a1f2 = __float_as_uint(A1s[kr1][wm + grp]);
      uint32_t a1f3 = __float_as_uint(A1s[kr1][wm + grp + 8]);
      uint32_t a2f0 = __float_as_uint(A2s[kr0][wm + grp]);
      uint32_t a2f1 = __float_as_uint(A2s[kr0][wm + grp + 8]);
      uint32_t a2f2 = __float_as_uint(A2s[kr1][wm + grp]);
      uint32_t a2f3 = __float_as_uint(A2s[kr1][wm + grp + 8]);
      #pragma unroll
      for (int nt = 0; nt < 4; nt++) {
        uint32_t b0 = __float_as_uint(Hs[kr0][wl + nt * 8 + grp]);
        uint32_t b1 = __float_as_uint(Hs[kr1][wl + nt * 8 + grp]);
        asm volatile(
          "mma.sync.aligned.m16n8k8.row.col.f32.tf32.tf32.f32 "
          "{%0,%1,%2,%3}, {%4,%5,%6,%7}, {%8,%9}, {%0,%1,%2,%3};\n"
          : "+f"(acc1[nt][0]), "+f"(acc1[nt][1]), "+f"(acc1[nt][2]), "+f"(acc1[nt][3])
          : "r"(a1f0), "r"(a1f1), "r"(a1f2), "r"(a1f3), "r"(b0), "r"(b1));
        asm volatile(
          "mma.sync.aligned.m16n8k8.row.col.f32.tf32.tf32.f32 "
          "{%0,%1,%2,%3}, {%4,%5,%6,%7}, {%8,%9}, {%0,%1,%2,%3};\n"
          : "+f"(acc2[nt][0]), "+f"(acc2[nt][1]), "+f"(acc2[nt][2]), "+f"(acc2[nt][3])
          : "r"(a2f0), "r"(a2f1), "r"(a2f2), "r"(a2f3), "r"(b0), "r"(b1));
      }
    }
    __syncthreads();
  }

  int row0 = m0 + wm + grp;
  #pragma unroll
  for (int nt = 0; nt < 4; nt++) {
    int col = wl + nt * 8 + 2 * qid;
    *(float2*)&X1[hbase + row0 * Lt + col]       = make_float2(acc1[nt][0], acc1[nt][1]);
    *(float2*)&X1[hbase + (row0 + 8) * Lt + col] = make_float2(acc1[nt][2], acc1[nt][3]);
    *(float2*)&X2[hbase + row0 * Lt + col]       = make_float2(acc2[nt][0], acc2[nt][1]);
    *(float2*)&X2[hbase + (row0 + 8) * Lt + col] = make_float2(acc2[nt][2], acc2[nt][3]);
  }
}

// ---------------- FUSED: gcmix(layer i) + TCN(layer i+1) ----------------
// Phase 1: load H/X1/X2 tiles + Wgc. Phase 2: gcmix -> h2 (smem, overlaid) + optional
// global spill (residual for next fusion); load TCN weights into freed smem.
// Phase 3: gated TCN + skip (mode 1 = add to skipbuf, mode 2 = final BN+transpose).
// smem pool layout (floats):
//   [0, 2176)      hs      -> phase3: wfs (2048)
//   [2176, 4352)   x1s     -> phase3: h2
//   [4352, 6528)   x2s     -> phase3: hns
//   [6528, 9600)   wgs     -> phase3: wgs2 (2048) + wsks (1024)
__global__ void k_fuse(const float* __restrict__ Ht, const float* __restrict__ X1,
                       const float* __restrict__ X2, const float* __restrict__ Res,
                       float* __restrict__ h1_out,
                       const float* __restrict__ Wgc, const float* __restrict__ bgc,
                       const float* __restrict__ gg, const float* __restrict__ gb,
                       const float* __restrict__ bng, const float* __restrict__ bnb,
                       const float* __restrict__ Wf, const float* __restrict__ bfv,
                       const float* __restrict__ Wg, const float* __restrict__ bgv,
                       const float* __restrict__ Wsk, const float* __restrict__ bskv,
                       float* __restrict__ t_out, float* __restrict__ skipbuf,
                       float* __restrict__ outp,
                       const float* __restrict__ obng, const float* __restrict__ obnb,
                       int LoutG, int mode) {
  __shared__ float pool[9600];
  float (*hs)[68]  = (float(*)[68])(pool);
  float (*x1s)[68] = (float(*)[68])(pool + 2176);
  float (*x2s)[68] = (float(*)[68])(pool + 4352);
  float* wgs = pool + 6528;
  // phase-3 overlays
  float* wfs = pool;
  float (*h2)[68]  = (float(*)[68])(pool + 2176);
  float (*hns)[68] = (float(*)[68])(pool + 4352);
  float* wgs2 = pool + 6528;
  float* wsks = pool + 6528 + 2048;

  int t = threadIdx.x;
  int n = blockIdx.x, b = blockIdx.y;
  int base = ((b * 32) * Nn + n) * Lt;

  // ---- phase 1: load gcmix inputs ----
  #pragma unroll
  for (int q = 0; q < 2; q++) {
    int idx = t + q * 256;
    int c = idx >> 4, l4 = (idx & 15) * 4;
    int gptr = base + c * (Nn * Lt) + l4;
    *(float4*)&hs[c][l4]  = *(const float4*)&Ht[gptr];
    *(float4*)&x1s[c][l4] = *(const float4*)&X1[gptr];
    *(float4*)&x2s[c][l4] = *(const float4*)&X2[gptr];
  }
  #pragma unroll
  for (int q = 0; q < 3; q++) {
    int idx = t + q * 256;
    *(float4*)&wgs[idx * 4] = *(const float4*)&Wgc[idx * 4];
  }
  __syncthreads();

  // ---- phase 2: gcmix accumulate (2 o x 4 l per thread) ----
  int op = t >> 4;              // 0..15 -> o0 = op*2
  int o0 = op * 2;
  int lq = (t & 15) * 4;        // l quad
  float acc[2][4] = {};
  for (int c = 0; c < 32; c++) {
    float4 h = *(float4*)&hs[c][lq];
    float4 p = *(float4*)&x1s[c][lq];
    float4 q = *(float4*)&x2s[c][lq];
    #pragma unroll
    for (int r = 0; r < 2; r++) {
      int o = o0 + r;
      float wh = wgs[o * 96 + c], w1 = wgs[o * 96 + 32 + c], w2 = wgs[o * 96 + 64 + c];
      acc[r][0] += wh * h.x + w1 * p.x + w2 * q.x;
      acc[r][1] += wh * h.y + w1 * p.y + w2 * q.y;
      acc[r][2] += wh * h.z + w1 * p.z + w2 * q.z;
      acc[r][3] += wh * h.w + w1 * p.w + w2 * q.w;
    }
  }
  // BN + residual + BN into registers
  const float inv0 = rsqrtf(1.0f + 1e-5f);
  float hv[2][4];
  #pragma unroll
  for (int r = 0; r < 2; r++) {
    int o = o0 + r;
    float gi = gg[o] * inv0, gbb = gb[o];
    float bi = bng[o] * inv0, bbb = bnb[o];
    float bo = bgc[o];
    int ob = base + o * (Nn * Lt);
    #pragma unroll
    for (int j = 0; j < 4; j++) {
      float v = (acc[r][j] + bo) * gi + gbb;
      v += __ldg(&Res[ob + lq + j + 1]);
      hv[r][j] = v * bi + bbb;
    }
  }
  __syncthreads();   // gcmix reads done; safe to overlay

  // write h2 tile + optional global spill; load TCN weights
  #pragma unroll
  for (int r = 0; r < 2; r++) {
    int o = o0 + r;
    *(float4*)&h2[o][lq] = *(float4*)&hv[r][0];
    if (h1_out) {
      int ob = base + o * (Nn * Lt);
      #pragma unroll
      for (int j = 0; j < 4; j++)
        if (lq + j < LoutG) h1_out[ob + lq + j] = hv[r][j];
    }
  }
  #pragma unroll
  for (int q = 0; q < 2; q++) {
    int idx = t + q * 256;
    *(float4*)&wfs[idx * 4]  = *(const float4*)&Wf[idx * 4];
    *(float4*)&wgs2[idx * 4] = *(const float4*)&Wg[idx * 4];
  }
  ((float4*)wsks)[t] = ((const float4*)Wsk)[t];
  __syncthreads();

  // ---- phase 3: gated TCN on h2 (Lin = LoutG) ----
  int o = t >> 3, sub = t & 7;
  int Lin = LoutG;
  int Lout = Lin - 1;
  int l0 = sub * 8;
  float f[8], g[8];
  float bfo = bfv[o], bgo = bgv[o];
  #pragma unroll
  for (int j = 0; j < 8; j++) { f[j] = bfo; g[j] = bgo; }

  for (int c = 0; c < 32; c++) {
    float wf0 = wfs[(o * 32 + c) * 2], wf1 = wfs[(o * 32 + c) * 2 + 1];
    float wg0 = wgs2[(o * 32 + c) * 2], wg1 = wgs2[(o * 32 + c) * 2 + 1];
    float hp = h2[c][l0];
    #pragma unroll
    for (int j = 0; j < 8; j++) {
      float hc = h2[c][l0 + j + 1];
      f[j] += hp * wf0 + hc * wf1;
      g[j] += hp * wg0 + hc * wg1;
      hp = hc;
    }
  }

  int obase = base + o * (Nn * Lt);
  #pragma unroll
  for (int j = 0; j < 8; j++) {
    int l = l0 + j;
    float hvv = ftanh(f[j]) * fsig(g[j]);
    hns[o][l] = hvv;
    if (mode != 2 && l < Lout) t_out[obase + l] = hvv;
  }
  __syncthreads();

  float s[8];
  float bs = bskv[o];
  #pragma unroll
  for (int j = 0; j < 8; j++) s[j] = bs;
  for (int c = 0; c < 32; c++) {
    float w = wsks[o * 32 + c];
    #pragma unroll
    for (int j = 0; j < 8; j++) s[j] += w * hns[c][l0 + j];
  }

  if (mode == 1) {
    #pragma unroll
    for (int j = 0; j < 8; j++) {
      int l = l0 + j;
      if (l >= 1 && l < Lout) skipbuf[obase + l - 1] += s[j];
    }
  } else {
    float inv = obng[o] * inv0;
    float bb = obnb[o];
    #pragma unroll
    for (int j = 0; j < 8; j++) {
      int l = l0 + j;
      if (l < 61)
        outp[((b * 61 + l) * Nn + n) * 32 + o] = (skipbuf[obase + l] + s[j]) * inv + bb;
    }
  }
}

extern "C" void kernel_launch(void* const* d_in, const int* in_sizes, int n_in,
                              void* d_out, int out_size) {
  const float* x      = (const float*)d_in[0];
  const float* adj    = (const float*)d_in[1];
  const float* Wstart = (const float*)d_in[2];
  const float* bstart = (const float*)d_in[3];
  const float* Wf     = (const float*)d_in[4];
  const float* bf     = (const float*)d_in[5];
  const float* Wg     = (const float*)d_in[6];
  const float* bg     = (const float*)d_in[7];
  const float* Wsk    = (const float*)d_in[8];
  const float* bsk    = (const float*)d_in[9];
  const float* Wgc    = (const float*)d_in[10];
  const float* bgc    = (const float*)d_in[11];
  const float* gcg    = (const float*)d_in[12];
  const float* gcb    = (const float*)d_in[13];
  const float* bng    = (const float*)d_in[14];
  const float* bnb    = (const float*)d_in[15];
  const float* obng   = (const float*)d_in[16];
  const float* obnb   = (const float*)d_in[17];
  float* out = (float*)d_out;

  float *A, *Bu, *Cu, *Du, *Eu, *SK, *A2p;
  cudaGetSymbolAddress((void**)&A,   g_A);
  cudaGetSymbolAddress((void**)&Bu,  g_B);
  cudaGetSymbolAddress((void**)&Cu,  g_C);
  cudaGetSymbolAddress((void**)&Du,  g_D);
  cudaGetSymbolAddress((void**)&Eu,  g_E);
  cudaGetSymbolAddress((void**)&SK,  g_SK);
  cudaGetSymbolAddress((void**)&A2p, g_A2);

  dim3 bn_grid(Nn, Bn);
  dim3 diff_grid(8, Bn * Cch);

  k_start<<<(BUF + 255) / 256, 256>>>(x, Wstart, bstart, A);
  k_a2<<<dim3(16, 16), dim3(32, 8)>>>(adj, A2p);

  // layer 0 TCN (Lin=64)
  k_tcn<<<bn_grid, 256>>>(A, Bu, SK, Wf, bf, Wg, bg, Wsk, bsk, 64);
  k_diff<<<diff_grid, 256>>>(Bu, adj, A2p, Cu, Du);

  // gcmix(layer0) + TCN(layer1): LoutG=63, mode 1; spills h1 -> Eu (residual for next)
  k_fuse<<<bn_grid, 256>>>(Bu, Cu, Du, A, Eu,
                           Wgc, bgc, gcg, gcb, bng, bnb,
                           Wf + 2048, bf + 32, Wg + 2048, bg + 32,
                           Wsk + 1024, bsk + 32,
                           Bu, SK, nullptr, nullptr, nullptr, 63, 1);
  k_diff<<<diff_grid, 256>>>(Bu, adj, A2p, Cu, Du);

  // gcmix(layer1) + TCN(layer2, final): LoutG=62, mode 2
  k_fuse<<<bn_grid, 256>>>(Bu, Cu, Du, Eu, nullptr,
                           Wgc + 3072, bgc + 32, gcg + 32, gcb + 32,
                           bng + 32, bnb + 32,
                           Wf + 4096, bf + 64, Wg + 4096, bg + 64,
                           Wsk + 2048, bsk + 64,
                           nullptr, SK, out, obng, obnb, 62, 2);
}

// round 9
// speedup vs baseline: 2.0370x; 1.0694x over previous
#include <cuda_runtime.h>
#include <cuda_fp16.h>
#include <math.h>
#include <stdint.h>

#define Bn 8
#define Cch 32
#define Nn 512
#define Lt 64
#define BUF (Bn*Cch*Nn*Lt)

// Scratch (device globals). Big tensors in fp16, skip accumulator in fp32.
__device__ __half g_A[BUF];    // h (start output / residual 0)
__device__ __half g_B[BUF];    // H (TCN output)
__device__ __half g_C[BUF];    // X1
__device__ __half g_D[BUF];    // X2
__device__ __half g_E[BUF];    // h1 (residual 1)
__device__ float  g_SK[BUF];   // skip accumulator
__device__ float  g_A2[Nn*Nn];

__device__ __forceinline__ float tf32r(float x) {
  uint32_t u;
  asm("cvt.rna.tf32.f32 %0, %1;" : "=r"(u) : "f"(x));
  return __uint_as_float(u);
}
__device__ __forceinline__ float fsig(float x) {
  return __fdividef(1.0f, 1.0f + __expf(-x));
}
__device__ __forceinline__ float ftanh(float x) {
  float e = __expf(-2.0f * x);
  return __fdividef(1.0f - e, 1.0f + e);
}

// ---------------- start conv: x[8,2,512,64] -> h[8,32,512,64] (fp16 out) ----------------
__global__ void k_start(const float* __restrict__ x, const float* __restrict__ W,
                        const float* __restrict__ bias, __half* __restrict__ h) {
  int idx4 = blockIdx.x * 256 + threadIdx.x;  // BUF/4 quads
  int l4 = (idx4 & 15) * 4;
  int n  = (idx4 >> 4) & 511;
  int c  = (idx4 >> 13) & 31;
  int b  = idx4 >> 18;
  int xb = ((b * 2) * Nn + n) * Lt + l4;
  float4 x0 = *(const float4*)&x[xb];
  float4 x1 = *(const float4*)&x[xb + Nn * Lt];
  float w0 = W[c * 2], w1 = W[c * 2 + 1], bs = bias[c];
  int ob = (((b * 32 + c) * Nn + n) * Lt) + l4;
  *(__half2*)&h[ob]     = __floats2half2_rn(x0.x * w0 + x1.x * w1 + bs,
                                            x0.y * w0 + x1.y * w1 + bs);
  *(__half2*)&h[ob + 2] = __floats2half2_rn(x0.z * w0 + x1.z * w1 + bs,
                                            x0.w * w0 + x1.w * w1 + bs);
}

// ---------------- A2 = adj @ adj ----------------
__global__ void k_a2(const float* __restrict__ adj, float* __restrict__ A2) {
  __shared__ float As[32][33], Bs[32][33];
  int tx = threadIdx.x, ty = threadIdx.y;
  int p0 = blockIdx.y * 32, m0 = blockIdx.x * 32;
  float acc[4] = {0.f, 0.f, 0.f, 0.f};
  for (int k0 = 0; k0 < Nn; k0 += 32) {
    #pragma unroll
    for (int r = 0; r < 4; r++) {
      As[ty + 8 * r][tx] = adj[(p0 + ty + 8 * r) * Nn + k0 + tx];
      Bs[ty + 8 * r][tx] = adj[(k0 + ty + 8 * r) * Nn + m0 + tx];
    }
    __syncthreads();
    #pragma unroll
    for (int k = 0; k < 32; k++) {
      float bv = Bs[k][tx];
      #pragma unroll
      for (int r = 0; r < 4; r++) acc[r] += As[ty + 8 * r][k] * bv;
    }
    __syncthreads();
  }
  #pragma unroll
  for (int r = 0; r < 4; r++) A2[(p0 + ty + 8 * r) * Nn + m0 + tx] = acc[r];
}

// ---------------- standalone gated TCN (layer 0) ----------------
__global__ void k_tcn(const __half* __restrict__ h_in, __half* __restrict__ t_out,
                      float* __restrict__ skipbuf,
                      const float* __restrict__ Wf, const float* __restrict__ bfv,
                      const float* __restrict__ Wg, const float* __restrict__ bgv,
                      const float* __restrict__ Wsk, const float* __restrict__ bskv,
                      int Lin) {
  __shared__ float hs[32][73];
  __shared__ float hns[32][73];
  __shared__ float wfs[2048], wgs[2048], wsks[1024];
  int t = threadIdx.x;
  int n = blockIdx.x, b = blockIdx.y;
  int base = ((b * 32) * Nn + n) * Lt;

  for (int idx = t; idx < 1024; idx += 256) {
    int c = idx >> 5, l2 = (idx & 31) * 2;
    float2 v = __half22float2(*(const __half2*)&h_in[base + c * (Nn * Lt) + l2]);
    hs[c][l2] = v.x; hs[c][l2 + 1] = v.y;
  }
  for (int idx = t; idx < 2048; idx += 256) { wfs[idx] = Wf[idx]; wgs[idx] = Wg[idx]; }
  for (int idx = t; idx < 1024; idx += 256) wsks[idx] = Wsk[idx];
  __syncthreads();

  int o = t >> 3, sub = t & 7;
  int Lout = Lin - 1;
  int l0 = sub * 8;
  float f[8], g[8];
  float bfo = bfv[o], bgo = bgv[o];
  #pragma unroll
  for (int j = 0; j < 8; j++) { f[j] = bfo; g[j] = bgo; }

  for (int c = 0; c < 32; c++) {
    float wf0 = wfs[(o * 32 + c) * 2], wf1 = wfs[(o * 32 + c) * 2 + 1];
    float wg0 = wgs[(o * 32 + c) * 2], wg1 = wgs[(o * 32 + c) * 2 + 1];
    float hp = hs[c][l0];
    #pragma unroll
    for (int j = 0; j < 8; j++) {
      float hc = hs[c][l0 + j + 1];
      f[j] += hp * wf0 + hc * wf1;
      g[j] += hp * wg0 + hc * wg1;
      hp = hc;
    }
  }

  int obase = base + o * (Nn * Lt);
  #pragma unroll
  for (int j = 0; j < 8; j++) {
    int l = l0 + j;
    float hv = ftanh(f[j]) * fsig(g[j]);
    hns[o][l] = hv;
    if (l < Lout) t_out[obase + l] = __float2half_rn(hv);
  }
  __syncthreads();

  float s[8];
  float bs = bskv[o];
  #pragma unroll
  for (int j = 0; j < 8; j++) s[j] = bs;
  for (int c = 0; c < 32; c++) {
    float w = wsks[o * 32 + c];
    #pragma unroll
    for (int j = 0; j < 8; j++) s[j] += w * hns[c][l0 + j];
  }
  #pragma unroll
  for (int j = 0; j < 8; j++) {
    int l = l0 + j;
    if (l >= 2 && l < Lout) skipbuf[obase + l - 2] = s[j];
  }
}

// ---------------- fused diffusion (TF32 mma), fp16 H in / fp16 X out ----------------
#define PADW 68
__global__ void __launch_bounds__(256, 3) k_diff(
    const __half* __restrict__ H, const float* __restrict__ adj,
    const float* __restrict__ A2,
    __half* __restrict__ X1, __half* __restrict__ X2) {
  __shared__ float Hs[32][PADW], A1s[32][PADW], A2s[32][PADW];
  int t = threadIdx.x;
  int m0 = blockIdx.x * 64;
  int bc = blockIdx.y;
  int hbase = bc * (Nn * Lt);

  int wid = t >> 5, lane = t & 31;
  int wm = (wid & 3) * 16;
  int wl = (wid >> 2) * 32;
  int grp = lane >> 2, qid = lane & 3;

  float acc1[4][4] = {}, acc2[4][4] = {};

  int lr = t >> 4;
  int lc = (t & 15) * 4;

  for (int k0 = 0; k0 < Nn; k0 += 32) {
    #pragma unroll
    for (int q = 0; q < 2; q++) {
      int r = lr + q * 16;
      const __half* hp = &H[hbase + (k0 + r) * Lt + lc];
      float2 h01 = __half22float2(*(const __half2*)hp);
      float2 h23 = __half22float2(*(const __half2*)(hp + 2));
      float4 a1 = *(const float4*)&adj[(k0 + r) * Nn + m0 + lc];
      float4 a2 = *(const float4*)&A2[(k0 + r) * Nn + m0 + lc];
      a1.x = tf32r(a1.x); a1.y = tf32r(a1.y); a1.z = tf32r(a1.z); a1.w = tf32r(a1.w);
      a2.x = tf32r(a2.x); a2.y = tf32r(a2.y); a2.z = tf32r(a2.z); a2.w = tf32r(a2.w);
      Hs[r][lc] = h01.x; Hs[r][lc + 1] = h01.y; Hs[r][lc + 2] = h23.x; Hs[r][lc + 3] = h23.y;
      *(float4*)&A1s[r][lc] = a1;
      *(float4*)&A2s[r][lc] = a2;
    }
    __syncthreads();

    #pragma unroll
    for (int kk = 0; kk < 32; kk += 8) {
      int kr0 = kk + qid, kr1 = kk + qid + 4;
      uint32_t a1f0 = __float_as_uint(A1s[kr0][wm + grp]);
      uint32_t a1f1 = __float_as_uint(A1s[kr0][wm + grp + 8]);
      uint32_t a1f2 = __float_as_uint(A1s[kr1][wm + grp]);
      uint32_t a1f3 = __float_as_uint(A1s[kr1][wm + grp + 8]);
      uint32_t a2f0 = __float_as_uint(A2s[kr0][wm + grp]);
      uint32_t a2f1 = __float_as_uint(A2s[kr0][wm + grp + 8]);
      uint32_t a2f2 = __float_as_uint(A2s[kr1][wm + grp]);
      uint32_t a2f3 = __float_as_uint(A2s[kr1][wm + grp + 8]);
      #pragma unroll
      for (int nt = 0; nt < 4; nt++) {
        uint32_t b0 = __float_as_uint(Hs[kr0][wl + nt * 8 + grp]);
        uint32_t b1 = __float_as_uint(Hs[kr1][wl + nt * 8 + grp]);
        asm volatile(
          "mma.sync.aligned.m16n8k8.row.col.f32.tf32.tf32.f32 "
          "{%0,%1,%2,%3}, {%4,%5,%6,%7}, {%8,%9}, {%0,%1,%2,%3};\n"
          : "+f"(acc1[nt][0]), "+f"(acc1[nt][1]), "+f"(acc1[nt][2]), "+f"(acc1[nt][3])
          : "r"(a1f0), "r"(a1f1), "r"(a1f2), "r"(a1f3), "r"(b0), "r"(b1));
        asm volatile(
          "mma.sync.aligned.m16n8k8.row.col.f32.tf32.tf32.f32 "
          "{%0,%1,%2,%3}, {%4,%5,%6,%7}, {%8,%9}, {%0,%1,%2,%3};\n"
          : "+f"(acc2[nt][0]), "+f"(acc2[nt][1]), "+f"(acc2[nt][2]), "+f"(acc2[nt][3])
          : "r"(a2f0), "r"(a2f1), "r"(a2f2), "r"(a2f3), "r"(b0), "r"(b1));
      }
    }
    __syncthreads();
  }

  int row0 = m0 + wm + grp;
  #pragma unroll
  for (int nt = 0; nt < 4; nt++) {
    int col = wl + nt * 8 + 2 * qid;
    *(__half2*)&X1[hbase + row0 * Lt + col]       = __floats2half2_rn(acc1[nt][0], acc1[nt][1]);
    *(__half2*)&X1[hbase + (row0 + 8) * Lt + col] = __floats2half2_rn(acc1[nt][2], acc1[nt][3]);
    *(__half2*)&X2[hbase + row0 * Lt + col]       = __floats2half2_rn(acc2[nt][0], acc2[nt][1]);
    *(__half2*)&X2[hbase + (row0 + 8) * Lt + col] = __floats2half2_rn(acc2[nt][2], acc2[nt][3]);
  }
}

// ---------------- FUSED: gcmix(layer i) + TCN(layer i+1) ----------------
__global__ void k_fuse(const __half* __restrict__ Ht, const __half* __restrict__ X1,
                       const __half* __restrict__ X2, const __half* __restrict__ Res,
                       __half* __restrict__ h1_out,
                       const float* __restrict__ Wgc, const float* __restrict__ bgc,
                       const float* __restrict__ gg, const float* __restrict__ gb,
                       const float* __restrict__ bng, const float* __restrict__ bnb,
                       const float* __restrict__ Wf, const float* __restrict__ bfv,
                       const float* __restrict__ Wg, const float* __restrict__ bgv,
                       const float* __restrict__ Wsk, const float* __restrict__ bskv,
                       __half* __restrict__ t_out, float* __restrict__ skipbuf,
                       float* __restrict__ outp,
                       const float* __restrict__ obng, const float* __restrict__ obnb,
                       int LoutG, int mode) {
  __shared__ float pool[9600];
  float (*hs)[68]  = (float(*)[68])(pool);
  float (*x1s)[68] = (float(*)[68])(pool + 2176);
  float (*x2s)[68] = (float(*)[68])(pool + 4352);
  float* wgs = pool + 6528;
  float* wfs = pool;
  float (*h2)[68]  = (float(*)[68])(pool + 2176);
  float (*hns)[68] = (float(*)[68])(pool + 4352);
  float* wgs2 = pool + 6528;
  float* wsks = pool + 6528 + 2048;

  int t = threadIdx.x;
  int n = blockIdx.x, b = blockIdx.y;
  int base = ((b * 32) * Nn + n) * Lt;

  // ---- phase 1 ----
  #pragma unroll
  for (int q = 0; q < 2; q++) {
    int idx = t + q * 256;
    int c = idx >> 4, l4 = (idx & 15) * 4;
    int gptr = base + c * (Nn * Lt) + l4;
    float2 ha = __half22float2(*(const __half2*)&Ht[gptr]);
    float2 hb = __half22float2(*(const __half2*)&Ht[gptr + 2]);
    float2 pa = __half22float2(*(const __half2*)&X1[gptr]);
    float2 pb = __half22float2(*(const __half2*)&X1[gptr + 2]);
    float2 qa = __half22float2(*(const __half2*)&X2[gptr]);
    float2 qb = __half22float2(*(const __half2*)&X2[gptr + 2]);
    hs[c][l4] = ha.x; hs[c][l4+1] = ha.y; hs[c][l4+2] = hb.x; hs[c][l4+3] = hb.y;
    x1s[c][l4] = pa.x; x1s[c][l4+1] = pa.y; x1s[c][l4+2] = pb.x; x1s[c][l4+3] = pb.y;
    x2s[c][l4] = qa.x; x2s[c][l4+1] = qa.y; x2s[c][l4+2] = qb.x; x2s[c][l4+3] = qb.y;
  }
  #pragma unroll
  for (int q = 0; q < 3; q++) {
    int idx = t + q * 256;
    *(float4*)&wgs[idx * 4] = *(const float4*)&Wgc[idx * 4];
  }
  __syncthreads();

  // ---- phase 2: gcmix ----
  int op = t >> 4;
  int o0 = op * 2;
  int lq = (t & 15) * 4;
  float acc[2][4] = {};
  for (int c = 0; c < 32; c++) {
    float4 h = *(float4*)&hs[c][lq];
    float4 p = *(float4*)&x1s[c][lq];
    float4 q = *(float4*)&x2s[c][lq];
    #pragma unroll
    for (int r = 0; r < 2; r++) {
      int o = o0 + r;
      float wh = wgs[o * 96 + c], w1 = wgs[o * 96 + 32 + c], w2 = wgs[o * 96 + 64 + c];
      acc[r][0] += wh * h.x + w1 * p.x + w2 * q.x;
      acc[r][1] += wh * h.y + w1 * p.y + w2 * q.y;
      acc[r][2] += wh * h.z + w1 * p.z + w2 * q.z;
      acc[r][3] += wh * h.w + w1 * p.w + w2 * q.w;
    }
  }
  const float inv0 = rsqrtf(1.0f + 1e-5f);
  float hv[2][4];
  #pragma unroll
  for (int r = 0; r < 2; r++) {
    int o = o0 + r;
    float gi = gg[o] * inv0, gbb = gb[o];
    float bi = bng[o] * inv0, bbb = bnb[o];
    float bo = bgc[o];
    int ob = base + o * (Nn * Lt);
    #pragma unroll
    for (int j = 0; j < 4; j++) {
      float v = (acc[r][j] + bo) * gi + gbb;
      v += __half2float(Res[ob + lq + j + 1]);
      hv[r][j] = v * bi + bbb;
    }
  }
  __syncthreads();

  #pragma unroll
  for (int r = 0; r < 2; r++) {
    int o = o0 + r;
    *(float4*)&h2[o][lq] = *(float4*)&hv[r][0];
    if (h1_out) {
      int ob = base + o * (Nn * Lt);
      #pragma unroll
      for (int j = 0; j < 4; j++)
        if (lq + j < LoutG) h1_out[ob + lq + j] = __float2half_rn(hv[r][j]);
    }
  }
  #pragma unroll
  for (int q = 0; q < 2; q++) {
    int idx = t + q * 256;
    *(float4*)&wfs[idx * 4]  = *(const float4*)&Wf[idx * 4];
    *(float4*)&wgs2[idx * 4] = *(const float4*)&Wg[idx * 4];
  }
  ((float4*)wsks)[t] = ((const float4*)Wsk)[t];
  __syncthreads();

  // ---- phase 3: gated TCN ----
  int o = t >> 3, sub = t & 7;
  int Lin = LoutG;
  int Lout = Lin - 1;
  int l0 = sub * 8;
  float f[8], g[8];
  float bfo = bfv[o], bgo = bgv[o];
  #pragma unroll
  for (int j = 0; j < 8; j++) { f[j] = bfo; g[j] = bgo; }

  for (int c = 0; c < 32; c++) {
    float wf0 = wfs[(o * 32 + c) * 2], wf1 = wfs[(o * 32 + c) * 2 + 1];
    float wg0 = wgs2[(o * 32 + c) * 2], wg1 = wgs2[(o * 32 + c) * 2 + 1];
    float hp = h2[c][l0];
    #pragma unroll
    for (int j = 0; j < 8; j++) {
      float hc = h2[c][l0 + j + 1];
      f[j] += hp * wf0 + hc * wf1;
      g[j] += hp * wg0 + hc * wg1;
      hp = hc;
    }
  }

  int obase = base + o * (Nn * Lt);
  #pragma unroll
  for (int j = 0; j < 8; j++) {
    int l = l0 + j;
    float hvv = ftanh(f[j]) * fsig(g[j]);
    hns[o][l] = hvv;
    if (mode != 2 && l < Lout) t_out[obase + l] = __float2half_rn(hvv);
  }
  __syncthreads();

  float s[8];
  float bs = bskv[o];
  #pragma unroll
  for (int j = 0; j < 8; j++) s[j] = bs;
  for (int c = 0; c < 32; c++) {
    float w = wsks[o * 32 + c];
    #pragma unroll
    for (int j = 0; j < 8; j++) s[j] += w * hns[c][l0 + j];
  }

  if (mode == 1) {
    #pragma unroll
    for (int j = 0; j < 8; j++) {
      int l = l0 + j;
      if (l >= 1 && l < Lout) skipbuf[obase + l - 1] += s[j];
    }
  } else {
    float inv = obng[o] * inv0;
    float bb = obnb[o];
    #pragma unroll
    for (int j = 0; j < 8; j++) {
      int l = l0 + j;
      if (l < 61)
        outp[((b * 61 + l) * Nn + n) * 32 + o] = (skipbuf[obase + l] + s[j]) * inv + bb;
    }
  }
}

extern "C" void kernel_launch(void* const* d_in, const int* in_sizes, int n_in,
                              void* d_out, int out_size) {
  const float* x      = (const float*)d_in[0];
  const float* adj    = (const float*)d_in[1];
  const float* Wstart = (const float*)d_in[2];
  const float* bstart = (const float*)d_in[3];
  const float* Wf     = (const float*)d_in[4];
  const float* bf     = (const float*)d_in[5];
  const float* Wg     = (const float*)d_in[6];
  const float* bg     = (const float*)d_in[7];
  const float* Wsk    = (const float*)d_in[8];
  const float* bsk    = (const float*)d_in[9];
  const float* Wgc    = (const float*)d_in[10];
  const float* bgc    = (const float*)d_in[11];
  const float* gcg    = (const float*)d_in[12];
  const float* gcb    = (const float*)d_in[13];
  const float* bng    = (const float*)d_in[14];
  const float* bnb    = (const float*)d_in[15];
  const float* obng   = (const float*)d_in[16];
  const float* obnb   = (const float*)d_in[17];
  float* out = (float*)d_out;

  __half *A, *Bu, *Cu, *Du, *Eu;
  float *SK, *A2p;
  cudaGetSymbolAddress((void**)&A,   g_A);
  cudaGetSymbolAddress((void**)&Bu,  g_B);
  cudaGetSymbolAddress((void**)&Cu,  g_C);
  cudaGetSymbolAddress((void**)&Du,  g_D);
  cudaGetSymbolAddress((void**)&Eu,  g_E);
  cudaGetSymbolAddress((void**)&SK,  g_SK);
  cudaGetSymbolAddress((void**)&A2p, g_A2);

  dim3 bn_grid(Nn, Bn);
  dim3 diff_grid(8, Bn * Cch);

  k_start<<<BUF / 4 / 256, 256>>>(x, Wstart, bstart, A);
  k_a2<<<dim3(16, 16), dim3(32, 8)>>>(adj, A2p);

  // layer 0 TCN (Lin=64)
  k_tcn<<<bn_grid, 256>>>(A, Bu, SK, Wf, bf, Wg, bg, Wsk, bsk, 64);
  k_diff<<<diff_grid, 256>>>(Bu, adj, A2p, Cu, Du);

  // gcmix(layer0) + TCN(layer1): LoutG=63, mode 1; spills h1 -> Eu
  k_fuse<<<bn_grid, 256>>>(Bu, Cu, Du, A, Eu,
                           Wgc, bgc, gcg, gcb, bng, bnb,
                           Wf + 2048, bf + 32, Wg + 2048, bg + 32,
                           Wsk + 1024, bsk + 32,
                           Bu, SK, nullptr, nullptr, nullptr, 63, 1);
  k_diff<<<diff_grid, 256>>>(Bu, adj, A2p, Cu, Du);

  // gcmix(layer1) + TCN(layer2, final): LoutG=62, mode 2
  k_fuse<<<bn_grid, 256>>>(Bu, Cu, Du, Eu, nullptr,
                           Wgc + 3072, bgc + 32, gcg + 32, gcb + 32,
                           bng + 32, bnb + 32,
                           Wf + 4096, bf + 64, Wg + 4096, bg + 64,
                           Wsk + 2048, bsk + 64,
                           nullptr, SK, out, obng, obnb, 62, 2);
}

// round 10
// speedup vs baseline: 2.5545x; 1.2540x over previous
#include <cuda_runtime.h>
#include <cuda_fp16.h>
#include <math.h>
#include <stdint.h>

#define Bn 8
#define Cch 32
#define Nn 512
#define Lt 64
#define BUF (Bn*Cch*Nn*Lt)

// Scratch (device globals). Big tensors fp16, skip accumulator fp32.
__device__ __half g_A[BUF];      // h (start output / residual 0)
__device__ __half g_B[BUF];      // H (TCN output)
__device__ __half g_C[BUF];      // X1
__device__ __half g_D[BUF];      // X2
__device__ __half g_E[BUF];      // h1 (residual 1)
__device__ float  g_SK[BUF];     // skip accumulator
__device__ __half g_adjh[Nn*Nn]; // adj fp16
__device__ __half g_A2h[Nn*Nn];  // adj@adj fp16

__device__ __forceinline__ float fsig(float x) {
  return __fdividef(1.0f, 1.0f + __expf(-x));
}
__device__ __forceinline__ float ftanh(float x) {
  float e = __expf(-2.0f * x);
  return __fdividef(1.0f - e, 1.0f + e);
}
__device__ __forceinline__ void ldsm4t(uint32_t* r, uint32_t addr) {
  asm volatile("ldmatrix.sync.aligned.m8n8.x4.trans.shared.b16 {%0,%1,%2,%3}, [%4];"
    : "=r"(r[0]), "=r"(r[1]), "=r"(r[2]), "=r"(r[3]) : "r"(addr));
}
__device__ __forceinline__ void mma16816(float* c, const uint32_t* a, uint32_t b0, uint32_t b1) {
  asm volatile("mma.sync.aligned.m16n8k16.row.col.f32.f16.f16.f32 "
    "{%0,%1,%2,%3}, {%4,%5,%6,%7}, {%8,%9}, {%0,%1,%2,%3};"
    : "+f"(c[0]), "+f"(c[1]), "+f"(c[2]), "+f"(c[3])
    : "r"(a[0]), "r"(a[1]), "r"(a[2]), "r"(a[3]), "r"(b0), "r"(b1));
}

// ---------------- start conv: x[8,2,512,64] -> h (fp16) ----------------
__global__ void k_start(const float* __restrict__ x, const float* __restrict__ W,
                        const float* __restrict__ bias, __half* __restrict__ h) {
  int idx4 = blockIdx.x * 256 + threadIdx.x;
  int l4 = (idx4 & 15) * 4;
  int n  = (idx4 >> 4) & 511;
  int c  = (idx4 >> 13) & 31;
  int b  = idx4 >> 18;
  int xb = ((b * 2) * Nn + n) * Lt + l4;
  float4 x0 = *(const float4*)&x[xb];
  float4 x1 = *(const float4*)&x[xb + Nn * Lt];
  float w0 = W[c * 2], w1 = W[c * 2 + 1], bs = bias[c];
  int ob = (((b * 32 + c) * Nn + n) * Lt) + l4;
  *(__half2*)&h[ob]     = __floats2half2_rn(x0.x * w0 + x1.x * w1 + bs,
                                            x0.y * w0 + x1.y * w1 + bs);
  *(__half2*)&h[ob + 2] = __floats2half2_rn(x0.z * w0 + x1.z * w1 + bs,
                                            x0.w * w0 + x1.w * w1 + bs);
}

// ---------------- adj -> fp16 ----------------
__global__ void k_adjh(const float* __restrict__ adj, __half* __restrict__ adjh) {
  int i4 = blockIdx.x * 256 + threadIdx.x;   // Nn*Nn/4 quads
  float4 v = *(const float4*)&adj[i4 * 4];
  *(__half2*)&adjh[i4 * 4]     = __floats2half2_rn(v.x, v.y);
  *(__half2*)&adjh[i4 * 4 + 2] = __floats2half2_rn(v.z, v.w);
}

// ---------------- A2 = adj @ adj (fp32 compute, fp16 out) ----------------
__global__ void k_a2(const float* __restrict__ adj, __half* __restrict__ A2h) {
  __shared__ float As[32][33], Bs[32][33];
  int tx = threadIdx.x, ty = threadIdx.y;
  int p0 = blockIdx.y * 32, m0 = blockIdx.x * 32;
  float acc[4] = {0.f, 0.f, 0.f, 0.f};
  for (int k0 = 0; k0 < Nn; k0 += 32) {
    #pragma unroll
    for (int r = 0; r < 4; r++) {
      As[ty + 8 * r][tx] = adj[(p0 + ty + 8 * r) * Nn + k0 + tx];
      Bs[ty + 8 * r][tx] = adj[(k0 + ty + 8 * r) * Nn + m0 + tx];
    }
    __syncthreads();
    #pragma unroll
    for (int k = 0; k < 32; k++) {
      float bv = Bs[k][tx];
      #pragma unroll
      for (int r = 0; r < 4; r++) acc[r] += As[ty + 8 * r][k] * bv;
    }
    __syncthreads();
  }
  #pragma unroll
  for (int r = 0; r < 4; r++)
    A2h[(p0 + ty + 8 * r) * Nn + m0 + tx] = __float2half_rn(acc[r]);
}

// ---------------- standalone gated TCN (layer 0) ----------------
__global__ void k_tcn(const __half* __restrict__ h_in, __half* __restrict__ t_out,
                      float* __restrict__ skipbuf,
                      const float* __restrict__ Wf, const float* __restrict__ bfv,
                      const float* __restrict__ Wg, const float* __restrict__ bgv,
                      const float* __restrict__ Wsk, const float* __restrict__ bskv,
                      int Lin) {
  __shared__ float hs[32][73];
  __shared__ float hns[32][73];
  __shared__ float wfs[2048], wgs[2048], wsks[1024];
  int t = threadIdx.x;
  int n = blockIdx.x, b = blockIdx.y;
  int base = ((b * 32) * Nn + n) * Lt;

  for (int idx = t; idx < 1024; idx += 256) {
    int c = idx >> 5, l2 = (idx & 31) * 2;
    float2 v = __half22float2(*(const __half2*)&h_in[base + c * (Nn * Lt) + l2]);
    hs[c][l2] = v.x; hs[c][l2 + 1] = v.y;
  }
  for (int idx = t; idx < 2048; idx += 256) { wfs[idx] = Wf[idx]; wgs[idx] = Wg[idx]; }
  for (int idx = t; idx < 1024; idx += 256) wsks[idx] = Wsk[idx];
  __syncthreads();

  int o = t >> 3, sub = t & 7;
  int Lout = Lin - 1;
  int l0 = sub * 8;
  float f[8], g[8];
  float bfo = bfv[o], bgo = bgv[o];
  #pragma unroll
  for (int j = 0; j < 8; j++) { f[j] = bfo; g[j] = bgo; }

  for (int c = 0; c < 32; c++) {
    float wf0 = wfs[(o * 32 + c) * 2], wf1 = wfs[(o * 32 + c) * 2 + 1];
    float wg0 = wgs[(o * 32 + c) * 2], wg1 = wgs[(o * 32 + c) * 2 + 1];
    float hp = hs[c][l0];
    #pragma unroll
    for (int j = 0; j < 8; j++) {
      float hc = hs[c][l0 + j + 1];
      f[j] += hp * wf0 + hc * wf1;
      g[j] += hp * wg0 + hc * wg1;
      hp = hc;
    }
  }

  int obase = base + o * (Nn * Lt);
  #pragma unroll
  for (int j = 0; j < 8; j++) {
    int l = l0 + j;
    float hv = ftanh(f[j]) * fsig(g[j]);
    hns[o][l] = hv;
    if (l < Lout) t_out[obase + l] = __float2half_rn(hv);
  }
  __syncthreads();

  float s[8];
  float bs = bskv[o];
  #pragma unroll
  for (int j = 0; j < 8; j++) s[j] = bs;
  for (int c = 0; c < 32; c++) {
    float w = wsks[o * 32 + c];
    #pragma unroll
    for (int j = 0; j < 8; j++) s[j] += w * hns[c][l0 + j];
  }
  #pragma unroll
  for (int j = 0; j < 8; j++) {
    int l = l0 + j;
    if (l >= 2 && l < Lout) skipbuf[obase + l - 2] = s[j];
  }
}

// ---------------- fused diffusion: fp16 HMMA + ldmatrix ----------------
// Block tile 64(m) x 64(l), K=512 in chunks of 64. 8 warps: 4(m) x 2(l).
// Per warp: m16, l32 (4 n8-tiles), two GEMMs (adj, A2) sharing B frags.
#define PH 72   // smem pitch in halves (144 B -> conflict-free LDSM)
__global__ void __launch_bounds__(256) k_diff(
    const __half* __restrict__ H, const __half* __restrict__ adjh,
    const __half* __restrict__ A2h,
    __half* __restrict__ X1, __half* __restrict__ X2) {
  __shared__ __align__(16) __half Hs[64 * PH];
  __shared__ __align__(16) __half A1s[64 * PH];
  __shared__ __align__(16) __half A2s[64 * PH];
  int t = threadIdx.x, lane = t & 31, wid = t >> 5;
  int m0 = blockIdx.x * 64;
  int bc = blockIdx.y;
  int hbase = bc * (Nn * Lt);

  int wm = (wid & 3) * 16;    // warp m-offset
  int wl = (wid >> 2) * 32;   // warp l-offset
  int grp = lane >> 2, qid = lane & 3;

  float acc1[4][4] = {}, acc2[4][4] = {};

  // global->smem: 2 x uint4 (8 halves) per tile per thread
  int lr = t >> 3;            // 0..31 (and +32)
  int lc8 = (t & 7) * 8;

  // ldmatrix per-thread addresses (within chunk)
  int tt = lane & 7, sel = lane >> 3;
  int a_r = (sel >> 1) * 8 + tt;      // A: k-row
  int a_c = wm + (sel & 1) * 8;       // A: m-col
  int b_r = (sel & 1) * 8 + tt;       // B: k-row
  int b_c = wl + (sel >> 1) * 8;      // B: l-col (covers 2 n8 tiles)

  uint32_t Hu  = (uint32_t)__cvta_generic_to_shared(Hs);
  uint32_t A1u = (uint32_t)__cvta_generic_to_shared(A1s);
  uint32_t A2u = (uint32_t)__cvta_generic_to_shared(A2s);

  for (int k0 = 0; k0 < Nn; k0 += 64) {
    #pragma unroll
    for (int q = 0; q < 2; q++) {
      int r = lr + q * 32;
      *(uint4*)&Hs[r * PH + lc8]  = *(const uint4*)&H[hbase + (k0 + r) * Lt + lc8];
      *(uint4*)&A1s[r * PH + lc8] = *(const uint4*)&adjh[(k0 + r) * Nn + m0 + lc8];
      *(uint4*)&A2s[r * PH + lc8] = *(const uint4*)&A2h[(k0 + r) * Nn + m0 + lc8];
    }
    __syncthreads();

    #pragma unroll
    for (int ks = 0; ks < 64; ks += 16) {
      uint32_t a1[4], a2[4], bA[4], bB[4];
      ldsm4t(a1, A1u + ((ks + a_r) * PH + a_c) * 2);
      ldsm4t(a2, A2u + ((ks + a_r) * PH + a_c) * 2);
      ldsm4t(bA, Hu + ((ks + b_r) * PH + b_c) * 2);        // n-tiles 0,1
      ldsm4t(bB, Hu + ((ks + b_r) * PH + b_c + 16) * 2);   // n-tiles 2,3
      mma16816(acc1[0], a1, bA[0], bA[1]);
      mma16816(acc1[1], a1, bA[2], bA[3]);
      mma16816(acc1[2], a1, bB[0], bB[1]);
      mma16816(acc1[3], a1, bB[2], bB[3]);
      mma16816(acc2[0], a2, bA[0], bA[1]);
      mma16816(acc2[1], a2, bA[2], bA[3]);
      mma16816(acc2[2], a2, bB[0], bB[1]);
      mma16816(acc2[3], a2, bB[2], bB[3]);
    }
    __syncthreads();
  }

  // Store: c0,c1 at (row=grp, col=2*qid); c2,c3 at row grp+8.
  int row0 = m0 + wm + grp;
  #pragma unroll
  for (int nt = 0; nt < 4; nt++) {
    int col = wl + nt * 8 + 2 * qid;
    *(__half2*)&X1[hbase + row0 * Lt + col]       = __floats2half2_rn(acc1[nt][0], acc1[nt][1]);
    *(__half2*)&X1[hbase + (row0 + 8) * Lt + col] = __floats2half2_rn(acc1[nt][2], acc1[nt][3]);
    *(__half2*)&X2[hbase + row0 * Lt + col]       = __floats2half2_rn(acc2[nt][0], acc2[nt][1]);
    *(__half2*)&X2[hbase + (row0 + 8) * Lt + col] = __floats2half2_rn(acc2[nt][2], acc2[nt][3]);
  }
}

// ---------------- FUSED: gcmix(layer i) + TCN(layer i+1) ----------------
__global__ void k_fuse(const __half* __restrict__ Ht, const __half* __restrict__ X1,
                       const __half* __restrict__ X2, const __half* __restrict__ Res,
                       __half* __restrict__ h1_out,
                       const float* __restrict__ Wgc, const float* __restrict__ bgc,
                       const float* __restrict__ gg, const float* __restrict__ gb,
                       const float* __restrict__ bng, const float* __restrict__ bnb,
                       const float* __restrict__ Wf, const float* __restrict__ bfv,
                       const float* __restrict__ Wg, const float* __restrict__ bgv,
                       const float* __restrict__ Wsk, const float* __restrict__ bskv,
                       __half* __restrict__ t_out, float* __restrict__ skipbuf,
                       float* __restrict__ outp,
                       const float* __restrict__ obng, const float* __restrict__ obnb,
                       int LoutG, int mode) {
  __shared__ float pool[9600];
  float (*hs)[68]  = (float(*)[68])(pool);
  float (*x1s)[68] = (float(*)[68])(pool + 2176);
  float (*x2s)[68] = (float(*)[68])(pool + 4352);
  float* wgs = pool + 6528;
  float* wfs = pool;
  float (*h2)[68]  = (float(*)[68])(pool + 2176);
  float (*hns)[68] = (float(*)[68])(pool + 4352);
  float* wgs2 = pool + 6528;
  float* wsks = pool + 6528 + 2048;

  int t = threadIdx.x;
  int n = blockIdx.x, b = blockIdx.y;
  int base = ((b * 32) * Nn + n) * Lt;

  // ---- phase 1 ----
  #pragma unroll
  for (int q = 0; q < 2; q++) {
    int idx = t + q * 256;
    int c = idx >> 4, l4 = (idx & 15) * 4;
    int gptr = base + c * (Nn * Lt) + l4;
    float2 ha = __half22float2(*(const __half2*)&Ht[gptr]);
    float2 hb = __half22float2(*(const __half2*)&Ht[gptr + 2]);
    float2 pa = __half22float2(*(const __half2*)&X1[gptr]);
    float2 pb = __half22float2(*(const __half2*)&X1[gptr + 2]);
    float2 qa = __half22float2(*(const __half2*)&X2[gptr]);
    float2 qb = __half22float2(*(const __half2*)&X2[gptr + 2]);
    hs[c][l4] = ha.x; hs[c][l4+1] = ha.y; hs[c][l4+2] = hb.x; hs[c][l4+3] = hb.y;
    x1s[c][l4] = pa.x; x1s[c][l4+1] = pa.y; x1s[c][l4+2] = pb.x; x1s[c][l4+3] = pb.y;
    x2s[c][l4] = qa.x; x2s[c][l4+1] = qa.y; x2s[c][l4+2] = qb.x; x2s[c][l4+3] = qb.y;
  }
  #pragma unroll
  for (int q = 0; q < 3; q++) {
    int idx = t + q * 256;
    *(float4*)&wgs[idx * 4] = *(const float4*)&Wgc[idx * 4];
  }
  __syncthreads();

  // ---- phase 2: gcmix ----
  int op = t >> 4;
  int o0 = op * 2;
  int lq = (t & 15) * 4;
  float acc[2][4] = {};
  for (int c = 0; c < 32; c++) {
    float4 h = *(float4*)&hs[c][lq];
    float4 p = *(float4*)&x1s[c][lq];
    float4 q = *(float4*)&x2s[c][lq];
    #pragma unroll
    for (int r = 0; r < 2; r++) {
      int o = o0 + r;
      float wh = wgs[o * 96 + c], w1 = wgs[o * 96 + 32 + c], w2 = wgs[o * 96 + 64 + c];
      acc[r][0] += wh * h.x + w1 * p.x + w2 * q.x;
      acc[r][1] += wh * h.y + w1 * p.y + w2 * q.y;
      acc[r][2] += wh * h.z + w1 * p.z + w2 * q.z;
      acc[r][3] += wh * h.w + w1 * p.w + w2 * q.w;
    }
  }
  const float inv0 = rsqrtf(1.0f + 1e-5f);
  float hv[2][4];
  #pragma unroll
  for (int r = 0; r < 2; r++) {
    int o = o0 + r;
    float gi = gg[o] * inv0, gbb = gb[o];
    float bi = bng[o] * inv0, bbb = bnb[o];
    float bo = bgc[o];
    int ob = base + o * (Nn * Lt);
    #pragma unroll
    for (int j = 0; j < 4; j++) {
      float v = (acc[r][j] + bo) * gi + gbb;
      v += __half2float(Res[ob + lq + j + 1]);
      hv[r][j] = v * bi + bbb;
    }
  }
  __syncthreads();

  #pragma unroll
  for (int r = 0; r < 2; r++) {
    int o = o0 + r;
    *(float4*)&h2[o][lq] = *(float4*)&hv[r][0];
    if (h1_out) {
      int ob = base + o * (Nn * Lt);
      #pragma unroll
      for (int j = 0; j < 4; j++)
        if (lq + j < LoutG) h1_out[ob + lq + j] = __float2half_rn(hv[r][j]);
    }
  }
  #pragma unroll
  for (int q = 0; q < 2; q++) {
    int idx = t + q * 256;
    *(float4*)&wfs[idx * 4]  = *(const float4*)&Wf[idx * 4];
    *(float4*)&wgs2[idx * 4] = *(const float4*)&Wg[idx * 4];
  }
  ((float4*)wsks)[t] = ((const float4*)Wsk)[t];
  __syncthreads();

  // ---- phase 3: gated TCN ----
  int o = t >> 3, sub = t & 7;
  int Lin = LoutG;
  int Lout = Lin - 1;
  int l0 = sub * 8;
  float f[8], g[8];
  float bfo = bfv[o], bgo = bgv[o];
  #pragma unroll
  for (int j = 0; j < 8; j++) { f[j] = bfo; g[j] = bgo; }

  for (int c = 0; c < 32; c++) {
    float wf0 = wfs[(o * 32 + c) * 2], wf1 = wfs[(o * 32 + c) * 2 + 1];
    float wg0 = wgs2[(o * 32 + c) * 2], wg1 = wgs2[(o * 32 + c) * 2 + 1];
    float hp = h2[c][l0];
    #pragma unroll
    for (int j = 0; j < 8; j++) {
      float hc = h2[c][l0 + j + 1];
      f[j] += hp * wf0 + hc * wf1;
      g[j] += hp * wg0 + hc * wg1;
      hp = hc;
    }
  }

  int obase = base + o * (Nn * Lt);
  #pragma unroll
  for (int j = 0; j < 8; j++) {
    int l = l0 + j;
    float hvv = ftanh(f[j]) * fsig(g[j]);
    hns[o][l] = hvv;
    if (mode != 2 && l < Lout) t_out[obase + l] = __float2half_rn(hvv);
  }
  __syncthreads();

  float s[8];
  float bs = bskv[o];
  #pragma unroll
  for (int j = 0; j < 8; j++) s[j] = bs;
  for (int c = 0; c < 32; c++) {
    float w = wsks[o * 32 + c];
    #pragma unroll
    for (int j = 0; j < 8; j++) s[j] += w * hns[c][l0 + j];
  }

  if (mode == 1) {
    #pragma unroll
    for (int j = 0; j < 8; j++) {
      int l = l0 + j;
      if (l >= 1 && l < Lout) skipbuf[obase + l - 1] += s[j];
    }
  } else {
    float inv = obng[o] * inv0;
    float bb = obnb[o];
    #pragma unroll
    for (int j = 0; j < 8; j++) {
      int l = l0 + j;
      if (l < 61)
        outp[((b * 61 + l) * Nn + n) * 32 + o] = (skipbuf[obase + l] + s[j]) * inv + bb;
    }
  }
}

extern "C" void kernel_launch(void* const* d_in, const int* in_sizes, int n_in,
                              void* d_out, int out_size) {
  const float* x      = (const float*)d_in[0];
  const float* adj    = (const float*)d_in[1];
  const float* Wstart = (const float*)d_in[2];
  const float* bstart = (const float*)d_in[3];
  const float* Wf     = (const float*)d_in[4];
  const float* bf     = (const float*)d_in[5];
  const float* Wg     = (const float*)d_in[6];
  const float* bg     = (const float*)d_in[7];
  const float* Wsk    = (const float*)d_in[8];
  const float* bsk    = (const float*)d_in[9];
  const float* Wgc    = (const float*)d_in[10];
  const float* bgc    = (const float*)d_in[11];
  const float* gcg    = (const float*)d_in[12];
  const float* gcb    = (const float*)d_in[13];
  const float* bng    = (const float*)d_in[14];
  const float* bnb    = (const float*)d_in[15];
  const float* obng   = (const float*)d_in[16];
  const float* obnb   = (const float*)d_in[17];
  float* out = (float*)d_out;

  __half *A, *Bu, *Cu, *Du, *Eu, *AJH, *A2H;
  float *SK;
  cudaGetSymbolAddress((void**)&A,   g_A);
  cudaGetSymbolAddress((void**)&Bu,  g_B);
  cudaGetSymbolAddress((void**)&Cu,  g_C);
  cudaGetSymbolAddress((void**)&Du,  g_D);
  cudaGetSymbolAddress((void**)&Eu,  g_E);
  cudaGetSymbolAddress((void**)&SK,  g_SK);
  cudaGetSymbolAddress((void**)&AJH, g_adjh);
  cudaGetSymbolAddress((void**)&A2H, g_A2h);

  dim3 bn_grid(Nn, Bn);
  dim3 diff_grid(8, Bn * Cch);

  k_start<<<BUF / 4 / 256, 256>>>(x, Wstart, bstart, A);
  k_adjh<<<Nn * Nn / 4 / 256, 256>>>(adj, AJH);
  k_a2<<<dim3(16, 16), dim3(32, 8)>>>(adj, A2H);

  // layer 0 TCN (Lin=64)
  k_tcn<<<bn_grid, 256>>>(A, Bu, SK, Wf, bf, Wg, bg, Wsk, bsk, 64);
  k_diff<<<diff_grid, 256>>>(Bu, AJH, A2H, Cu, Du);

  // gcmix(layer0) + TCN(layer1): LoutG=63, mode 1; spills h1 -> Eu
  k_fuse<<<bn_grid, 256>>>(Bu, Cu, Du, A, Eu,
                           Wgc, bgc, gcg, gcb, bng, bnb,
                           Wf + 2048, bf + 32, Wg + 2048, bg + 32,
                           Wsk + 1024, bsk + 32,
                           Bu, SK, nullptr, nullptr, nullptr, 63, 1);
  k_diff<<<diff_grid, 256>>>(Bu, AJH, A2H, Cu, Du);

  // gcmix(layer1) + TCN(layer2, final): LoutG=62, mode 2
  k_fuse<<<bn_grid, 256>>>(Bu, Cu, Du, Eu, nullptr,
                           Wgc + 3072, bgc + 32, gcg + 32, gcb + 32,
                           bng + 32, bnb + 32,
                           Wf + 4096, bf + 64, Wg + 4096, bg + 64,
                           Wsk + 2048, bsk + 64,
                           nullptr, SK, out, obng, obnb, 62, 2);
}

// round 11
// speedup vs baseline: 3.6520x; 1.4296x over previous
#include <cuda_runtime.h>
#include <cuda_fp16.h>
#include <math.h>
#include <stdint.h>

#define Bn 8
#define Cch 32
#define Nn 512
#define Lt 64
#define NL (Nn*Lt)
#define BUF (Bn*Cch*Nn*Lt)

__device__ __half g_A[BUF];      // h (start output / residual 0)
__device__ __half g_B[BUF];      // H (TCN output)
__device__ __half g_C[BUF];      // X1
__device__ __half g_D[BUF];      // X2
__device__ __half g_E[BUF];      // h1 (residual 1)
__device__ float  g_SK[BUF];     // skip accumulator
__device__ __half g_adjh[Nn*Nn];
__device__ __half g_A2h[Nn*Nn];

__device__ __forceinline__ float fsig(float x) {
  return __fdividef(1.0f, 1.0f + __expf(-x));
}
__device__ __forceinline__ float ftanh(float x) {
  float e = __expf(-2.0f * x);
  return __fdividef(1.0f - e, 1.0f + e);
}
__device__ __forceinline__ void ldsm4t(uint32_t* r, uint32_t addr) {
  asm volatile("ldmatrix.sync.aligned.m8n8.x4.trans.shared.b16 {%0,%1,%2,%3}, [%4];"
    : "=r"(r[0]), "=r"(r[1]), "=r"(r[2]), "=r"(r[3]) : "r"(addr));
}
__device__ __forceinline__ void mma16816(float* c, const uint32_t* a, uint32_t b0, uint32_t b1) {
  asm volatile("mma.sync.aligned.m16n8k16.row.col.f32.f16.f16.f32 "
    "{%0,%1,%2,%3}, {%4,%5,%6,%7}, {%8,%9}, {%0,%1,%2,%3};"
    : "+f"(c[0]), "+f"(c[1]), "+f"(c[2]), "+f"(c[3])
    : "r"(a[0]), "r"(a[1]), "r"(a[2]), "r"(a[3]), "r"(b0), "r"(b1));
}

// ---------------- start conv ----------------
__global__ void k_start(const float* __restrict__ x, const float* __restrict__ W,
                        const float* __restrict__ bias, __half* __restrict__ h) {
  int idx4 = blockIdx.x * 256 + threadIdx.x;
  int l4 = (idx4 & 15) * 4;
  int n  = (idx4 >> 4) & 511;
  int c  = (idx4 >> 13) & 31;
  int b  = idx4 >> 18;
  int xb = ((b * 2) * Nn + n) * Lt + l4;
  float4 x0 = *(const float4*)&x[xb];
  float4 x1 = *(const float4*)&x[xb + NL];
  float w0 = W[c * 2], w1 = W[c * 2 + 1], bs = bias[c];
  int ob = (((b * 32 + c) * Nn + n) * Lt) + l4;
  *(__half2*)&h[ob]     = __floats2half2_rn(x0.x * w0 + x1.x * w1 + bs,
                                            x0.y * w0 + x1.y * w1 + bs);
  *(__half2*)&h[ob + 2] = __floats2half2_rn(x0.z * w0 + x1.z * w1 + bs,
                                            x0.w * w0 + x1.w * w1 + bs);
}

// ---------------- adj -> fp16 ----------------
__global__ void k_adjh(const float* __restrict__ adj, __half* __restrict__ adjh) {
  int i4 = blockIdx.x * 256 + threadIdx.x;
  float4 v = *(const float4*)&adj[i4 * 4];
  *(__half2*)&adjh[i4 * 4]     = __floats2half2_rn(v.x, v.y);
  *(__half2*)&adjh[i4 * 4 + 2] = __floats2half2_rn(v.z, v.w);
}

// ---------------- A2 = adj @ adj (fp32 compute, fp16 out) ----------------
__global__ void k_a2(const float* __restrict__ adj, __half* __restrict__ A2h) {
  __shared__ float As[32][33], Bs[32][33];
  int tx = threadIdx.x, ty = threadIdx.y;
  int p0 = blockIdx.y * 32, m0 = blockIdx.x * 32;
  float acc[4] = {0.f, 0.f, 0.f, 0.f};
  for (int k0 = 0; k0 < Nn; k0 += 32) {
    #pragma unroll
    for (int r = 0; r < 4; r++) {
      As[ty + 8 * r][tx] = adj[(p0 + ty + 8 * r) * Nn + k0 + tx];
      Bs[ty + 8 * r][tx] = adj[(k0 + ty + 8 * r) * Nn + m0 + tx];
    }
    __syncthreads();
    #pragma unroll
    for (int k = 0; k < 32; k++) {
      float bv = Bs[k][tx];
      #pragma unroll
      for (int r = 0; r < 4; r++) acc[r] += As[ty + 8 * r][k] * bv;
    }
    __syncthreads();
  }
  #pragma unroll
  for (int r = 0; r < 4; r++)
    A2h[(p0 + ty + 8 * r) * Nn + m0 + tx] = __float2half_rn(acc[r]);
}

// ---------------- standalone gated TCN (layer 0, skip init) ----------------
// Thread map: lane = o (32 outs), warp = sub (8 l-octets). All h loads broadcast,
// all weight loads conflict-free via transposed pitch-33 staging.
__global__ void k_tcn(const __half* __restrict__ h_in, __half* __restrict__ t_out,
                      float* __restrict__ skipbuf,
                      const float* __restrict__ Wf, const float* __restrict__ bfv,
                      const float* __restrict__ Wg, const float* __restrict__ bgv,
                      const float* __restrict__ Wsk, const float* __restrict__ bskv,
                      int Lin) {
  __shared__ float hs[32][73];
  __shared__ float hns[32][73];
  __shared__ float wf0s[32*33], wf1s[32*33], wg0s[32*33], wg1s[32*33], wsts[32*33];
  int t = threadIdx.x;
  int n = blockIdx.x, b = blockIdx.y;
  int base = ((b * 32) * Nn + n) * Lt;

  for (int idx = t; idx < 1024; idx += 256) {
    int c = idx >> 5, l2 = (idx & 31) * 2;
    float2 v = __half22float2(*(const __half2*)&h_in[base + c * NL + l2]);
    hs[c][l2] = v.x; hs[c][l2 + 1] = v.y;
  }
  for (int idx = t; idx < 1024; idx += 256) {
    int o = idx >> 5, c = idx & 31;
    float2 wf = *(const float2*)&Wf[(o * 32 + c) * 2];
    float2 wg = *(const float2*)&Wg[(o * 32 + c) * 2];
    wf0s[c * 33 + o] = wf.x; wf1s[c * 33 + o] = wf.y;
    wg0s[c * 33 + o] = wg.x; wg1s[c * 33 + o] = wg.y;
    wsts[c * 33 + o] = Wsk[o * 32 + c];
  }
  __syncthreads();

  int o = t & 31, sub = t >> 5;
  int Lout = Lin - 1;
  int l0 = sub * 8;
  float f[8], g[8];
  float bfo = bfv[o], bgo = bgv[o];
  #pragma unroll
  for (int j = 0; j < 8; j++) { f[j] = bfo; g[j] = bgo; }

  for (int c = 0; c < 32; c++) {
    float wf0 = wf0s[c * 33 + o], wf1 = wf1s[c * 33 + o];
    float wg0 = wg0s[c * 33 + o], wg1 = wg1s[c * 33 + o];
    float hp = hs[c][l0];
    #pragma unroll
    for (int j = 0; j < 8; j++) {
      float hc = hs[c][l0 + j + 1];
      f[j] += hp * wf0 + hc * wf1;
      g[j] += hp * wg0 + hc * wg1;
      hp = hc;
    }
  }

  #pragma unroll
  for (int j = 0; j < 8; j++)
    hns[o][l0 + j] = ftanh(f[j]) * fsig(g[j]);
  __syncthreads();

  float s[8];
  float bs = bskv[o];
  #pragma unroll
  for (int j = 0; j < 8; j++) s[j] = bs;
  for (int c = 0; c < 32; c++) {
    float w = wsts[c * 33 + o];
    #pragma unroll
    for (int j = 0; j < 8; j++) s[j] += w * hns[c][l0 + j];
  }
  // stage skip into hs (free now)
  #pragma unroll
  for (int j = 0; j < 8; j++) hs[o][l0 + j] = s[j];
  __syncthreads();

  // coalesced outputs
  for (int idx = t; idx < 2048; idx += 256) {
    int c = idx >> 6, l = idx & 63;
    if (l < Lout) {
      t_out[base + c * NL + l] = __float2half_rn(hns[c][l]);
      if (l >= 2) skipbuf[base + c * NL + l - 2] = hs[c][l];
    }
  }
}

// ---------------- fused diffusion: fp16 HMMA + ldmatrix (unchanged) ----------------
#define PH 72
__global__ void __launch_bounds__(256) k_diff(
    const __half* __restrict__ H, const __half* __restrict__ adjh,
    const __half* __restrict__ A2h,
    __half* __restrict__ X1, __half* __restrict__ X2) {
  __shared__ __align__(16) __half Hs[64 * PH];
  __shared__ __align__(16) __half A1s[64 * PH];
  __shared__ __align__(16) __half A2s[64 * PH];
  int t = threadIdx.x, lane = t & 31, wid = t >> 5;
  int m0 = blockIdx.x * 64;
  int bc = blockIdx.y;
  int hbase = bc * NL;

  int wm = (wid & 3) * 16;
  int wl = (wid >> 2) * 32;
  int grp = lane >> 2, qid = lane & 3;

  float acc1[4][4] = {}, acc2[4][4] = {};

  int lr = t >> 3;
  int lc8 = (t & 7) * 8;

  int tt = lane & 7, sel = lane >> 3;
  int a_r = (sel >> 1) * 8 + tt;
  int a_c = wm + (sel & 1) * 8;
  int b_r = (sel & 1) * 8 + tt;
  int b_c = wl + (sel >> 1) * 8;

  uint32_t Hu  = (uint32_t)__cvta_generic_to_shared(Hs);
  uint32_t A1u = (uint32_t)__cvta_generic_to_shared(A1s);
  uint32_t A2u = (uint32_t)__cvta_generic_to_shared(A2s);

  for (int k0 = 0; k0 < Nn; k0 += 64) {
    #pragma unroll
    for (int q = 0; q < 2; q++) {
      int r = lr + q * 32;
      *(uint4*)&Hs[r * PH + lc8]  = *(const uint4*)&H[hbase + (k0 + r) * Lt + lc8];
      *(uint4*)&A1s[r * PH + lc8] = *(const uint4*)&adjh[(k0 + r) * Nn + m0 + lc8];
      *(uint4*)&A2s[r * PH + lc8] = *(const uint4*)&A2h[(k0 + r) * Nn + m0 + lc8];
    }
    __syncthreads();

    #pragma unroll
    for (int ks = 0; ks < 64; ks += 16) {
      uint32_t a1[4], a2[4], bA[4], bB[4];
      ldsm4t(a1, A1u + ((ks + a_r) * PH + a_c) * 2);
      ldsm4t(a2, A2u + ((ks + a_r) * PH + a_c) * 2);
      ldsm4t(bA, Hu + ((ks + b_r) * PH + b_c) * 2);
      ldsm4t(bB, Hu + ((ks + b_r) * PH + b_c + 16) * 2);
      mma16816(acc1[0], a1, bA[0], bA[1]);
      mma16816(acc1[1], a1, bA[2], bA[3]);
      mma16816(acc1[2], a1, bB[0], bB[1]);
      mma16816(acc1[3], a1, bB[2], bB[3]);
      mma16816(acc2[0], a2, bA[0], bA[1]);
      mma16816(acc2[1], a2, bA[2], bA[3]);
      mma16816(acc2[2], a2, bB[0], bB[1]);
      mma16816(acc2[3], a2, bB[2], bB[3]);
    }
    __syncthreads();
  }

  int row0 = m0 + wm + grp;
  #pragma unroll
  for (int nt = 0; nt < 4; nt++) {
    int col = wl + nt * 8 + 2 * qid;
    *(__half2*)&X1[hbase + row0 * Lt + col]       = __floats2half2_rn(acc1[nt][0], acc1[nt][1]);
    *(__half2*)&X1[hbase + (row0 + 8) * Lt + col] = __floats2half2_rn(acc1[nt][2], acc1[nt][3]);
    *(__half2*)&X2[hbase + row0 * Lt + col]       = __floats2half2_rn(acc2[nt][0], acc2[nt][1]);
    *(__half2*)&X2[hbase + (row0 + 8) * Lt + col] = __floats2half2_rn(acc2[nt][2], acc2[nt][3]);
  }
}

// ---------------- FUSED: gcmix(layer i) + TCN(layer i+1) ----------------
// Phase-3 pool layout (floats):
//   h2   [0, 2432)      32 x 76
//   hns  [2432, 4768)   32 x 73
//   wf0s [4768,5824) wf1s[5824,6880) wg0s[6880,7936) wg1s[7936,8992) wsts[8992,10048)
// Phase-1/2 layout: hs 0..2176, x1s 2176..4352, x2s 4352..6528, wgs 6528..9600
__global__ void k_fuse(const __half* __restrict__ Ht, const __half* __restrict__ X1,
                       const __half* __restrict__ X2, const __half* __restrict__ Res,
                       __half* __restrict__ h1_out,
                       const float* __restrict__ Wgc, const float* __restrict__ bgc,
                       const float* __restrict__ gg, const float* __restrict__ gb,
                       const float* __restrict__ bng, const float* __restrict__ bnb,
                       const float* __restrict__ Wf, const float* __restrict__ bfv,
                       const float* __restrict__ Wg, const float* __restrict__ bgv,
                       const float* __restrict__ Wsk, const float* __restrict__ bskv,
                       __half* __restrict__ t_out, float* __restrict__ skipbuf,
                       float* __restrict__ outp,
                       const float* __restrict__ obng, const float* __restrict__ obnb,
                       int LoutG, int mode) {
  __shared__ float pool[10048];
  float (*hs)[68]  = (float(*)[68])(pool);
  float (*x1s)[68] = (float(*)[68])(pool + 2176);
  float (*x2s)[68] = (float(*)[68])(pool + 4352);
  float* wgs = pool + 6528;
  float (*h2)[76]  = (float(*)[76])(pool);
  float (*hns)[73] = (float(*)[73])(pool + 2432);
  float* wf0s = pool + 4768;
  float* wf1s = pool + 5824;
  float* wg0s = pool + 6880;
  float* wg1s = pool + 7936;
  float* wsts = pool + 8992;

  int t = threadIdx.x;
  int n = blockIdx.x, b = blockIdx.y;
  int base = ((b * 32) * Nn + n) * Lt;

  // ---- phase 1: load gcmix inputs ----
  #pragma unroll
  for (int q = 0; q < 2; q++) {
    int idx = t + q * 256;
    int c = idx >> 4, l4 = (idx & 15) * 4;
    int gptr = base + c * NL + l4;
    float2 ha = __half22float2(*(const __half2*)&Ht[gptr]);
    float2 hb = __half22float2(*(const __half2*)&Ht[gptr + 2]);
    float2 pa = __half22float2(*(const __half2*)&X1[gptr]);
    float2 pb = __half22float2(*(const __half2*)&X1[gptr + 2]);
    float2 qa = __half22float2(*(const __half2*)&X2[gptr]);
    float2 qb = __half22float2(*(const __half2*)&X2[gptr + 2]);
    hs[c][l4] = ha.x; hs[c][l4+1] = ha.y; hs[c][l4+2] = hb.x; hs[c][l4+3] = hb.y;
    x1s[c][l4] = pa.x; x1s[c][l4+1] = pa.y; x1s[c][l4+2] = pb.x; x1s[c][l4+3] = pb.y;
    x2s[c][l4] = qa.x; x2s[c][l4+1] = qa.y; x2s[c][l4+2] = qb.x; x2s[c][l4+3] = qb.y;
  }
  #pragma unroll
  for (int q = 0; q < 3; q++) {
    int idx = t + q * 256;
    *(float4*)&wgs[idx * 4] = *(const float4*)&Wgc[idx * 4];
  }
  __syncthreads();

  // ---- phase 2: gcmix (2 o x 4 l per thread) ----
  int op = t >> 4;
  int o0 = op * 2;
  int lq = (t & 15) * 4;
  float acc[2][4] = {};
  for (int c = 0; c < 32; c++) {
    float4 h = *(float4*)&hs[c][lq];
    float4 p = *(float4*)&x1s[c][lq];
    float4 q = *(float4*)&x2s[c][lq];
    #pragma unroll
    for (int r = 0; r < 2; r++) {
      int o = o0 + r;
      float wh = wgs[o * 96 + c], w1 = wgs[o * 96 + 32 + c], w2 = wgs[o * 96 + 64 + c];
      acc[r][0] += wh * h.x + w1 * p.x + w2 * q.x;
      acc[r][1] += wh * h.y + w1 * p.y + w2 * q.y;
      acc[r][2] += wh * h.z + w1 * p.z + w2 * q.z;
      acc[r][3] += wh * h.w + w1 * p.w + w2 * q.w;
    }
  }
  const float inv0 = rsqrtf(1.0f + 1e-5f);
  float hv[2][4];
  #pragma unroll
  for (int r = 0; r < 2; r++) {
    int o = o0 + r;
    float gi = gg[o] * inv0, gbb = gb[o];
    float bi = bng[o] * inv0, bbb = bnb[o];
    float bo = bgc[o];
    int ob = base + o * NL;
    #pragma unroll
    for (int j = 0; j < 4; j++) {
      float v = (acc[r][j] + bo) * gi + gbb;
      v += __half2float(Res[ob + lq + j + 1]);
      hv[r][j] = v * bi + bbb;
    }
  }
  __syncthreads();   // phase-1/2 reads done; overlay

  #pragma unroll
  for (int r = 0; r < 2; r++) {
    int o = o0 + r;
    *(float4*)&h2[o][lq] = *(float4*)&hv[r][0];
    if (h1_out) {
      int ob = base + o * NL;
      #pragma unroll
      for (int j = 0; j < 4; j++)
        if (lq + j < LoutG) h1_out[ob + lq + j] = __float2half_rn(hv[r][j]);
    }
  }
  for (int idx = t; idx < 1024; idx += 256) {
    int o = idx >> 5, c = idx & 31;
    float2 wf = *(const float2*)&Wf[(o * 32 + c) * 2];
    float2 wg = *(const float2*)&Wg[(o * 32 + c) * 2];
    wf0s[c * 33 + o] = wf.x; wf1s[c * 33 + o] = wf.y;
    wg0s[c * 33 + o] = wg.x; wg1s[c * 33 + o] = wg.y;
    wsts[c * 33 + o] = Wsk[o * 32 + c];
  }
  __syncthreads();

  // ---- phase 3: gated TCN on h2, lane = o, warp = l-octet ----
  int o = t & 31, sub = t >> 5;
  int Lout = LoutG - 1;
  int l0 = sub * 8;
  float f[8], g[8];
  float bfo = bfv[o], bgo = bgv[o];
  #pragma unroll
  for (int j = 0; j < 8; j++) { f[j] = bfo; g[j] = bgo; }

  for (int c = 0; c < 32; c++) {
    float wf0 = wf0s[c * 33 + o], wf1 = wf1s[c * 33 + o];
    float wg0 = wg0s[c * 33 + o], wg1 = wg1s[c * 33 + o];
    float hp = h2[c][l0];
    #pragma unroll
    for (int j = 0; j < 8; j++) {
      float hc = h2[c][l0 + j + 1];
      f[j] += hp * wf0 + hc * wf1;
      g[j] += hp * wg0 + hc * wg1;
      hp = hc;
    }
  }

  #pragma unroll
  for (int j = 0; j < 8; j++)
    hns[o][l0 + j] = ftanh(f[j]) * fsig(g[j]);
  __syncthreads();

  float s[8];
  float bs = bskv[o];
  #pragma unroll
  for (int j = 0; j < 8; j++) s[j] = bs;
  for (int c = 0; c < 32; c++) {
    float w = wsts[c * 33 + o];
    #pragma unroll
    for (int j = 0; j < 8; j++) s[j] += w * hns[c][l0 + j];
  }
  __syncthreads();   // h2 reads (main loop) done everywhere; reuse for s staging
  #pragma unroll
  for (int j = 0; j < 8; j++) h2[o][l0 + j] = s[j];
  __syncthreads();

  if (mode == 1) {
    for (int idx = t; idx < 2048; idx += 256) {
      int c = idx >> 6, l = idx & 63;
      if (l < Lout) {
        t_out[base + c * NL + l] = __float2half_rn(hns[c][l]);
        if (l >= 1) skipbuf[base + c * NL + l - 1] += h2[c][l];
      }
    }
  } else {
    // phase A: add skip (coalesced in l) + final BN, store into hns
    for (int idx = t; idx < 2048; idx += 256) {
      int c = idx >> 6, l = idx & 63;
      if (l < 61) {
        float inv = obng[c] * inv0;
        hns[c][l] = (skipbuf[base + c * NL + l] + h2[c][l]) * inv + obnb[c];
      }
    }
    __syncthreads();
    // phase B: transposed write, o contiguous -> 128B coalesced
    for (int idx = t; idx < 2048; idx += 256) {
      int l = idx >> 5, oo = idx & 31;
      if (l < 61)
        outp[((b * 61 + l) * Nn + n) * 32 + oo] = hns[oo][l];
    }
  }
}

extern "C" void kernel_launch(void* const* d_in, const int* in_sizes, int n_in,
                              void* d_out, int out_size) {
  const float* x      = (const float*)d_in[0];
  const float* adj    = (const float*)d_in[1];
  const float* Wstart = (const float*)d_in[2];
  const float* bstart = (const float*)d_in[3];
  const float* Wf     = (const float*)d_in[4];
  const float* bf     = (const float*)d_in[5];
  const float* Wg     = (const float*)d_in[6];
  const float* bg     = (const float*)d_in[7];
  const float* Wsk    = (const float*)d_in[8];
  const float* bsk    = (const float*)d_in[9];
  const float* Wgc    = (const float*)d_in[10];
  const float* bgc    = (const float*)d_in[11];
  const float* gcg    = (const float*)d_in[12];
  const float* gcb    = (const float*)d_in[13];
  const float* bng    = (const float*)d_in[14];
  const float* bnb    = (const float*)d_in[15];
  const float* obng   = (const float*)d_in[16];
  const float* obnb   = (const float*)d_in[17];
  float* out = (float*)d_out;

  __half *A, *Bu, *Cu, *Du, *Eu, *AJH, *A2H;
  float *SK;
  cudaGetSymbolAddress((void**)&A,   g_A);
  cudaGetSymbolAddress((void**)&Bu,  g_B);
  cudaGetSymbolAddress((void**)&Cu,  g_C);
  cudaGetSymbolAddress((void**)&Du,  g_D);
  cudaGetSymbolAddress((void**)&Eu,  g_E);
  cudaGetSymbolAddress((void**)&SK,  g_SK);
  cudaGetSymbolAddress((void**)&AJH, g_adjh);
  cudaGetSymbolAddress((void**)&A2H, g_A2h);

  dim3 bn_grid(Nn, Bn);
  dim3 diff_grid(8, Bn * Cch);

  k_start<<<BUF / 4 / 256, 256>>>(x, Wstart, bstart, A);
  k_adjh<<<Nn * Nn / 4 / 256, 256>>>(adj, AJH);
  k_a2<<<dim3(16, 16), dim3(32, 8)>>>(adj, A2H);

  // layer 0 TCN (Lin=64)
  k_tcn<<<bn_grid, 256>>>(A, Bu, SK, Wf, bf, Wg, bg, Wsk, bsk, 64);
  k_diff<<<diff_grid, 256>>>(Bu, AJH, A2H, Cu, Du);

  // gcmix(layer0) + TCN(layer1): LoutG=63, mode 1; spills h1 -> Eu
  k_fuse<<<bn_grid, 256>>>(Bu, Cu, Du, A, Eu,
                           Wgc, bgc, gcg, gcb, bng, bnb,
                           Wf + 2048, bf + 32, Wg + 2048, bg + 32,
                           Wsk + 1024, bsk + 32,
                           Bu, SK, nullptr, nullptr, nullptr, 63, 1);
  k_diff<<<diff_grid, 256>>>(Bu, AJH, A2H, Cu, Du);

  // gcmix(layer1) + TCN(layer2, final): LoutG=62, mode 2
  k_fuse<<<bn_grid, 256>>>(Bu, Cu, Du, Eu, nullptr,
                           Wgc + 3072, bgc + 32, gcg + 32, gcb + 32,
                           bng + 32, bnb + 32,
                           Wf + 4096, bf + 64, Wg + 4096, bg + 64,
                           Wsk + 2048, bsk + 64,
                           nullptr, SK, out, obng, obnb, 62, 2);
}

// round 13
// speedup vs baseline: 4.2145x; 1.1540x over previous
#include <cuda_runtime.h>
#include <cuda_fp16.h>
#include <math.h>
#include <stdint.h>

#define Bn 8
#define Cch 32
#define Nn 512
#define Lt 64
#define NL (Nn*Lt)
#define BUF (Bn*Cch*Nn*Lt)
#define PH2 72   // activation/B pitch in halves (144B rows: 16B-aligned, conflict-free ldsm)
#define PW  40   // weight pitch in halves (80B rows: 16B-aligned, conflict-free ldsm)

__device__ __half g_A[BUF];      // h (start output / residual 0)
__device__ __half g_B[BUF];      // H (TCN output)
__device__ __half g_C[BUF];      // X1
__device__ __half g_D[BUF];      // X2
__device__ __half g_E[BUF];      // h1 (residual 1)
__device__ float  g_SK[BUF];     // skip accumulator
__device__ __half g_adjh[Nn*Nn];
__device__ __half g_A2h[Nn*Nn];

__device__ __forceinline__ float fsig(float x) {
  return __fdividef(1.0f, 1.0f + __expf(-x));
}
__device__ __forceinline__ float ftanh(float x) {
  float e = __expf(-2.0f * x);
  return __fdividef(1.0f - e, 1.0f + e);
}
__device__ __forceinline__ void ldsm4t(uint32_t* r, uint32_t addr) {
  asm volatile("ldmatrix.sync.aligned.m8n8.x4.trans.shared.b16 {%0,%1,%2,%3}, [%4];"
    : "=r"(r[0]), "=r"(r[1]), "=r"(r[2]), "=r"(r[3]) : "r"(addr));
}
__device__ __forceinline__ void mma16816(float* c, const uint32_t* a, uint32_t b0, uint32_t b1) {
  asm volatile("mma.sync.aligned.m16n8k16.row.col.f32.f16.f16.f32 "
    "{%0,%1,%2,%3}, {%4,%5,%6,%7}, {%8,%9}, {%0,%1,%2,%3};"
    : "+f"(c[0]), "+f"(c[1]), "+f"(c[2]), "+f"(c[3])
    : "r"(a[0]), "r"(a[1]), "r"(a[2]), "r"(a[3]), "r"(b0), "r"(b1));
}

// ---------------- start conv ----------------
__global__ void k_start(const float* __restrict__ x, const float* __restrict__ W,
                        const float* __restrict__ bias, __half* __restrict__ h) {
  int idx4 = blockIdx.x * 256 + threadIdx.x;
  int l4 = (idx4 & 15) * 4;
  int n  = (idx4 >> 4) & 511;
  int c  = (idx4 >> 13) & 31;
  int b  = idx4 >> 18;
  int xb = ((b * 2) * Nn + n) * Lt + l4;
  float4 x0 = *(const float4*)&x[xb];
  float4 x1 = *(const float4*)&x[xb + NL];
  float w0 = W[c * 2], w1 = W[c * 2 + 1], bs = bias[c];
  int ob = (((b * 32 + c) * Nn + n) * Lt) + l4;
  *(__half2*)&h[ob]     = __floats2half2_rn(x0.x * w0 + x1.x * w1 + bs,
                                            x0.y * w0 + x1.y * w1 + bs);
  *(__half2*)&h[ob + 2] = __floats2half2_rn(x0.z * w0 + x1.z * w1 + bs,
                                            x0.w * w0 + x1.w * w1 + bs);
}

// ---------------- adj -> fp16 ----------------
__global__ void k_adjh(const float* __restrict__ adj, __half* __restrict__ adjh) {
  int i4 = blockIdx.x * 256 + threadIdx.x;
  float4 v = *(const float4*)&adj[i4 * 4];
  *(__half2*)&adjh[i4 * 4]     = __floats2half2_rn(v.x, v.y);
  *(__half2*)&adjh[i4 * 4 + 2] = __floats2half2_rn(v.z, v.w);
}

// ---------------- A2 = adj @ adj (fp32 compute, fp16 out) ----------------
__global__ void k_a2(const float* __restrict__ adj, __half* __restrict__ A2h) {
  __shared__ float As[32][33], Bs[32][33];
  int tx = threadIdx.x, ty = threadIdx.y;
  int p0 = blockIdx.y * 32, m0 = blockIdx.x * 32;
  float acc[4] = {0.f, 0.f, 0.f, 0.f};
  for (int k0 = 0; k0 < Nn; k0 += 32) {
    #pragma unroll
    for (int r = 0; r < 4; r++) {
      As[ty + 8 * r][tx] = adj[(p0 + ty + 8 * r) * Nn + k0 + tx];
      Bs[ty + 8 * r][tx] = adj[(k0 + ty + 8 * r) * Nn + m0 + tx];
    }
    __syncthreads();
    #pragma unroll
    for (int k = 0; k < 32; k++) {
      float bv = Bs[k][tx];
      #pragma unroll
      for (int r = 0; r < 4; r++) acc[r] += As[ty + 8 * r][k] * bv;
    }
    __syncthreads();
  }
  #pragma unroll
  for (int r = 0; r < 4; r++)
    A2h[(p0 + ty + 8 * r) * Nn + m0 + tx] = __float2half_rn(acc[r]);
}

// ---------------- standalone gated TCN via HMMA (layer 0, skip init) ----------------
__global__ void k_tcn(const __half* __restrict__ h_in, __half* __restrict__ t_out,
                      float* __restrict__ skipbuf,
                      const float* __restrict__ Wf, const float* __restrict__ bfv,
                      const float* __restrict__ Wg, const float* __restrict__ bgv,
                      const float* __restrict__ Wsk, const float* __restrict__ bskv,
                      int Lin) {
  __shared__ __align__(16) __half Bs[64 * PH2];     // rows 0..31: h, rows 32..63: h shifted +1
  __shared__ __align__(16) __half wfs[64 * PW];
  __shared__ __align__(16) __half wgs[64 * PW];
  __shared__ __align__(16) __half wsk16[32 * PW];
  __shared__ __align__(16) __half hns[32 * PH2];
  int t = threadIdx.x, lane = t & 31, wid = t >> 5;
  int n = blockIdx.x, b = blockIdx.y;
  int base = ((b * 32) * Nn + n) * Lt;

  { int r = t >> 3, c8 = (t & 7) * 8;
    *(uint4*)&Bs[r * PH2 + c8] = *(const uint4*)&h_in[base + r * NL + c8]; }
  if (t < 32) *(uint4*)&Bs[t * PH2 + 64] = make_uint4(0, 0, 0, 0);
  #pragma unroll
  for (int q = 0; q < 4; q++) {      // FIX: 1024 weight pairs, not 2048
    int idx = t + q * 256; int o = idx >> 5, c = idx & 31;
    float2 wf = *(const float2*)&Wf[idx * 2];
    float2 wg = *(const float2*)&Wg[idx * 2];
    wfs[c * PW + o] = __float2half_rn(wf.x); wfs[(c + 32) * PW + o] = __float2half_rn(wf.y);
    wgs[c * PW + o] = __float2half_rn(wg.x); wgs[(c + 32) * PW + o] = __float2half_rn(wg.y);
  }
  #pragma unroll
  for (int q = 0; q < 4; q++) {
    int idx = t + q * 256; int o = idx >> 5, c = idx & 31;
    wsk16[c * PW + o] = __float2half_rn(Wsk[idx]);
  }
  __syncthreads();
  #pragma unroll
  for (int q = 0; q < 8; q++) {
    int idx = t + q * 256; int c = idx >> 6, l = idx & 63;
    Bs[(c + 32) * PH2 + l] = Bs[c * PH2 + l + 1];
  }
  __syncthreads();

  int mw = wid & 1, nw = wid >> 1;
  int wm = mw * 16, wl = nw * 16;
  int tt = lane & 7, sel = lane >> 3;
  int a_r = (sel >> 1) * 8 + tt, a_c = wm + (sel & 1) * 8;
  int b_r = (sel & 1) * 8 + tt, b_c = wl + (sel >> 1) * 8;
  uint32_t Bsu = (uint32_t)__cvta_generic_to_shared(Bs);
  uint32_t Wfu = (uint32_t)__cvta_generic_to_shared(wfs);
  uint32_t Wgu = (uint32_t)__cvta_generic_to_shared(wgs);
  uint32_t Hnu = (uint32_t)__cvta_generic_to_shared(hns);
  uint32_t Sku = (uint32_t)__cvta_generic_to_shared(wsk16);

  float fa[2][4] = {}, ga[2][4] = {};
  #pragma unroll
  for (int ks = 0; ks < 64; ks += 16) {
    uint32_t af[4], ag[4], bb[4];
    ldsm4t(af, Wfu + ((ks + a_r) * PW + a_c) * 2);
    ldsm4t(ag, Wgu + ((ks + a_r) * PW + a_c) * 2);
    ldsm4t(bb, Bsu + ((ks + b_r) * PH2 + b_c) * 2);
    mma16816(fa[0], af, bb[0], bb[1]); mma16816(fa[1], af, bb[2], bb[3]);
    mma16816(ga[0], ag, bb[0], bb[1]); mma16816(ga[1], ag, bb[2], bb[3]);
  }
  int grp = lane >> 2, qid = lane & 3;
  int o0 = wm + grp;
  float bf0 = bfv[o0], bf8 = bfv[o0 + 8], bg0 = bgv[o0], bg8 = bgv[o0 + 8];
  #pragma unroll
  for (int nt = 0; nt < 2; nt++) {
    int col = wl + nt * 8 + 2 * qid;
    float h00 = ftanh(fa[nt][0] + bf0) * fsig(ga[nt][0] + bg0);
    float h01 = ftanh(fa[nt][1] + bf0) * fsig(ga[nt][1] + bg0);
    float h10 = ftanh(fa[nt][2] + bf8) * fsig(ga[nt][2] + bg8);
    float h11 = ftanh(fa[nt][3] + bf8) * fsig(ga[nt][3] + bg8);
    *(__half2*)&hns[o0 * PH2 + col]       = __floats2half2_rn(h00, h01);
    *(__half2*)&hns[(o0 + 8) * PH2 + col] = __floats2half2_rn(h10, h11);
  }
  __syncthreads();

  float sa[2][4] = {};
  #pragma unroll
  for (int ks = 0; ks < 32; ks += 16) {
    uint32_t as4[4], bb[4];
    ldsm4t(as4, Sku + ((ks + a_r) * PW + a_c) * 2);
    ldsm4t(bb, Hnu + ((ks + b_r) * PH2 + b_c) * 2);
    mma16816(sa[0], as4, bb[0], bb[1]); mma16816(sa[1], as4, bb[2], bb[3]);
  }
  // coalesced H write (full 64 cols; garbage cols are finite & never read as valid)
  { int r = t >> 3, c8 = (t & 7) * 8;
    *(uint4*)&t_out[base + r * NL + c8] = *(uint4*)&hns[r * PH2 + c8]; }
  // skip init store (mode 0): skipbuf[l-2] = s for 2 <= l < Lout
  int Lout = Lin - 1;
  float bs0 = bskv[o0], bs8 = bskv[o0 + 8];
  int ob0 = base + o0 * NL, ob8 = base + (o0 + 8) * NL;
  #pragma unroll
  for (int nt = 0; nt < 2; nt++) {
    int col = wl + nt * 8 + 2 * qid;
    float s00 = sa[nt][0] + bs0, s01 = sa[nt][1] + bs0;
    float s10 = sa[nt][2] + bs8, s11 = sa[nt][3] + bs8;
    if (col >= 2 && col < Lout)         { skipbuf[ob0 + col - 2] = s00; skipbuf[ob8 + col - 2] = s10; }
    if (col + 1 >= 2 && col + 1 < Lout) { skipbuf[ob0 + col - 1] = s01; skipbuf[ob8 + col - 1] = s11; }
  }
}

// ---------------- fused diffusion: fp16 HMMA + ldmatrix (unchanged) ----------------
__global__ void __launch_bounds__(256) k_diff(
    const __half* __restrict__ H, const __half* __restrict__ adjh,
    const __half* __restrict__ A2h,
    __half* __restrict__ X1, __half* __restrict__ X2) {
  __shared__ __align__(16) __half Hs[64 * PH2];
  __shared__ __align__(16) __half A1s[64 * PH2];
  __shared__ __align__(16) __half A2s[64 * PH2];
  int t = threadIdx.x, lane = t & 31, wid = t >> 5;
  int m0 = blockIdx.x * 64;
  int bc = blockIdx.y;
  int hbase = bc * NL;

  int wm = (wid & 3) * 16;
  int wl = (wid >> 2) * 32;
  int grp = lane >> 2, qid = lane & 3;

  float acc1[4][4] = {}, acc2[4][4] = {};

  int lr = t >> 3;
  int lc8 = (t & 7) * 8;

  int tt = lane & 7, sel = lane >> 3;
  int a_r = (sel >> 1) * 8 + tt;
  int a_c = wm + (sel & 1) * 8;
  int b_r = (sel & 1) * 8 + tt;
  int b_c = wl + (sel >> 1) * 8;

  uint32_t Hu  = (uint32_t)__cvta_generic_to_shared(Hs);
  uint32_t A1u = (uint32_t)__cvta_generic_to_shared(A1s);
  uint32_t A2u = (uint32_t)__cvta_generic_to_shared(A2s);

  for (int k0 = 0; k0 < Nn; k0 += 64) {
    #pragma unroll
    for (int q = 0; q < 2; q++) {
      int r = lr + q * 32;
      *(uint4*)&Hs[r * PH2 + lc8]  = *(const uint4*)&H[hbase + (k0 + r) * Lt + lc8];
      *(uint4*)&A1s[r * PH2 + lc8] = *(const uint4*)&adjh[(k0 + r) * Nn + m0 + lc8];
      *(uint4*)&A2s[r * PH2 + lc8] = *(const uint4*)&A2h[(k0 + r) * Nn + m0 + lc8];
    }
    __syncthreads();

    #pragma unroll
    for (int ks = 0; ks < 64; ks += 16) {
      uint32_t a1[4], a2[4], bA[4], bB[4];
      ldsm4t(a1, A1u + ((ks + a_r) * PH2 + a_c) * 2);
      ldsm4t(a2, A2u + ((ks + a_r) * PH2 + a_c) * 2);
      ldsm4t(bA, Hu + ((ks + b_r) * PH2 + b_c) * 2);
      ldsm4t(bB, Hu + ((ks + b_r) * PH2 + b_c + 16) * 2);
      mma16816(acc1[0], a1, bA[0], bA[1]);
      mma16816(acc1[1], a1, bA[2], bA[3]);
      mma16816(acc1[2], a1, bB[0], bB[1]);
      mma16816(acc1[3], a1, bB[2], bB[3]);
      mma16816(acc2[0], a2, bA[0], bA[1]);
      mma16816(acc2[1], a2, bA[2], bA[3]);
      mma16816(acc2[2], a2, bB[0], bB[1]);
      mma16816(acc2[3], a2, bB[2], bB[3]);
    }
    __syncthreads();
  }

  int row0 = m0 + wm + grp;
  #pragma unroll
  for (int nt = 0; nt < 4; nt++) {
    int col = wl + nt * 8 + 2 * qid;
    *(__half2*)&X1[hbase + row0 * Lt + col]       = __floats2half2_rn(acc1[nt][0], acc1[nt][1]);
    *(__half2*)&X1[hbase + (row0 + 8) * Lt + col] = __floats2half2_rn(acc1[nt][2], acc1[nt][3]);
    *(__half2*)&X2[hbase + row0 * Lt + col]       = __floats2half2_rn(acc2[nt][0], acc2[nt][1]);
    *(__half2*)&X2[hbase + (row0 + 8) * Lt + col] = __floats2half2_rn(acc2[nt][2], acc2[nt][3]);
  }
}

// ---------------- FUSED: gcmix(layer i) + TCN(layer i+1), all GEMMs on HMMA ----------------
#define SB_OFF 13312
__global__ void k_fuse(const __half* __restrict__ Ht, const __half* __restrict__ X1,
                       const __half* __restrict__ X2, const __half* __restrict__ Res,
                       __half* __restrict__ h1_out,
                       const float* __restrict__ Wgc, const float* __restrict__ bgc,
                       const float* __restrict__ gg, const float* __restrict__ gb,
                       const float* __restrict__ bng, const float* __restrict__ bnb,
                       const float* __restrict__ Wf, const float* __restrict__ bfv,
                       const float* __restrict__ Wg, const float* __restrict__ bgv,
                       const float* __restrict__ Wsk, const float* __restrict__ bskv,
                       __half* __restrict__ t_out, float* __restrict__ skipbuf,
                       float* __restrict__ outp,
                       const float* __restrict__ obng, const float* __restrict__ obnb,
                       int LoutG, int mode) {
  __shared__ __align__(16) __half pool[SB_OFF + 32 * 67 * 2];
  __half* cat   = pool;                 // 96 x PH2
  __half* wgc16 = pool + 6912;          // 96 x PW
  __half* Bs2   = pool;                 // 64 x PH2 (overlay)
  __half* wfs   = pool + 4608;
  __half* wgs   = pool + 7168;
  __half* wsk16 = pool + 9728;
  __half* hns   = pool + 11008;         // 32 x PH2
  float*  sbuf  = (float*)(pool + SB_OFF);  // 32 x 67

  int t = threadIdx.x, lane = t & 31, wid = t >> 5;
  int n = blockIdx.x, b = blockIdx.y;
  int base = ((b * 32) * Nn + n) * Lt;

  // ---- stage cat = [Ht; X1; X2] and transposed gc weights ----
  #pragma unroll
  for (int q = 0; q < 3; q++) {
    int idx = t + q * 256;          // 768 = 96 rows x 8 uint4
    int r = idx >> 3, c8 = (idx & 7) * 8;
    const __half* src = (r < 32) ? &Ht[base + r * NL + c8]
                      : (r < 64) ? &X1[base + (r - 32) * NL + c8]
                                 : &X2[base + (r - 64) * NL + c8];
    *(uint4*)&cat[r * PH2 + c8] = *(const uint4*)src;
  }
  #pragma unroll
  for (int q = 0; q < 12; q++) {
    int idx = t + q * 256;          // 3072 = 32 o x 96 k
    int o = idx / 96, k = idx - o * 96;
    wgc16[k * PW + o] = __float2half_rn(Wgc[idx]);
  }
  __syncthreads();

  // ---- gcmix mma: m=32(o), n=64(l), k=96 ----
  int mw = wid & 1, nw = wid >> 1;
  int wm = mw * 16, wl = nw * 16;
  int tt = lane & 7, sel = lane >> 3;
  int a_r = (sel >> 1) * 8 + tt, a_c = wm + (sel & 1) * 8;
  int b_r = (sel & 1) * 8 + tt, b_c = wl + (sel >> 1) * 8;
  uint32_t Cu  = (uint32_t)__cvta_generic_to_shared(cat);
  uint32_t Gu  = (uint32_t)__cvta_generic_to_shared(wgc16);

  float ac[2][4] = {};
  #pragma unroll
  for (int ks = 0; ks < 96; ks += 16) {
    uint32_t ag[4], bb[4];
    ldsm4t(ag, Gu + ((ks + a_r) * PW + a_c) * 2);
    ldsm4t(bb, Cu + ((ks + b_r) * PH2 + b_c) * 2);
    mma16816(ac[0], ag, bb[0], bb[1]); mma16816(ac[1], ag, bb[2], bb[3]);
  }

  // BN + residual + BN in regs
  const float inv0 = rsqrtf(1.0f + 1e-5f);
  int grp = lane >> 2, qid = lane & 3;
  int o0 = wm + grp;
  float hv[2][4];
  #pragma unroll
  for (int rr = 0; rr < 2; rr++) {
    int o = o0 + rr * 8;
    float gi = gg[o] * inv0, gbb = gb[o];
    float bi = bng[o] * inv0, bbb = bnb[o];
    float bo = bgc[o];
    int ob = base + o * NL;
    #pragma unroll
    for (int nt = 0; nt < 2; nt++) {
      int col = wl + nt * 8 + 2 * qid;
      float r0 = __half2float(Res[ob + col + 1]);
      float r1 = (col + 2 < 64) ? __half2float(Res[ob + col + 2]) : 0.0f;
      float v0 = (ac[nt][rr * 2]     + bo) * gi + gbb + r0;
      float v1 = (ac[nt][rr * 2 + 1] + bo) * gi + gbb + r1;
      hv[rr][nt * 2]     = v0 * bi + bbb;
      hv[rr][nt * 2 + 1] = v1 * bi + bbb;
    }
  }
  __syncthreads();   // all gcmix smem reads done; overlay begins

  // ---- write h2 tile (B rows 0..31), spill h1, stage TCN weights ----
  #pragma unroll
  for (int rr = 0; rr < 2; rr++) {
    int o = o0 + rr * 8;
    #pragma unroll
    for (int nt = 0; nt < 2; nt++) {
      int col = wl + nt * 8 + 2 * qid;
      *(__half2*)&Bs2[o * PH2 + col] = __floats2half2_rn(hv[rr][nt * 2], hv[rr][nt * 2 + 1]);
      if (h1_out) {
        int ob = base + o * NL;
        if (col < LoutG)     h1_out[ob + col]     = __float2half_rn(hv[rr][nt * 2]);
        if (col + 1 < LoutG) h1_out[ob + col + 1] = __float2half_rn(hv[rr][nt * 2 + 1]);
      }
    }
  }
  if (t < 32) *(uint4*)&Bs2[t * PH2 + 64] = make_uint4(0, 0, 0, 0);
  #pragma unroll
  for (int q = 0; q < 4; q++) {      // FIX: 1024 weight pairs, not 2048
    int idx = t + q * 256; int o = idx >> 5, c = idx & 31;
    float2 wf = *(const float2*)&Wf[idx * 2];
    float2 wg = *(const float2*)&Wg[idx * 2];
    wfs[c * PW + o] = __float2half_rn(wf.x); wfs[(c + 32) * PW + o] = __float2half_rn(wf.y);
    wgs[c * PW + o] = __float2half_rn(wg.x); wgs[(c + 32) * PW + o] = __float2half_rn(wg.y);
  }
  #pragma unroll
  for (int q = 0; q < 4; q++) {
    int idx = t + q * 256; int o = idx >> 5, c = idx & 31;
    wsk16[c * PW + o] = __float2half_rn(Wsk[idx]);
  }
  __syncthreads();
  // build shifted B rows 32..63
  #pragma unroll
  for (int q = 0; q < 8; q++) {
    int idx = t + q * 256; int c = idx >> 6, l = idx & 63;
    Bs2[(c + 32) * PH2 + l] = Bs2[c * PH2 + l + 1];
  }
  __syncthreads();

  // ---- TCN mma on h2 ----
  uint32_t Bsu = (uint32_t)__cvta_generic_to_shared(Bs2);
  uint32_t Wfu = (uint32_t)__cvta_generic_to_shared(wfs);
  uint32_t Wgu = (uint32_t)__cvta_generic_to_shared(wgs);
  uint32_t Hnu = (uint32_t)__cvta_generic_to_shared(hns);
  uint32_t Sku = (uint32_t)__cvta_generic_to_shared(wsk16);

  float fa[2][4] = {}, ga[2][4] = {};
  #pragma unroll
  for (int ks = 0; ks < 64; ks += 16) {
    uint32_t af[4], ag[4], bb[4];
    ldsm4t(af, Wfu + ((ks + a_r) * PW + a_c) * 2);
    ldsm4t(ag, Wgu + ((ks + a_r) * PW + a_c) * 2);
    ldsm4t(bb, Bsu + ((ks + b_r) * PH2 + b_c) * 2);
    mma16816(fa[0], af, bb[0], bb[1]); mma16816(fa[1], af, bb[2], bb[3]);
    mma16816(ga[0], ag, bb[0], bb[1]); mma16816(ga[1], ag, bb[2], bb[3]);
  }
  float bf0 = bfv[o0], bf8 = bfv[o0 + 8], bg0 = bgv[o0], bg8 = bgv[o0 + 8];
  #pragma unroll
  for (int nt = 0; nt < 2; nt++) {
    int col = wl + nt * 8 + 2 * qid;
    float h00 = ftanh(fa[nt][0] + bf0) * fsig(ga[nt][0] + bg0);
    float h01 = ftanh(fa[nt][1] + bf0) * fsig(ga[nt][1] + bg0);
    float h10 = ftanh(fa[nt][2] + bf8) * fsig(ga[nt][2] + bg8);
    float h11 = ftanh(fa[nt][3] + bf8) * fsig(ga[nt][3] + bg8);
    *(__half2*)&hns[o0 * PH2 + col]       = __floats2half2_rn(h00, h01);
    *(__half2*)&hns[(o0 + 8) * PH2 + col] = __floats2half2_rn(h10, h11);
  }
  __syncthreads();

  float sa[2][4] = {};
  #pragma unroll
  for (int ks = 0; ks < 32; ks += 16) {
    uint32_t as4[4], bb[4];
    ldsm4t(as4, Sku + ((ks + a_r) * PW + a_c) * 2);
    ldsm4t(bb, Hnu + ((ks + b_r) * PH2 + b_c) * 2);
    mma16816(sa[0], as4, bb[0], bb[1]); mma16816(sa[1], as4, bb[2], bb[3]);
  }

  int Lout = LoutG - 1;
  float bs0 = bskv[o0], bs8 = bskv[o0 + 8];
  int ob0 = base + o0 * NL, ob8 = base + (o0 + 8) * NL;

  if (mode == 1) {
    // H write (full cols) + skip accumulate at l-1
    { int r = t >> 3, c8 = (t & 7) * 8;
      *(uint4*)&t_out[base + r * NL + c8] = *(uint4*)&hns[r * PH2 + c8]; }
    #pragma unroll
    for (int nt = 0; nt < 2; nt++) {
      int col = wl + nt * 8 + 2 * qid;
      float s00 = sa[nt][0] + bs0, s01 = sa[nt][1] + bs0;
      float s10 = sa[nt][2] + bs8, s11 = sa[nt][3] + bs8;
      if (col >= 1 && col < Lout) {
        skipbuf[ob0 + col - 1] += s00; skipbuf[ob8 + col - 1] += s10;
      }
      if (col + 1 < Lout) {
        skipbuf[ob0 + col] += s01; skipbuf[ob8 + col] += s11;
      }
    }
  } else {
    // stage s into fp32 sbuf (pitch 67)
    #pragma unroll
    for (int nt = 0; nt < 2; nt++) {
      int col = wl + nt * 8 + 2 * qid;
      sbuf[o0 * 67 + col]           = sa[nt][0] + bs0;
      sbuf[o0 * 67 + col + 1]       = sa[nt][1] + bs0;
      sbuf[(o0 + 8) * 67 + col]     = sa[nt][2] + bs8;
      sbuf[(o0 + 8) * 67 + col + 1] = sa[nt][3] + bs8;
    }
    __syncthreads();
    // phase A: skip add + final BN (coalesced in l), in place
    for (int idx = t; idx < 2048; idx += 256) {
      int c = idx >> 6, l = idx & 63;
      if (l < 61) {
        float inv = obng[c] * inv0;
        sbuf[c * 67 + l] = (skipbuf[base + c * NL + l] + sbuf[c * 67 + l]) * inv + obnb[c];
      }
    }
    __syncthreads();
    // phase B: transposed coalesced write (o contiguous)
    for (int idx = t; idx < 2048; idx += 256) {
      int l = idx >> 5, oo = idx & 31;
      if (l < 61)
        outp[((b * 61 + l) * Nn + n) * 32 + oo] = sbuf[oo * 67 + l];
    }
  }
}

extern "C" void kernel_launch(void* const* d_in, const int* in_sizes, int n_in,
                              void* d_out, int out_size) {
  const float* x      = (const float*)d_in[0];
  const float* adj    = (const float*)d_in[1];
  const float* Wstart = (const float*)d_in[2];
  const float* bstart = (const float*)d_in[3];
  const float* Wf     = (const float*)d_in[4];
  const float* bf     = (const float*)d_in[5];
  const float* Wg     = (const float*)d_in[6];
  const float* bg     = (const float*)d_in[7];
  const float* Wsk    = (const float*)d_in[8];
  const float* bsk    = (const float*)d_in[9];
  const float* Wgc    = (const float*)d_in[10];
  const float* bgc    = (const float*)d_in[11];
  const float* gcg    = (const float*)d_in[12];
  const float* gcb    = (const float*)d_in[13];
  const float* bng    = (const float*)d_in[14];
  const float* bnb    = (const float*)d_in[15];
  const float* obng   = (const float*)d_in[16];
  const float* obnb   = (const float*)d_in[17];
  float* out = (float*)d_out;

  __half *A, *Bu, *Cu, *Du, *Eu, *AJH, *A2H;
  float *SK;
  cudaGetSymbolAddress((void**)&A,   g_A);
  cudaGetSymbolAddress((void**)&Bu,  g_B);
  cudaGetSymbolAddress((void**)&Cu,  g_C);
  cudaGetSymbolAddress((void**)&Du,  g_D);
  cudaGetSymbolAddress((void**)&Eu,  g_E);
  cudaGetSymbolAddress((void**)&SK,  g_SK);
  cudaGetSymbolAddress((void**)&AJH, g_adjh);
  cudaGetSymbolAddress((void**)&A2H, g_A2h);

  dim3 bn_grid(Nn, Bn);
  dim3 diff_grid(8, Bn * Cch);

  k_start<<<BUF / 4 / 256, 256>>>(x, Wstart, bstart, A);
  k_adjh<<<Nn * Nn / 4 / 256, 256>>>(adj, AJH);
  k_a2<<<dim3(16, 16), dim3(32, 8)>>>(adj, A2H);

  // layer 0 TCN (Lin=64)
  k_tcn<<<bn_grid, 256>>>(A, Bu, SK, Wf, bf, Wg, bg, Wsk, bsk, 64);
  k_diff<<<diff_grid, 256>>>(Bu, AJH, A2H, Cu, Du);

  // gcmix(layer0) + TCN(layer1): LoutG=63, mode 1; spills h1 -> Eu
  k_fuse<<<bn_grid, 256>>>(Bu, Cu, Du, A, Eu,
                           Wgc, bgc, gcg, gcb, bng, bnb,
                           Wf + 2048, bf + 32, Wg + 2048, bg + 32,
                           Wsk + 1024, bsk + 32,
                           Bu, SK, nullptr, nullptr, nullptr, 63, 1);
  k_diff<<<diff_grid, 256>>>(Bu, AJH, A2H, Cu, Du);

  // gcmix(layer1) + TCN(layer2, final): LoutG=62, mode 2
  k_fuse<<<bn_grid, 256>>>(Bu, Cu, Du, Eu, nullptr,
                           Wgc + 3072, bgc + 32, gcg + 32, gcb + 32,
                           bng + 32, bnb + 32,
                           Wf + 4096, bf + 64, Wg + 4096, bg + 64,
                           Wsk + 2048, bsk + 64,
                           nullptr, SK, out, obng, obnb, 62, 2);
}

// round 14
// speedup vs baseline: 6.4239x; 1.5242x over previous
#include <cuda_runtime.h>
#include <cuda_fp16.h>
#include <math.h>
#include <stdint.h>

#define Bn 8
#define Cch 32
#define Nn 512
#define Lt 64
#define NL (Nn*Lt)
#define BUF (Bn*Cch*Nn*Lt)
#define PH2 72   // activation/B pitch in halves (144B rows: 16B-aligned, conflict-free ldsm)
#define PW  40   // weight pitch in halves (80B rows: 16B-aligned, conflict-free ldsm)

__device__ __half g_A[BUF];      // h (start output / residual 0)
__device__ __half g_B[BUF];      // H (TCN output)
__device__ __half g_C[BUF];      // X1
__device__ __half g_D[BUF];      // X2
__device__ __half g_E[BUF];      // h1 (residual 1)
__device__ float  g_SK[BUF];     // skip accumulator
__device__ __half g_adjh[Nn*Nn];
__device__ __half g_A2h[Nn*Nn];

__device__ __forceinline__ float fsig(float x) {
  return __fdividef(1.0f, 1.0f + __expf(-x));
}
__device__ __forceinline__ float ftanh(float x) {
  float e = __expf(-2.0f * x);
  return __fdividef(1.0f - e, 1.0f + e);
}
__device__ __forceinline__ void ldsm4t(uint32_t* r, uint32_t addr) {
  asm volatile("ldmatrix.sync.aligned.m8n8.x4.trans.shared.b16 {%0,%1,%2,%3}, [%4];"
    : "=r"(r[0]), "=r"(r[1]), "=r"(r[2]), "=r"(r[3]) : "r"(addr));
}
__device__ __forceinline__ void mma16816(float* c, const uint32_t* a, uint32_t b0, uint32_t b1) {
  asm volatile("mma.sync.aligned.m16n8k16.row.col.f32.f16.f16.f32 "
    "{%0,%1,%2,%3}, {%4,%5,%6,%7}, {%8,%9}, {%0,%1,%2,%3};"
    : "+f"(c[0]), "+f"(c[1]), "+f"(c[2]), "+f"(c[3])
    : "r"(a[0]), "r"(a[1]), "r"(a[2]), "r"(a[3]), "r"(b0), "r"(b1));
}

// ---------------- start conv ----------------
__global__ void k_start(const float* __restrict__ x, const float* __restrict__ W,
                        const float* __restrict__ bias, __half* __restrict__ h) {
  int idx4 = blockIdx.x * 256 + threadIdx.x;
  int l4 = (idx4 & 15) * 4;
  int n  = (idx4 >> 4) & 511;
  int c  = (idx4 >> 13) & 31;
  int b  = idx4 >> 18;
  int xb = ((b * 2) * Nn + n) * Lt + l4;
  float4 x0 = *(const float4*)&x[xb];
  float4 x1 = *(const float4*)&x[xb + NL];
  float w0 = W[c * 2], w1 = W[c * 2 + 1], bs = bias[c];
  int ob = (((b * 32 + c) * Nn + n) * Lt) + l4;
  *(__half2*)&h[ob]     = __floats2half2_rn(x0.x * w0 + x1.x * w1 + bs,
                                            x0.y * w0 + x1.y * w1 + bs);
  *(__half2*)&h[ob + 2] = __floats2half2_rn(x0.z * w0 + x1.z * w1 + bs,
                                            x0.w * w0 + x1.w * w1 + bs);
}

// ---------------- adj -> fp16 ----------------
__global__ void k_adjh(const float* __restrict__ adj, __half* __restrict__ adjh) {
  int i4 = blockIdx.x * 256 + threadIdx.x;
  float4 v = *(const float4*)&adj[i4 * 4];
  *(__half2*)&adjh[i4 * 4]     = __floats2half2_rn(v.x, v.y);
  *(__half2*)&adjh[i4 * 4 + 2] = __floats2half2_rn(v.z, v.w);
}

// ---------------- A2 = adj @ adj (fp32 compute, fp16 out) ----------------
__global__ void k_a2(const float* __restrict__ adj, __half* __restrict__ A2h) {
  __shared__ float As[32][33], Bs[32][33];
  int tx = threadIdx.x, ty = threadIdx.y;
  int p0 = blockIdx.y * 32, m0 = blockIdx.x * 32;
  float acc[4] = {0.f, 0.f, 0.f, 0.f};
  for (int k0 = 0; k0 < Nn; k0 += 32) {
    #pragma unroll
    for (int r = 0; r < 4; r++) {
      As[ty + 8 * r][tx] = adj[(p0 + ty + 8 * r) * Nn + k0 + tx];
      Bs[ty + 8 * r][tx] = adj[(k0 + ty + 8 * r) * Nn + m0 + tx];
    }
    __syncthreads();
    #pragma unroll
    for (int k = 0; k < 32; k++) {
      float bv = Bs[k][tx];
      #pragma unroll
      for (int r = 0; r < 4; r++) acc[r] += As[ty + 8 * r][k] * bv;
    }
    __syncthreads();
  }
  #pragma unroll
  for (int r = 0; r < 4; r++)
    A2h[(p0 + ty + 8 * r) * Nn + m0 + tx] = __float2half_rn(acc[r]);
}

// ---------------- standalone gated TCN via HMMA (layer 0, skip init) ----------------
__global__ void k_tcn(const __half* __restrict__ h_in, __half* __restrict__ t_out,
                      float* __restrict__ skipbuf,
                      const float* __restrict__ Wf, const float* __restrict__ bfv,
                      const float* __restrict__ Wg, const float* __restrict__ bgv,
                      const float* __restrict__ Wsk, const float* __restrict__ bskv,
                      int Lin) {
  __shared__ __align__(16) __half Bs[64 * PH2];     // rows 0..31: h, rows 32..63: h shifted +1
  __shared__ __align__(16) __half wfs[64 * PW];
  __shared__ __align__(16) __half wgs[64 * PW];
  __shared__ __align__(16) __half wsk16[32 * PW];
  __shared__ __align__(16) __half hns[32 * PH2];
  int t = threadIdx.x, lane = t & 31, wid = t >> 5;
  int n = blockIdx.x, b = blockIdx.y;
  int base = ((b * 32) * Nn + n) * Lt;

  { int r = t >> 3, c8 = (t & 7) * 8;
    *(uint4*)&Bs[r * PH2 + c8] = *(const uint4*)&h_in[base + r * NL + c8]; }
  if (t < 32) *(uint4*)&Bs[t * PH2 + 64] = make_uint4(0, 0, 0, 0);
  #pragma unroll
  for (int q = 0; q < 4; q++) {
    int idx = t + q * 256; int o = idx >> 5, c = idx & 31;
    float2 wf = *(const float2*)&Wf[idx * 2];
    float2 wg = *(const float2*)&Wg[idx * 2];
    wfs[c * PW + o] = __float2half_rn(wf.x); wfs[(c + 32) * PW + o] = __float2half_rn(wf.y);
    wgs[c * PW + o] = __float2half_rn(wg.x); wgs[(c + 32) * PW + o] = __float2half_rn(wg.y);
  }
  #pragma unroll
  for (int q = 0; q < 4; q++) {
    int idx = t + q * 256; int o = idx >> 5, c = idx & 31;
    wsk16[c * PW + o] = __float2half_rn(Wsk[idx]);
  }
  __syncthreads();
  #pragma unroll
  for (int q = 0; q < 8; q++) {
    int idx = t + q * 256; int c = idx >> 6, l = idx & 63;
    Bs[(c + 32) * PH2 + l] = Bs[c * PH2 + l + 1];
  }
  __syncthreads();

  int mw = wid & 1, nw = wid >> 1;
  int wm = mw * 16, wl = nw * 16;
  int tt = lane & 7, sel = lane >> 3;
  int a_r = (sel >> 1) * 8 + tt, a_c = wm + (sel & 1) * 8;
  int b_r = (sel & 1) * 8 + tt, b_c = wl + (sel >> 1) * 8;
  uint32_t Bsu = (uint32_t)__cvta_generic_to_shared(Bs);
  uint32_t Wfu = (uint32_t)__cvta_generic_to_shared(wfs);
  uint32_t Wgu = (uint32_t)__cvta_generic_to_shared(wgs);
  uint32_t Hnu = (uint32_t)__cvta_generic_to_shared(hns);
  uint32_t Sku = (uint32_t)__cvta_generic_to_shared(wsk16);

  float fa[2][4] = {}, ga[2][4] = {};
  #pragma unroll
  for (int ks = 0; ks < 64; ks += 16) {
    uint32_t af[4], ag[4], bb[4];
    ldsm4t(af, Wfu + ((ks + a_r) * PW + a_c) * 2);
    ldsm4t(ag, Wgu + ((ks + a_r) * PW + a_c) * 2);
    ldsm4t(bb, Bsu + ((ks + b_r) * PH2 + b_c) * 2);
    mma16816(fa[0], af, bb[0], bb[1]); mma16816(fa[1], af, bb[2], bb[3]);
    mma16816(ga[0], ag, bb[0], bb[1]); mma16816(ga[1], ag, bb[2], bb[3]);
  }
  int grp = lane >> 2, qid = lane & 3;
  int o0 = wm + grp;
  float bf0 = bfv[o0], bf8 = bfv[o0 + 8], bg0 = bgv[o0], bg8 = bgv[o0 + 8];
  #pragma unroll
  for (int nt = 0; nt < 2; nt++) {
    int col = wl + nt * 8 + 2 * qid;
    float h00 = ftanh(fa[nt][0] + bf0) * fsig(ga[nt][0] + bg0);
    float h01 = ftanh(fa[nt][1] + bf0) * fsig(ga[nt][1] + bg0);
    float h10 = ftanh(fa[nt][2] + bf8) * fsig(ga[nt][2] + bg8);
    float h11 = ftanh(fa[nt][3] + bf8) * fsig(ga[nt][3] + bg8);
    *(__half2*)&hns[o0 * PH2 + col]       = __floats2half2_rn(h00, h01);
    *(__half2*)&hns[(o0 + 8) * PH2 + col] = __floats2half2_rn(h10, h11);
  }
  __syncthreads();

  float sa[2][4] = {};
  #pragma unroll
  for (int ks = 0; ks < 32; ks += 16) {
    uint32_t as4[4], bb[4];
    ldsm4t(as4, Sku + ((ks + a_r) * PW + a_c) * 2);
    ldsm4t(bb, Hnu + ((ks + b_r) * PH2 + b_c) * 2);
    mma16816(sa[0], as4, bb[0], bb[1]); mma16816(sa[1], as4, bb[2], bb[3]);
  }
  // coalesced H write (full 64 cols; garbage cols are finite & never read as valid)
  { int r = t >> 3, c8 = (t & 7) * 8;
    *(uint4*)&t_out[base + r * NL + c8] = *(uint4*)&hns[r * PH2 + c8]; }
  // skip init store (mode 0)
  int Lout = Lin - 1;
  float bs0 = bskv[o0], bs8 = bskv[o0 + 8];
  int ob0 = base + o0 * NL, ob8 = base + (o0 + 8) * NL;
  #pragma unroll
  for (int nt = 0; nt < 2; nt++) {
    int col = wl + nt * 8 + 2 * qid;
    float s00 = sa[nt][0] + bs0, s01 = sa[nt][1] + bs0;
    float s10 = sa[nt][2] + bs8, s11 = sa[nt][3] + bs8;
    if (col >= 2 && col < Lout)         { skipbuf[ob0 + col - 2] = s00; skipbuf[ob8 + col - 2] = s10; }
    if (col + 1 >= 2 && col + 1 < Lout) { skipbuf[ob0 + col - 1] = s01; skipbuf[ob8 + col - 1] = s11; }
  }
}

// ---------------- fused diffusion: fp16 HMMA, 2 batches per block ----------------
// Block: 64(m) x 64(l) x 2(bc batches). adj/A2 strips loaded once, serve both batches.
__global__ void __launch_bounds__(256) k_diff(
    const __half* __restrict__ H, const __half* __restrict__ adjh,
    const __half* __restrict__ A2h,
    __half* __restrict__ X1, __half* __restrict__ X2) {
  __shared__ __align__(16) __half H0s[64 * PH2];
  __shared__ __align__(16) __half H1s[64 * PH2];
  __shared__ __align__(16) __half A1s[64 * PH2];
  __shared__ __align__(16) __half A2s[64 * PH2];
  int t = threadIdx.x, lane = t & 31, wid = t >> 5;
  int m0 = blockIdx.x * 64;
  int hb0 = (blockIdx.y * 2) * NL;
  int hb1 = hb0 + NL;

  int wm = (wid & 3) * 16;
  int wl = (wid >> 2) * 32;
  int grp = lane >> 2, qid = lane & 3;

  float p1[2][4][4] = {}, p2[2][4][4] = {};   // [batch][n-tile][frag]

  int lr = t >> 3;
  int lc8 = (t & 7) * 8;

  int tt = lane & 7, sel = lane >> 3;
  int a_r = (sel >> 1) * 8 + tt;
  int a_c = wm + (sel & 1) * 8;
  int b_r = (sel & 1) * 8 + tt;
  int b_c = wl + (sel >> 1) * 8;

  uint32_t H0u = (uint32_t)__cvta_generic_to_shared(H0s);
  uint32_t H1u = (uint32_t)__cvta_generic_to_shared(H1s);
  uint32_t A1u = (uint32_t)__cvta_generic_to_shared(A1s);
  uint32_t A2u = (uint32_t)__cvta_generic_to_shared(A2s);

  for (int k0 = 0; k0 < Nn; k0 += 64) {
    #pragma unroll
    for (int q = 0; q < 2; q++) {
      int r = lr + q * 32;
      *(uint4*)&H0s[r * PH2 + lc8] = *(const uint4*)&H[hb0 + (k0 + r) * Lt + lc8];
      *(uint4*)&H1s[r * PH2 + lc8] = *(const uint4*)&H[hb1 + (k0 + r) * Lt + lc8];
      *(uint4*)&A1s[r * PH2 + lc8] = *(const uint4*)&adjh[(k0 + r) * Nn + m0 + lc8];
      *(uint4*)&A2s[r * PH2 + lc8] = *(const uint4*)&A2h[(k0 + r) * Nn + m0 + lc8];
    }
    __syncthreads();

    #pragma unroll
    for (int ks = 0; ks < 64; ks += 16) {
      uint32_t a1[4], a2[4], b0A[4], b0B[4], b1A[4], b1B[4];
      ldsm4t(a1, A1u + ((ks + a_r) * PH2 + a_c) * 2);
      ldsm4t(a2, A2u + ((ks + a_r) * PH2 + a_c) * 2);
      ldsm4t(b0A, H0u + ((ks + b_r) * PH2 + b_c) * 2);
      ldsm4t(b0B, H0u + ((ks + b_r) * PH2 + b_c + 16) * 2);
      ldsm4t(b1A, H1u + ((ks + b_r) * PH2 + b_c) * 2);
      ldsm4t(b1B, H1u + ((ks + b_r) * PH2 + b_c + 16) * 2);
      mma16816(p1[0][0], a1, b0A[0], b0A[1]); mma16816(p1[0][1], a1, b0A[2], b0A[3]);
      mma16816(p1[0][2], a1, b0B[0], b0B[1]); mma16816(p1[0][3], a1, b0B[2], b0B[3]);
      mma16816(p2[0][0], a2, b0A[0], b0A[1]); mma16816(p2[0][1], a2, b0A[2], b0A[3]);
      mma16816(p2[0][2], a2, b0B[0], b0B[1]); mma16816(p2[0][3], a2, b0B[2], b0B[3]);
      mma16816(p1[1][0], a1, b1A[0], b1A[1]); mma16816(p1[1][1], a1, b1A[2], b1A[3]);
      mma16816(p1[1][2], a1, b1B[0], b1B[1]); mma16816(p1[1][3], a1, b1B[2], b1B[3]);
      mma16816(p2[1][0], a2, b1A[0], b1A[1]); mma16816(p2[1][1], a2, b1A[2], b1A[3]);
      mma16816(p2[1][2], a2, b1B[0], b1B[1]); mma16816(p2[1][3], a2, b1B[2], b1B[3]);
    }
    __syncthreads();
  }

  int row0 = m0 + wm + grp;
  #pragma unroll
  for (int bt = 0; bt < 2; bt++) {
    int hb = bt ? hb1 : hb0;
    #pragma unroll
    for (int nt = 0; nt < 4; nt++) {
      int col = wl + nt * 8 + 2 * qid;
      *(__half2*)&X1[hb + row0 * Lt + col]       = __floats2half2_rn(p1[bt][nt][0], p1[bt][nt][1]);
      *(__half2*)&X1[hb + (row0 + 8) * Lt + col] = __floats2half2_rn(p1[bt][nt][2], p1[bt][nt][3]);
      *(__half2*)&X2[hb + row0 * Lt + col]       = __floats2half2_rn(p2[bt][nt][0], p2[bt][nt][1]);
      *(__half2*)&X2[hb + (row0 + 8) * Lt + col] = __floats2half2_rn(p2[bt][nt][2], p2[bt][nt][3]);
    }
  }
}

// ---------------- FUSED: gcmix(layer i) + TCN(layer i+1), all GEMMs on HMMA ----------------
#define SB_OFF 13312
__global__ void k_fuse(const __half* __restrict__ Ht, const __half* __restrict__ X1,
                       const __half* __restrict__ X2, const __half* __restrict__ Res,
                       __half* __restrict__ h1_out,
                       const float* __restrict__ Wgc, const float* __restrict__ bgc,
                       const float* __restrict__ gg, const float* __restrict__ gb,
                       const float* __restrict__ bng, const float* __restrict__ bnb,
                       const float* __restrict__ Wf, const float* __restrict__ bfv,
                       const float* __restrict__ Wg, const float* __restrict__ bgv,
                       const float* __restrict__ Wsk, const float* __restrict__ bskv,
                       __half* __restrict__ t_out, float* __restrict__ skipbuf,
                       float* __restrict__ outp,
                       const float* __restrict__ obng, const float* __restrict__ obnb,
                       int LoutG, int mode) {
  __shared__ __align__(16) __half pool[SB_OFF + 32 * 67 * 2];
  __half* cat   = pool;                 // 96 x PH2
  __half* wgc16 = pool + 6912;          // 96 x PW
  __half* Bs2   = pool;                 // 64 x PH2 (overlay)
  __half* wfs   = pool + 4608;
  __half* wgs   = pool + 7168;
  __half* wsk16 = pool + 9728;
  __half* hns   = pool + 11008;         // 32 x PH2 (also Res staging during gcmix)
  float*  sbuf  = (float*)(pool + SB_OFF);  // 32 x 67

  int t = threadIdx.x, lane = t & 31, wid = t >> 5;
  int n = blockIdx.x, b = blockIdx.y;
  int base = ((b * 32) * Nn + n) * Lt;

  // ---- stage cat = [Ht; X1; X2], Res (coalesced), transposed gc weights ----
  #pragma unroll
  for (int q = 0; q < 3; q++) {
    int idx = t + q * 256;
    int r = idx >> 3, c8 = (idx & 7) * 8;
    const __half* src = (r < 32) ? &Ht[base + r * NL + c8]
                      : (r < 64) ? &X1[base + (r - 32) * NL + c8]
                                 : &X2[base + (r - 64) * NL + c8];
    *(uint4*)&cat[r * PH2 + c8] = *(const uint4*)src;
  }
  { int r = t >> 3, c8 = (t & 7) * 8;          // Res -> hns region, coalesced
    *(uint4*)&hns[r * PH2 + c8] = *(const uint4*)&Res[base + r * NL + c8]; }
  #pragma unroll
  for (int q = 0; q < 12; q++) {
    int idx = t + q * 256;
    int o = idx / 96, k = idx - o * 96;
    wgc16[k * PW + o] = __float2half_rn(Wgc[idx]);
  }
  __syncthreads();

  // ---- gcmix mma: m=32(o), n=64(l), k=96 ----
  int mw = wid & 1, nw = wid >> 1;
  int wm = mw * 16, wl = nw * 16;
  int tt = lane & 7, sel = lane >> 3;
  int a_r = (sel >> 1) * 8 + tt, a_c = wm + (sel & 1) * 8;
  int b_r = (sel & 1) * 8 + tt, b_c = wl + (sel >> 1) * 8;
  uint32_t Cu  = (uint32_t)__cvta_generic_to_shared(cat);
  uint32_t Gu  = (uint32_t)__cvta_generic_to_shared(wgc16);

  float ac[2][4] = {};
  #pragma unroll
  for (int ks = 0; ks < 96; ks += 16) {
    uint32_t ag[4], bb[4];
    ldsm4t(ag, Gu + ((ks + a_r) * PW + a_c) * 2);
    ldsm4t(bb, Cu + ((ks + b_r) * PH2 + b_c) * 2);
    mma16816(ac[0], ag, bb[0], bb[1]); mma16816(ac[1], ag, bb[2], bb[3]);
  }

  // BN + residual (from smem) + BN in regs
  const float inv0 = rsqrtf(1.0f + 1e-5f);
  int grp = lane >> 2, qid = lane & 3;
  int o0 = wm + grp;
  float hv[2][4];
  #pragma unroll
  for (int rr = 0; rr < 2; rr++) {
    int o = o0 + rr * 8;
    float gi = gg[o] * inv0, gbb = gb[o];
    float bi = bng[o] * inv0, bbb = bnb[o];
    float bo = bgc[o];
    #pragma unroll
    for (int nt = 0; nt < 2; nt++) {
      int col = wl + nt * 8 + 2 * qid;
      float r0 = __half2float(hns[o * PH2 + col + 1]);
      float r1 = (col + 2 < 64) ? __half2float(hns[o * PH2 + col + 2]) : 0.0f;
      float v0 = (ac[nt][rr * 2]     + bo) * gi + gbb + r0;
      float v1 = (ac[nt][rr * 2 + 1] + bo) * gi + gbb + r1;
      hv[rr][nt * 2]     = v0 * bi + bbb;
      hv[rr][nt * 2 + 1] = v1 * bi + bbb;
    }
  }
  __syncthreads();   // all gcmix smem reads done; overlay begins

  // ---- write h2 tile (B rows 0..31), stage TCN weights ----
  #pragma unroll
  for (int rr = 0; rr < 2; rr++) {
    int o = o0 + rr * 8;
    #pragma unroll
    for (int nt = 0; nt < 2; nt++) {
      int col = wl + nt * 8 + 2 * qid;
      *(__half2*)&Bs2[o * PH2 + col] = __floats2half2_rn(hv[rr][nt * 2], hv[rr][nt * 2 + 1]);
    }
  }
  if (t < 32) *(uint4*)&Bs2[t * PH2 + 64] = make_uint4(0, 0, 0, 0);
  #pragma unroll
  for (int q = 0; q < 4; q++) {
    int idx = t + q * 256; int o = idx >> 5, c = idx & 31;
    float2 wf = *(const float2*)&Wf[idx * 2];
    float2 wg = *(const float2*)&Wg[idx * 2];
    wfs[c * PW + o] = __float2half_rn(wf.x); wfs[(c + 32) * PW + o] = __float2half_rn(wf.y);
    wgs[c * PW + o] = __float2half_rn(wg.x); wgs[(c + 32) * PW + o] = __float2half_rn(wg.y);
  }
  #pragma unroll
  for (int q = 0; q < 4; q++) {
    int idx = t + q * 256; int o = idx >> 5, c = idx & 31;
    wsk16[c * PW + o] = __float2half_rn(Wsk[idx]);
  }
  __syncthreads();
  // coalesced h1 spill (full rows; garbage col>=LoutG is finite and feeds no valid output)
  if (h1_out) {
    int r = t >> 3, c8 = (t & 7) * 8;
    *(uint4*)&h1_out[base + r * NL + c8] = *(uint4*)&Bs2[r * PH2 + c8];
  }
  // build shifted B rows 32..63
  #pragma unroll
  for (int q = 0; q < 8; q++) {
    int idx = t + q * 256; int c = idx >> 6, l = idx & 63;
    Bs2[(c + 32) * PH2 + l] = Bs2[c * PH2 + l + 1];
  }
  __syncthreads();

  // ---- TCN mma on h2 ----
  uint32_t Bsu = (uint32_t)__cvta_generic_to_shared(Bs2);
  uint32_t Wfu = (uint32_t)__cvta_generic_to_shared(wfs);
  uint32_t Wgu = (uint32_t)__cvta_generic_to_shared(wgs);
  uint32_t Hnu = (uint32_t)__cvta_generic_to_shared(hns);
  uint32_t Sku = (uint32_t)__cvta_generic_to_shared(wsk16);

  float fa[2][4] = {}, ga[2][4] = {};
  #pragma unroll
  for (int ks = 0; ks < 64; ks += 16) {
    uint32_t af[4], ag[4], bb[4];
    ldsm4t(af, Wfu + ((ks + a_r) * PW + a_c) * 2);
    ldsm4t(ag, Wgu + ((ks + a_r) * PW + a_c) * 2);
    ldsm4t(bb, Bsu + ((ks + b_r) * PH2 + b_c) * 2);
    mma16816(fa[0], af, bb[0], bb[1]); mma16816(fa[1], af, bb[2], bb[3]);
    mma16816(ga[0], ag, bb[0], bb[1]); mma16816(ga[1], ag, bb[2], bb[3]);
  }
  float bf0 = bfv[o0], bf8 = bfv[o0 + 8], bg0 = bgv[o0], bg8 = bgv[o0 + 8];
  #pragma unroll
  for (int nt = 0; nt < 2; nt++) {
    int col = wl + nt * 8 + 2 * qid;
    float h00 = ftanh(fa[nt][0] + bf0) * fsig(ga[nt][0] + bg0);
    float h01 = ftanh(fa[nt][1] + bf0) * fsig(ga[nt][1] + bg0);
    float h10 = ftanh(fa[nt][2] + bf8) * fsig(ga[nt][2] + bg8);
    float h11 = ftanh(fa[nt][3] + bf8) * fsig(ga[nt][3] + bg8);
    *(__half2*)&hns[o0 * PH2 + col]       = __floats2half2_rn(h00, h01);
    *(__half2*)&hns[(o0 + 8) * PH2 + col] = __floats2half2_rn(h10, h11);
  }
  __syncthreads();

  float sa[2][4] = {};
  #pragma unroll
  for (int ks = 0; ks < 32; ks += 16) {
    uint32_t as4[4], bb[4];
    ldsm4t(as4, Sku + ((ks + a_r) * PW + a_c) * 2);
    ldsm4t(bb, Hnu + ((ks + b_r) * PH2 + b_c) * 2);
    mma16816(sa[0], as4, bb[0], bb[1]); mma16816(sa[1], as4, bb[2], bb[3]);
  }

  int Lout = LoutG - 1;
  float bs0 = bskv[o0], bs8 = bskv[o0 + 8];
  int ob0 = base + o0 * NL, ob8 = base + (o0 + 8) * NL;

  if (mode == 1) {
    // H write (full cols) + skip accumulate at l-1
    { int r = t >> 3, c8 = (t & 7) * 8;
      *(uint4*)&t_out[base + r * NL + c8] = *(uint4*)&hns[r * PH2 + c8]; }
    #pragma unroll
    for (int nt = 0; nt < 2; nt++) {
      int col = wl + nt * 8 + 2 * qid;
      float s00 = sa[nt][0] + bs0, s01 = sa[nt][1] + bs0;
      float s10 = sa[nt][2] + bs8, s11 = sa[nt][3] + bs8;
      if (col >= 1 && col < Lout) {
        skipbuf[ob0 + col - 1] += s00; skipbuf[ob8 + col - 1] += s10;
      }
      if (col + 1 < Lout) {
        skipbuf[ob0 + col] += s01; skipbuf[ob8 + col] += s11;
      }
    }
  } else {
    // stage s into fp32 sbuf (pitch 67)
    #pragma unroll
    for (int nt = 0; nt < 2; nt++) {
      int col = wl + nt * 8 + 2 * qid;
      sbuf[o0 * 67 + col]           = sa[nt][0] + bs0;
      sbuf[o0 * 67 + col + 1]       = sa[nt][1] + bs0;
      sbuf[(o0 + 8) * 67 + col]     = sa[nt][2] + bs8;
      sbuf[(o0 + 8) * 67 + col + 1] = sa[nt][3] + bs8;
    }
    __syncthreads();
    // phase A: skip add + final BN (coalesced in l), in place
    for (int idx = t; idx < 2048; idx += 256) {
      int c = idx >> 6, l = idx & 63;
      if (l < 61) {
        float inv = obng[c] * inv0;
        sbuf[c * 67 + l] = (skipbuf[base + c * NL + l] + sbuf[c * 67 + l]) * inv + obnb[c];
      }
    }
    __syncthreads();
    // phase B: transposed coalesced write (o contiguous)
    for (int idx = t; idx < 2048; idx += 256) {
      int l = idx >> 5, oo = idx & 31;
      if (l < 61)
        outp[((b * 61 + l) * Nn + n) * 32 + oo] = sbuf[oo * 67 + l];
    }
  }
}

extern "C" void kernel_launch(void* const* d_in, const int* in_sizes, int n_in,
                              void* d_out, int out_size) {
  const float* x      = (const float*)d_in[0];
  const float* adj    = (const float*)d_in[1];
  const float* Wstart = (const float*)d_in[2];
  const float* bstart = (const float*)d_in[3];
  const float* Wf     = (const float*)d_in[4];
  const float* bf     = (const float*)d_in[5];
  const float* Wg     = (const float*)d_in[6];
  const float* bg     = (const float*)d_in[7];
  const float* Wsk    = (const float*)d_in[8];
  const float* bsk    = (const float*)d_in[9];
  const float* Wgc    = (const float*)d_in[10];
  const float* bgc    = (const float*)d_in[11];
  const float* gcg    = (const float*)d_in[12];
  const float* gcb    = (const float*)d_in[13];
  const float* bng    = (const float*)d_in[14];
  const float* bnb    = (const float*)d_in[15];
  const float* obng   = (const float*)d_in[16];
  const float* obnb   = (const float*)d_in[17];
  float* out = (float*)d_out;

  __half *A, *Bu, *Cu, *Du, *Eu, *AJH, *A2H;
  float *SK;
  cudaGetSymbolAddress((void**)&A,   g_A);
  cudaGetSymbolAddress((void**)&Bu,  g_B);
  cudaGetSymbolAddress((void**)&Cu,  g_C);
  cudaGetSymbolAddress((void**)&Du,  g_D);
  cudaGetSymbolAddress((void**)&Eu,  g_E);
  cudaGetSymbolAddress((void**)&SK,  g_SK);
  cudaGetSymbolAddress((void**)&AJH, g_adjh);
  cudaGetSymbolAddress((void**)&A2H, g_A2h);

  dim3 bn_grid(Nn, Bn);
  dim3 diff_grid(8, Bn * Cch / 2);   // 2 batches per block

  k_start<<<BUF / 4 / 256, 256>>>(x, Wstart, bstart, A);
  k_adjh<<<Nn * Nn / 4 / 256, 256>>>(adj, AJH);
  k_a2<<<dim3(16, 16), dim3(32, 8)>>>(adj, A2H);

  // layer 0 TCN (Lin=64)
  k_tcn<<<bn_grid, 256>>>(A, Bu, SK, Wf, bf, Wg, bg, Wsk, bsk, 64);
  k_diff<<<diff_grid, 256>>>(Bu, AJH, A2H, Cu, Du);

  // gcmix(layer0) + TCN(layer1): LoutG=63, mode 1; spills h1 -> Eu
  k_fuse<<<bn_grid, 256>>>(Bu, Cu, Du, A, Eu,
                           Wgc, bgc, gcg, gcb, bng, bnb,
                           Wf + 2048, bf + 32, Wg + 2048, bg + 32,
                           Wsk + 1024, bsk + 32,
                           Bu, SK, nullptr, nullptr, nullptr, 63, 1);
  k_diff<<<diff_grid, 256>>>(Bu, AJH, A2H, Cu, Du);

  // gcmix(layer1) + TCN(layer2, final): LoutG=62, mode 2
  k_fuse<<<bn_grid, 256>>>(Bu, Cu, Du, Eu, nullptr,
                           Wgc + 3072, bgc + 32, gcg + 32, gcb + 32,
                           bng + 32, bnb + 32,
                           Wf + 4096, bf + 64, Wg + 4096, bg + 64,
                           Wsk + 2048, bsk + 64,
                           nullptr, SK, out, obng, obnb, 62, 2);
}

// round 15
// speedup vs baseline: 7.6658x; 1.1933x over previous
#include <cuda_runtime.h>
#include <cuda_fp16.h>
#include <math.h>
#include <stdint.h>

#define Bn 8
#define Cch 32
#define Nn 512
#define Lt 64
#define NL (Nn*Lt)
#define BUF (Bn*Cch*Nn*Lt)
#define PH2 72   // activation/B pitch in halves (144B rows: 16B-aligned, conflict-free ldsm)
#define PW  40   // weight pitch in halves (80B rows: 16B-aligned, conflict-free ldsm)

__device__ __half g_A[BUF];      // h (start output / residual 0)
__device__ __half g_B[BUF];      // H (TCN output)
__device__ __half g_C[BUF];      // X1
__device__ __half g_D[BUF];      // X2
__device__ __half g_E[BUF];      // h1 (residual 1)
__device__ float  g_SK[BUF];     // skip accumulator
__device__ __half g_adjh[Nn*Nn];
__device__ __half g_A2h[Nn*Nn];
// pre-converted fp16 weights (transposed, pitched)
__device__ __align__(16) __half g_Wf16[3 * 64 * PW];
__device__ __align__(16) __half g_Wg16[3 * 64 * PW];
__device__ __align__(16) __half g_Wsk16[3 * 32 * PW];
__device__ __align__(16) __half g_Wgc16[2 * 96 * PW];

__device__ __forceinline__ float fsig(float x) {
  return __fdividef(1.0f, 1.0f + __expf(-x));
}
__device__ __forceinline__ float ftanh(float x) {
  float e = __expf(-2.0f * x);
  return __fdividef(1.0f - e, 1.0f + e);
}
__device__ __forceinline__ void ldsm4t(uint32_t* r, uint32_t addr) {
  asm volatile("ldmatrix.sync.aligned.m8n8.x4.trans.shared.b16 {%0,%1,%2,%3}, [%4];"
    : "=r"(r[0]), "=r"(r[1]), "=r"(r[2]), "=r"(r[3]) : "r"(addr));
}
__device__ __forceinline__ void mma16816(float* c, const uint32_t* a, uint32_t b0, uint32_t b1) {
  asm volatile("mma.sync.aligned.m16n8k16.row.col.f32.f16.f16.f32 "
    "{%0,%1,%2,%3}, {%4,%5,%6,%7}, {%8,%9}, {%0,%1,%2,%3};"
    : "+f"(c[0]), "+f"(c[1]), "+f"(c[2]), "+f"(c[3])
    : "r"(a[0]), "r"(a[1]), "r"(a[2]), "r"(a[3]), "r"(b0), "r"(b1));
}
__device__ __forceinline__ void cp16(uint32_t dst, const void* src) {
  asm volatile("cp.async.cg.shared.global [%0], [%1], 16;" :: "r"(dst), "l"(src));
}

// ---------------- one-time weight conversion ----------------
__global__ void k_wprep(const float* __restrict__ Wf, const float* __restrict__ Wg,
                        const float* __restrict__ Wsk, const float* __restrict__ Wgc) {
  int t = threadIdx.x;
  for (int idx = t; idx < 3 * 1024; idx += 256) {
    int L = idx >> 10, r = idx & 1023;
    int o = r >> 5, c = r & 31;
    float2 wf = *(const float2*)&Wf[idx * 2];
    float2 wg = *(const float2*)&Wg[idx * 2];
    g_Wf16[L * 64 * PW + c * PW + o]        = __float2half_rn(wf.x);
    g_Wf16[L * 64 * PW + (c + 32) * PW + o] = __float2half_rn(wf.y);
    g_Wg16[L * 64 * PW + c * PW + o]        = __float2half_rn(wg.x);
    g_Wg16[L * 64 * PW + (c + 32) * PW + o] = __float2half_rn(wg.y);
    g_Wsk16[L * 32 * PW + c * PW + o]       = __float2half_rn(Wsk[idx]);
  }
  for (int idx = t; idx < 2 * 3072; idx += 256) {
    int L = idx / 3072, r = idx % 3072;
    int o = r / 96, k = r - o * 96;
    g_Wgc16[L * 96 * PW + k * PW + o] = __float2half_rn(Wgc[idx]);
  }
}

// ---------------- adj -> fp16 ----------------
__global__ void k_adjh(const float* __restrict__ adj, __half* __restrict__ adjh) {
  int i4 = blockIdx.x * 256 + threadIdx.x;
  float4 v = *(const float4*)&adj[i4 * 4];
  *(__half2*)&adjh[i4 * 4]     = __floats2half2_rn(v.x, v.y);
  *(__half2*)&adjh[i4 * 4 + 2] = __floats2half2_rn(v.z, v.w);
}

// ---------------- A2 = adj @ adj (fp32 compute, fp16 out) ----------------
__global__ void k_a2(const float* __restrict__ adj, __half* __restrict__ A2h) {
  __shared__ float As[32][33], Bs[32][33];
  int tx = threadIdx.x, ty = threadIdx.y;
  int p0 = blockIdx.y * 32, m0 = blockIdx.x * 32;
  float acc[4] = {0.f, 0.f, 0.f, 0.f};
  for (int k0 = 0; k0 < Nn; k0 += 32) {
    #pragma unroll
    for (int r = 0; r < 4; r++) {
      As[ty + 8 * r][tx] = adj[(p0 + ty + 8 * r) * Nn + k0 + tx];
      Bs[ty + 8 * r][tx] = adj[(k0 + ty + 8 * r) * Nn + m0 + tx];
    }
    __syncthreads();
    #pragma unroll
    for (int k = 0; k < 32; k++) {
      float bv = Bs[k][tx];
      #pragma unroll
      for (int r = 0; r < 4; r++) acc[r] += As[ty + 8 * r][k] * bv;
    }
    __syncthreads();
  }
  #pragma unroll
  for (int r = 0; r < 4; r++)
    A2h[(p0 + ty + 8 * r) * Nn + m0 + tx] = __float2half_rn(acc[r]);
}

// ---------------- gated TCN layer 0 with fused start conv ----------------
__global__ void k_tcn(const float* __restrict__ x,
                      const float* __restrict__ Wst, const float* __restrict__ bst,
                      __half* __restrict__ A_out, __half* __restrict__ t_out,
                      float* __restrict__ skipbuf,
                      const __half* __restrict__ wf16, const __half* __restrict__ wg16,
                      const __half* __restrict__ wskg,
                      const float* __restrict__ bfv, const float* __restrict__ bgv,
                      const float* __restrict__ bskv) {
  __shared__ __align__(16) __half Bs[64 * PH2];
  __shared__ __align__(16) __half wfs[64 * PW];
  __shared__ __align__(16) __half wgs[64 * PW];
  __shared__ __align__(16) __half wsk16[32 * PW];
  __shared__ __align__(16) __half hns[32 * PH2];
  __shared__ float sbuf[32 * 65];
  int t = threadIdx.x, lane = t & 31, wid = t >> 5;
  int n = blockIdx.x, b = blockIdx.y;
  int base = ((b * 32) * Nn + n) * Lt;

  // fused start conv: h[r][c8..c8+7] from x, write to Bs + g_A
  { int r = t >> 3, c8 = (t & 7) * 8;
    int xb = ((b * 2) * Nn + n) * Lt + c8;
    float4 xa = *(const float4*)&x[xb];
    float4 xb4 = *(const float4*)&x[xb + 4];
    float4 ya = *(const float4*)&x[xb + NL];
    float4 yb = *(const float4*)&x[xb + NL + 4];
    float w0 = __ldg(&Wst[r * 2]), w1 = __ldg(&Wst[r * 2 + 1]), bsv = __ldg(&bst[r]);
    __half2 h01 = __floats2half2_rn(xa.x * w0 + ya.x * w1 + bsv, xa.y * w0 + ya.y * w1 + bsv);
    __half2 h23 = __floats2half2_rn(xa.z * w0 + ya.z * w1 + bsv, xa.w * w0 + ya.w * w1 + bsv);
    __half2 h45 = __floats2half2_rn(xb4.x * w0 + yb.x * w1 + bsv, xb4.y * w0 + yb.y * w1 + bsv);
    __half2 h67 = __floats2half2_rn(xb4.z * w0 + yb.z * w1 + bsv, xb4.w * w0 + yb.w * w1 + bsv);
    *(__half2*)&Bs[r * PH2 + c8]     = h01;
    *(__half2*)&Bs[r * PH2 + c8 + 2] = h23;
    *(__half2*)&Bs[r * PH2 + c8 + 4] = h45;
    *(__half2*)&Bs[r * PH2 + c8 + 6] = h67;
    *(__half2*)&A_out[base + r * NL + c8]     = h01;
    *(__half2*)&A_out[base + r * NL + c8 + 2] = h23;
    *(__half2*)&A_out[base + r * NL + c8 + 4] = h45;
    *(__half2*)&A_out[base + r * NL + c8 + 6] = h67;
  }
  if (t < 32) *(uint4*)&Bs[t * PH2 + 64] = make_uint4(0, 0, 0, 0);
  // vectorized weight staging from pre-converted buffers
  for (int idx = t; idx < 320; idx += 256) {
    ((uint4*)wfs)[idx] = ((const uint4*)wf16)[idx];
    ((uint4*)wgs)[idx] = ((const uint4*)wg16)[idx];
  }
  for (int idx = t; idx < 160; idx += 256)
    ((uint4*)wsk16)[idx] = ((const uint4*)wskg)[idx];
  __syncthreads();
  #pragma unroll
  for (int q = 0; q < 8; q++) {
    int idx = t + q * 256; int c = idx >> 6, l = idx & 63;
    Bs[(c + 32) * PH2 + l] = Bs[c * PH2 + l + 1];
  }
  __syncthreads();

  int mw = wid & 1, nw = wid >> 1;
  int wm = mw * 16, wl = nw * 16;
  int tt = lane & 7, sel = lane >> 3;
  int a_r = (sel >> 1) * 8 + tt, a_c = wm + (sel & 1) * 8;
  int b_r = (sel & 1) * 8 + tt, b_c = wl + (sel >> 1) * 8;
  uint32_t Bsu = (uint32_t)__cvta_generic_to_shared(Bs);
  uint32_t Wfu = (uint32_t)__cvta_generic_to_shared(wfs);
  uint32_t Wgu = (uint32_t)__cvta_generic_to_shared(wgs);
  uint32_t Hnu = (uint32_t)__cvta_generic_to_shared(hns);
  uint32_t Sku = (uint32_t)__cvta_generic_to_shared(wsk16);

  float fa[2][4] = {}, ga[2][4] = {};
  #pragma unroll
  for (int ks = 0; ks < 64; ks += 16) {
    uint32_t af[4], ag[4], bb[4];
    ldsm4t(af, Wfu + ((ks + a_r) * PW + a_c) * 2);
    ldsm4t(ag, Wgu + ((ks + a_r) * PW + a_c) * 2);
    ldsm4t(bb, Bsu + ((ks + b_r) * PH2 + b_c) * 2);
    mma16816(fa[0], af, bb[0], bb[1]); mma16816(fa[1], af, bb[2], bb[3]);
    mma16816(ga[0], ag, bb[0], bb[1]); mma16816(ga[1], ag, bb[2], bb[3]);
  }
  int grp = lane >> 2, qid = lane & 3;
  int o0 = wm + grp;
  float bf0 = bfv[o0], bf8 = bfv[o0 + 8], bg0 = bgv[o0], bg8 = bgv[o0 + 8];
  #pragma unroll
  for (int nt = 0; nt < 2; nt++) {
    int col = wl + nt * 8 + 2 * qid;
    float h00 = ftanh(fa[nt][0] + bf0) * fsig(ga[nt][0] + bg0);
    float h01 = ftanh(fa[nt][1] + bf0) * fsig(ga[nt][1] + bg0);
    float h10 = ftanh(fa[nt][2] + bf8) * fsig(ga[nt][2] + bg8);
    float h11 = ftanh(fa[nt][3] + bf8) * fsig(ga[nt][3] + bg8);
    *(__half2*)&hns[o0 * PH2 + col]       = __floats2half2_rn(h00, h01);
    *(__half2*)&hns[(o0 + 8) * PH2 + col] = __floats2half2_rn(h10, h11);
  }
  __syncthreads();

  float sa[2][4] = {};
  #pragma unroll
  for (int ks = 0; ks < 32; ks += 16) {
    uint32_t as4[4], bb[4];
    ldsm4t(as4, Sku + ((ks + a_r) * PW + a_c) * 2);
    ldsm4t(bb, Hnu + ((ks + b_r) * PH2 + b_c) * 2);
    mma16816(sa[0], as4, bb[0], bb[1]); mma16816(sa[1], as4, bb[2], bb[3]);
  }
  // coalesced H write
  { int r = t >> 3, c8 = (t & 7) * 8;
    *(uint4*)&t_out[base + r * NL + c8] = *(uint4*)&hns[r * PH2 + c8]; }
  // stage skip into sbuf (fp32), then coalesced store
  float bs0 = bskv[o0], bs8 = bskv[o0 + 8];
  #pragma unroll
  for (int nt = 0; nt < 2; nt++) {
    int col = wl + nt * 8 + 2 * qid;
    sbuf[o0 * 65 + col]           = sa[nt][0] + bs0;
    sbuf[o0 * 65 + col + 1]       = sa[nt][1] + bs0;
    sbuf[(o0 + 8) * 65 + col]     = sa[nt][2] + bs8;
    sbuf[(o0 + 8) * 65 + col + 1] = sa[nt][3] + bs8;
  }
  __syncthreads();
  for (int idx = t; idx < 2048; idx += 256) {
    int c = idx >> 6, l = idx & 63;
    if (l >= 2 && l < 63) skipbuf[base + c * NL + l - 2] = sbuf[c * 65 + l];
  }
}

// ---------------- fused diffusion: fp16 HMMA, 2 batches/block, cp.async pipeline ----------------
__global__ void __launch_bounds__(256) k_diff(
    const __half* __restrict__ H, const __half* __restrict__ adjh,
    const __half* __restrict__ A2h,
    __half* __restrict__ X1, __half* __restrict__ X2) {
  extern __shared__ __half dsm[];      // 2 stages x 4 strips x 64*PH2
  const int STR = 64 * PH2;
  int t = threadIdx.x, lane = t & 31, wid = t >> 5;
  int m0 = blockIdx.x * 64;
  int hb0 = (blockIdx.y * 2) * NL;
  int hb1 = hb0 + NL;

  int wm = (wid & 3) * 16;
  int wl = (wid >> 2) * 32;
  int grp = lane >> 2, qid = lane & 3;

  float p1[2][4][4] = {}, p2[2][4][4] = {};

  int lr = t >> 3;
  int lc8 = (t & 7) * 8;

  int tt = lane & 7, sel = lane >> 3;
  int a_r = (sel >> 1) * 8 + tt;
  int a_c = wm + (sel & 1) * 8;
  int b_r = (sel & 1) * 8 + tt;
  int b_c = wl + (sel >> 1) * 8;

  uint32_t dsmu = (uint32_t)__cvta_generic_to_shared(dsm);

  auto stage = [&](int i, int k0) {
    #pragma unroll
    for (int q = 0; q < 2; q++) {
      int r = lr + q * 32;
      uint32_t off = (uint32_t)((r * PH2 + lc8) * 2);
      uint32_t bb = dsmu + (uint32_t)(i * 4 * STR * 2);
      cp16(bb + off,               &H[hb0 + (k0 + r) * Lt + lc8]);
      cp16(bb + STR * 2 + off,     &H[hb1 + (k0 + r) * Lt + lc8]);
      cp16(bb + STR * 4 + off,     &adjh[(k0 + r) * Nn + m0 + lc8]);
      cp16(bb + STR * 6 + off,     &A2h[(k0 + r) * Nn + m0 + lc8]);
    }
    asm volatile("cp.async.commit_group;");
  };

  stage(0, 0);
  for (int ck = 0; ck < 8; ck++) {
    if (ck < 7) {
      stage((ck + 1) & 1, (ck + 1) * 64);
      asm volatile("cp.async.wait_group 1;");
    } else {
      asm volatile("cp.async.wait_group 0;");
    }
    __syncthreads();
    int i = ck & 1;
    uint32_t H0u = dsmu + (uint32_t)((i * 4 + 0) * STR * 2);
    uint32_t H1u = dsmu + (uint32_t)((i * 4 + 1) * STR * 2);
    uint32_t A1u = dsmu + (uint32_t)((i * 4 + 2) * STR * 2);
    uint32_t A2u = dsmu + (uint32_t)((i * 4 + 3) * STR * 2);
    #pragma unroll
    for (int ks = 0; ks < 64; ks += 16) {
      uint32_t a1[4], a2[4], b0A[4], b0B[4], b1A[4], b1B[4];
      ldsm4t(a1, A1u + ((ks + a_r) * PH2 + a_c) * 2);
      ldsm4t(a2, A2u + ((ks + a_r) * PH2 + a_c) * 2);
      ldsm4t(b0A, H0u + ((ks + b_r) * PH2 + b_c) * 2);
      ldsm4t(b0B, H0u + ((ks + b_r) * PH2 + b_c + 16) * 2);
      ldsm4t(b1A, H1u + ((ks + b_r) * PH2 + b_c) * 2);
      ldsm4t(b1B, H1u + ((ks + b_r) * PH2 + b_c + 16) * 2);
      mma16816(p1[0][0], a1, b0A[0], b0A[1]); mma16816(p1[0][1], a1, b0A[2], b0A[3]);
      mma16816(p1[0][2], a1, b0B[0], b0B[1]); mma16816(p1[0][3], a1, b0B[2], b0B[3]);
      mma16816(p2[0][0], a2, b0A[0], b0A[1]); mma16816(p2[0][1], a2, b0A[2], b0A[3]);
      mma16816(p2[0][2], a2, b0B[0], b0B[1]); mma16816(p2[0][3], a2, b0B[2], b0B[3]);
      mma16816(p1[1][0], a1, b1A[0], b1A[1]); mma16816(p1[1][1], a1, b1A[2], b1A[3]);
      mma16816(p1[1][2], a1, b1B[0], b1B[1]); mma16816(p1[1][3], a1, b1B[2], b1B[3]);
      mma16816(p2[1][0], a2, b1A[0], b1A[1]); mma16816(p2[1][1], a2, b1A[2], b1A[3]);
      mma16816(p2[1][2], a2, b1B[0], b1B[1]); mma16816(p2[1][3], a2, b1B[2], b1B[3]);
    }
    __syncthreads();
  }

  int row0 = m0 + wm + grp;
  #pragma unroll
  for (int bt = 0; bt < 2; bt++) {
    int hb = bt ? hb1 : hb0;
    #pragma unroll
    for (int nt = 0; nt < 4; nt++) {
      int col = wl + nt * 8 + 2 * qid;
      *(__half2*)&X1[hb + row0 * Lt + col]       = __floats2half2_rn(p1[bt][nt][0], p1[bt][nt][1]);
      *(__half2*)&X1[hb + (row0 + 8) * Lt + col] = __floats2half2_rn(p1[bt][nt][2], p1[bt][nt][3]);
      *(__half2*)&X2[hb + row0 * Lt + col]       = __floats2half2_rn(p2[bt][nt][0], p2[bt][nt][1]);
      *(__half2*)&X2[hb + (row0 + 8) * Lt + col] = __floats2half2_rn(p2[bt][nt][2], p2[bt][nt][3]);
    }
  }
}

// ---------------- FUSED: gcmix(layer i) + TCN(layer i+1), all GEMMs on HMMA ----------------
#define SB_OFF 13312
__global__ void k_fuse(const __half* __restrict__ Ht, const __half* __restrict__ X1,
                       const __half* __restrict__ X2, const __half* __restrict__ Res,
                       __half* __restrict__ h1_out,
                       const __half* __restrict__ wgc16g, const float* __restrict__ bgc,
                       const float* __restrict__ gg, const float* __restrict__ gb,
                       const float* __restrict__ bng, const float* __restrict__ bnb,
                       const __half* __restrict__ wf16g, const float* __restrict__ bfv,
                       const __half* __restrict__ wg16g, const float* __restrict__ bgv,
                       const __half* __restrict__ wskg, const float* __restrict__ bskv,
                       __half* __restrict__ t_out, float* __restrict__ skipbuf,
                       float* __restrict__ outp,
                       const float* __restrict__ obng, const float* __restrict__ obnb,
                       int LoutG, int mode) {
  __shared__ __align__(16) __half pool[SB_OFF + 32 * 67 * 2];
  __half* cat   = pool;                 // 96 x PH2
  __half* wgc16 = pool + 6912;          // 96 x PW
  __half* Bs2   = pool;                 // 64 x PH2 (overlay)
  __half* wfs   = pool + 4608;
  __half* wgs   = pool + 7168;
  __half* wsk16 = pool + 9728;
  __half* hns   = pool + 11008;         // 32 x PH2 (also Res staging during gcmix)
  float*  sbuf  = (float*)(pool + SB_OFF);  // 32 x 67

  int t = threadIdx.x, lane = t & 31, wid = t >> 5;
  int n = blockIdx.x, b = blockIdx.y;
  int base = ((b * 32) * Nn + n) * Lt;

  #pragma unroll
  for (int q = 0; q < 3; q++) {
    int idx = t + q * 256;
    int r = idx >> 3, c8 = (idx & 7) * 8;
    const __half* src = (r < 32) ? &Ht[base + r * NL + c8]
                      : (r < 64) ? &X1[base + (r - 32) * NL + c8]
                                 : &X2[base + (r - 64) * NL + c8];
    *(uint4*)&cat[r * PH2 + c8] = *(const uint4*)src;
  }
  { int r = t >> 3, c8 = (t & 7) * 8;
    *(uint4*)&hns[r * PH2 + c8] = *(const uint4*)&Res[base + r * NL + c8]; }
  for (int idx = t; idx < 480; idx += 256)
    ((uint4*)wgc16)[idx] = ((const uint4*)wgc16g)[idx];
  __syncthreads();

  int mw = wid & 1, nw = wid >> 1;
  int wm = mw * 16, wl = nw * 16;
  int tt = lane & 7, sel = lane >> 3;
  int a_r = (sel >> 1) * 8 + tt, a_c = wm + (sel & 1) * 8;
  int b_r = (sel & 1) * 8 + tt, b_c = wl + (sel >> 1) * 8;
  uint32_t Cu  = (uint32_t)__cvta_generic_to_shared(cat);
  uint32_t Gu  = (uint32_t)__cvta_generic_to_shared(wgc16);

  float ac[2][4] = {};
  #pragma unroll
  for (int ks = 0; ks < 96; ks += 16) {
    uint32_t ag[4], bb[4];
    ldsm4t(ag, Gu + ((ks + a_r) * PW + a_c) * 2);
    ldsm4t(bb, Cu + ((ks + b_r) * PH2 + b_c) * 2);
    mma16816(ac[0], ag, bb[0], bb[1]); mma16816(ac[1], ag, bb[2], bb[3]);
  }

  const float inv0 = rsqrtf(1.0f + 1e-5f);
  int grp = lane >> 2, qid = lane & 3;
  int o0 = wm + grp;
  float hv[2][4];
  #pragma unroll
  for (int rr = 0; rr < 2; rr++) {
    int o = o0 + rr * 8;
    float gi = gg[o] * inv0, gbb = gb[o];
    float bi = bng[o] * inv0, bbb = bnb[o];
    float bo = bgc[o];
    #pragma unroll
    for (int nt = 0; nt < 2; nt++) {
      int col = wl + nt * 8 + 2 * qid;
      float r0 = __half2float(hns[o * PH2 + col + 1]);
      float r1 = (col + 2 < 64) ? __half2float(hns[o * PH2 + col + 2]) : 0.0f;
      float v0 = (ac[nt][rr * 2]     + bo) * gi + gbb + r0;
      float v1 = (ac[nt][rr * 2 + 1] + bo) * gi + gbb + r1;
      hv[rr][nt * 2]     = v0 * bi + bbb;
      hv[rr][nt * 2 + 1] = v1 * bi + bbb;
    }
  }
  __syncthreads();

  #pragma unroll
  for (int rr = 0; rr < 2; rr++) {
    int o = o0 + rr * 8;
    #pragma unroll
    for (int nt = 0; nt < 2; nt++) {
      int col = wl + nt * 8 + 2 * qid;
      *(__half2*)&Bs2[o * PH2 + col] = __floats2half2_rn(hv[rr][nt * 2], hv[rr][nt * 2 + 1]);
    }
  }
  if (t < 32) *(uint4*)&Bs2[t * PH2 + 64] = make_uint4(0, 0, 0, 0);
  for (int idx = t; idx < 320; idx += 256) {
    ((uint4*)wfs)[idx] = ((const uint4*)wf16g)[idx];
    ((uint4*)wgs)[idx] = ((const uint4*)wg16g)[idx];
  }
  for (int idx = t; idx < 160; idx += 256)
    ((uint4*)wsk16)[idx] = ((const uint4*)wskg)[idx];
  __syncthreads();
  if (h1_out) {
    int r = t >> 3, c8 = (t & 7) * 8;
    *(uint4*)&h1_out[base + r * NL + c8] = *(uint4*)&Bs2[r * PH2 + c8];
  }
  #pragma unroll
  for (int q = 0; q < 8; q++) {
    int idx = t + q * 256; int c = idx >> 6, l = idx & 63;
    Bs2[(c + 32) * PH2 + l] = Bs2[c * PH2 + l + 1];
  }
  __syncthreads();

  uint32_t Bsu = (uint32_t)__cvta_generic_to_shared(Bs2);
  uint32_t Wfu = (uint32_t)__cvta_generic_to_shared(wfs);
  uint32_t Wgu = (uint32_t)__cvta_generic_to_shared(wgs);
  uint32_t Hnu = (uint32_t)__cvta_generic_to_shared(hns);
  uint32_t Sku = (uint32_t)__cvta_generic_to_shared(wsk16);

  float fa[2][4] = {}, ga[2][4] = {};
  #pragma unroll
  for (int ks = 0; ks < 64; ks += 16) {
    uint32_t af[4], ag[4], bb[4];
    ldsm4t(af, Wfu + ((ks + a_r) * PW + a_c) * 2);
    ldsm4t(ag, Wgu + ((ks + a_r) * PW + a_c) * 2);
    ldsm4t(bb, Bsu + ((ks + b_r) * PH2 + b_c) * 2);
    mma16816(fa[0], af, bb[0], bb[1]); mma16816(fa[1], af, bb[2], bb[3]);
    mma16816(ga[0], ag, bb[0], bb[1]); mma16816(ga[1], ag, bb[2], bb[3]);
  }
  float bf0 = bfv[o0], bf8 = bfv[o0 + 8], bg0 = bgv[o0], bg8 = bgv[o0 + 8];
  #pragma unroll
  for (int nt = 0; nt < 2; nt++) {
    int col = wl + nt * 8 + 2 * qid;
    float h00 = ftanh(fa[nt][0] + bf0) * fsig(ga[nt][0] + bg0);
    float h01 = ftanh(fa[nt][1] + bf0) * fsig(ga[nt][1] + bg0);
    float h10 = ftanh(fa[nt][2] + bf8) * fsig(ga[nt][2] + bg8);
    float h11 = ftanh(fa[nt][3] + bf8) * fsig(ga[nt][3] + bg8);
    *(__half2*)&hns[o0 * PH2 + col]       = __floats2half2_rn(h00, h01);
    *(__half2*)&hns[(o0 + 8) * PH2 + col] = __floats2half2_rn(h10, h11);
  }
  __syncthreads();

  float sa[2][4] = {};
  #pragma unroll
  for (int ks = 0; ks < 32; ks += 16) {
    uint32_t as4[4], bb[4];
    ldsm4t(as4, Sku + ((ks + a_r) * PW + a_c) * 2);
    ldsm4t(bb, Hnu + ((ks + b_r) * PH2 + b_c) * 2);
    mma16816(sa[0], as4, bb[0], bb[1]); mma16816(sa[1], as4, bb[2], bb[3]);
  }

  int Lout = LoutG - 1;
  float bs0 = bskv[o0], bs8 = bskv[o0 + 8];

  // stage s into fp32 sbuf (pitch 67) for coalesced skip traffic in BOTH modes
  #pragma unroll
  for (int nt = 0; nt < 2; nt++) {
    int col = wl + nt * 8 + 2 * qid;
    sbuf[o0 * 67 + col]           = sa[nt][0] + bs0;
    sbuf[o0 * 67 + col + 1]       = sa[nt][1] + bs0;
    sbuf[(o0 + 8) * 67 + col]     = sa[nt][2] + bs8;
    sbuf[(o0 + 8) * 67 + col + 1] = sa[nt][3] + bs8;
  }
  __syncthreads();

  if (mode == 1) {
    { int r = t >> 3, c8 = (t & 7) * 8;
      *(uint4*)&t_out[base + r * NL + c8] = *(uint4*)&hns[r * PH2 + c8]; }
    for (int idx = t; idx < 2048; idx += 256) {
      int c = idx >> 6, l = idx & 63;
      if (l >= 1 && l < Lout) skipbuf[base + c * NL + l - 1] += sbuf[c * 67 + l];
    }
  } else {
    for (int idx = t; idx < 2048; idx += 256) {
      int c = idx >> 6, l = idx & 63;
      if (l < 61) {
        float inv = obng[c] * inv0;
        sbuf[c * 67 + l] = (skipbuf[base + c * NL + l] + sbuf[c * 67 + l]) * inv + obnb[c];
      }
    }
    __syncthreads();
    for (int idx = t; idx < 2048; idx += 256) {
      int l = idx >> 5, oo = idx & 31;
      if (l < 61)
        outp[((b * 61 + l) * Nn + n) * 32 + oo] = sbuf[oo * 67 + l];
    }
  }
}

extern "C" void kernel_launch(void* const* d_in, const int* in_sizes, int n_in,
                              void* d_out, int out_size) {
  const float* x      = (const float*)d_in[0];
  const float* adj    = (const float*)d_in[1];
  const float* Wstart = (const float*)d_in[2];
  const float* bstart = (const float*)d_in[3];
  const float* Wf     = (const float*)d_in[4];
  const float* bf     = (const float*)d_in[5];
  const float* Wg     = (const float*)d_in[6];
  const float* bg     = (const float*)d_in[7];
  const float* Wsk    = (const float*)d_in[8];
  const float* bsk    = (const float*)d_in[9];
  const float* Wgc    = (const float*)d_in[10];
  const float* bgc    = (const float*)d_in[11];
  const float* gcg    = (const float*)d_in[12];
  const float* gcb    = (const float*)d_in[13];
  const float* bng    = (const float*)d_in[14];
  const float* bnb    = (const float*)d_in[15];
  const float* obng   = (const float*)d_in[16];
  const float* obnb   = (const float*)d_in[17];
  float* out = (float*)d_out;

  __half *A, *Bu, *Cu, *Du, *Eu, *AJH, *A2H;
  __half *WF16, *WG16, *WSK16, *WGC16;
  float *SK;
  cudaGetSymbolAddress((void**)&A,   g_A);
  cudaGetSymbolAddress((void**)&Bu,  g_B);
  cudaGetSymbolAddress((void**)&Cu,  g_C);
  cudaGetSymbolAddress((void**)&Du,  g_D);
  cudaGetSymbolAddress((void**)&Eu,  g_E);
  cudaGetSymbolAddress((void**)&SK,  g_SK);
  cudaGetSymbolAddress((void**)&AJH, g_adjh);
  cudaGetSymbolAddress((void**)&A2H, g_A2h);
  cudaGetSymbolAddress((void**)&WF16, g_Wf16);
  cudaGetSymbolAddress((void**)&WG16, g_Wg16);
  cudaGetSymbolAddress((void**)&WSK16, g_Wsk16);
  cudaGetSymbolAddress((void**)&WGC16, g_Wgc16);

  static bool attr_set = false;
  if (!attr_set) {
    cudaFuncSetAttribute(k_diff, cudaFuncAttributeMaxDynamicSharedMemorySize, 8 * 64 * PH2 * 2);
    attr_set = true;
  }

  dim3 bn_grid(Nn, Bn);
  dim3 diff_grid(8, Bn * Cch / 2);
  const int diff_smem = 8 * 64 * PH2 * 2;   // 73728 B

  k_wprep<<<1, 256>>>(Wf, Wg, Wsk, Wgc);
  k_adjh<<<Nn * Nn / 4 / 256, 256>>>(adj, AJH);
  k_a2<<<dim3(16, 16), dim3(32, 8)>>>(adj, A2H);

  // layer 0 TCN with fused start conv
  k_tcn<<<bn_grid, 256>>>(x, Wstart, bstart, A, Bu, SK,
                          WF16, WG16, WSK16, bf, bg, bsk);
  k_diff<<<diff_grid, 256, diff_smem>>>(Bu, AJH, A2H, Cu, Du);

  // gcmix(layer0) + TCN(layer1): LoutG=63, mode 1; spills h1 -> Eu
  k_fuse<<<bn_grid, 256>>>(Bu, Cu, Du, A, Eu,
                           WGC16, bgc, gcg, gcb, bng, bnb,
                           WF16 + 64 * PW, bf + 32, WG16 + 64 * PW, bg + 32,
                           WSK16 + 32 * PW, bsk + 32,
                           Bu, SK, nullptr, nullptr, nullptr, 63, 1);
  k_diff<<<diff_grid, 256, diff_smem>>>(Bu, AJH, A2H, Cu, Du);

  // gcmix(layer1) + TCN(layer2, final): LoutG=62, mode 2
  k_fuse<<<bn_grid, 256>>>(Bu, Cu, Du, Eu, nullptr,
                           WGC16 + 96 * PW, bgc + 32, gcg + 32, gcb + 32,
                           bng + 32, bnb + 32,
                           WF16 + 2 * 64 * PW, bf + 64, WG16 + 2 * 64 * PW, bg + 64,
                           WSK16 + 2 * 32 * PW, bsk + 64,
                           nullptr, SK, out, obng, obnb, 62, 2);
}